// round 2
// baseline (speedup 1.0000x reference)
#include <cuda_runtime.h>

#define N_NODES 100000
#define N_EDGES 1600000

// ---------------- scratch (allocation-free: __device__ globals) ----------------
__device__ __align__(16) float g_feat[N_NODES * 128];
__device__ __align__(16) float g_actA[N_NODES * 128];
__device__ __align__(16) float g_actB[N_NODES * 128];
__device__ __align__(16) float g_el[N_NODES * 4];
__device__ __align__(16) float g_er[N_NODES * 4];
__device__ int   g_rowptr[N_NODES + 1];
__device__ int   g_cursor[N_NODES];
__device__ int   g_deg[N_NODES];
__device__ int   g_esrc[N_EDGES];
__device__ float g_pooled[128];

__device__ __forceinline__ float lrelu(float x) { return x > 0.f ? x : 0.2f * x; }

// ---------------- init: zero degree counts + pooled ----------------
__global__ void init_kernel() {
    int i = blockIdx.x * blockDim.x + threadIdx.x;
    if (i < N_NODES) g_deg[i] = 0;
    if (i < 128)     g_pooled[i] = 0.f;
}

// ---------------- CSR build ----------------
__global__ void count_kernel(const int* __restrict__ dst) {
    int e = blockIdx.x * blockDim.x + threadIdx.x;
    if (e < N_EDGES) atomicAdd(&g_deg[dst[e]], 1);
}

__global__ void scan_kernel() {   // single block, 1024 threads, chunked exclusive scan
    __shared__ int wsum[32];
    int t = threadIdx.x;
    int lane = t & 31, w = t >> 5;
    if (t == 0) g_rowptr[0] = 0;
    int running = 0;
    for (int base = 0; base < N_NODES; base += 1024) {
        int i = base + t;
        int v = (i < N_NODES) ? g_deg[i] : 0;
        int x = v;
#pragma unroll
        for (int o = 1; o < 32; o <<= 1) {
            int y = __shfl_up_sync(0xffffffffu, x, o);
            if (lane >= o) x += y;
        }
        if (lane == 31) wsum[w] = x;
        __syncthreads();
        if (w == 0) {
            int sv = wsum[lane];
#pragma unroll
            for (int o = 1; o < 32; o <<= 1) {
                int y = __shfl_up_sync(0xffffffffu, sv, o);
                if (lane >= o) sv += y;
            }
            wsum[lane] = sv;
        }
        __syncthreads();
        int incl  = x + (w > 0 ? wsum[w - 1] : 0);
        int total = wsum[31];
        if (i < N_NODES) {
            g_rowptr[i + 1] = running + incl;
            g_cursor[i]     = running + incl - v;
        }
        running += total;
        __syncthreads();
    }
}

__global__ void fill_kernel(const int* __restrict__ src, const int* __restrict__ dst) {
    int e = blockIdx.x * blockDim.x + threadIdx.x;
    if (e < N_EDGES) {
        int p = atomicAdd(&g_cursor[dst[e]], 1);
        g_esrc[p] = src[e];
    }
}

// ---------------- GEMM feat = A @ W, fused el/er epilogue ----------------
// A: [N,128], W: [128,128] (k-major), al/ar: [4,32]. 32 rows per block, 256 threads.
__global__ void gemm_kernel(const float* __restrict__ Axin, int inWhich,
                            const float* __restrict__ W,
                            const float* __restrict__ al, const float* __restrict__ ar) {
    const float* A = (inWhich == 0) ? Axin : (inWhich == 1 ? g_actA : g_actB);
    __shared__ float4 sx[32 * 32];       // 32 rows x 128 floats
    int t  = threadIdx.x;
    int rb = blockIdx.x * 32;
    const float4* A4 = reinterpret_cast<const float4*>(A) + (size_t)rb * 32;
#pragma unroll
    for (int i = 0; i < 4; i++) sx[t + 256 * i] = A4[t + 256 * i];
    __syncthreads();

    int cg = t & 31, rq = t >> 5;        // cg: col-group (4 cols), rq: row quartet
    const float4* W4 = reinterpret_cast<const float4*>(W);
    const float*  sxf = reinterpret_cast<const float*>(sx);
    float4 acc[4];
#pragma unroll
    for (int j = 0; j < 4; j++) acc[j] = make_float4(0.f, 0.f, 0.f, 0.f);

#pragma unroll 4
    for (int k = 0; k < 128; k++) {
        float4 w = __ldg(&W4[k * 32 + cg]);
#pragma unroll
        for (int j = 0; j < 4; j++) {
            float xv = sxf[(rq * 4 + j) * 128 + k];
            acc[j].x += w.x * xv; acc[j].y += w.y * xv;
            acc[j].z += w.z * xv; acc[j].w += w.w * xv;
        }
    }

    int h = cg >> 3;
    float4 alv = __ldg(&reinterpret_cast<const float4*>(al)[h * 8 + (cg & 7)]);
    float4 arv = __ldg(&reinterpret_cast<const float4*>(ar)[h * 8 + (cg & 7)]);
#pragma unroll
    for (int j = 0; j < 4; j++) {
        int row = rb + rq * 4 + j;
        reinterpret_cast<float4*>(g_feat)[(size_t)row * 32 + cg] = acc[j];
        float pl = acc[j].x * alv.x + acc[j].y * alv.y + acc[j].z * alv.z + acc[j].w * alv.w;
        float pr = acc[j].x * arv.x + acc[j].y * arv.y + acc[j].z * arv.z + acc[j].w * arv.w;
#pragma unroll
        for (int o = 4; o; o >>= 1) {
            pl += __shfl_down_sync(0xffffffffu, pl, o, 8);
            pr += __shfl_down_sync(0xffffffffu, pr, o, 8);
        }
        if ((cg & 7) == 0) {
            g_el[row * 4 + h] = pl;
            g_er[row * 4 + h] = pr;
        }
    }
}

// ---------------- aggregation: one warp per dst node ----------------
__global__ void aggregate_kernel(int outWhich) {
    float* outp = (outWhich == 1) ? g_actA : g_actB;
    int warp = (blockIdx.x * blockDim.x + threadIdx.x) >> 5;
    int lane = threadIdx.x & 31;
    if (warp >= N_NODES) return;

    int s0  = g_rowptr[warp];
    int deg = g_rowptr[warp + 1] - s0;
    float4 acc = make_float4(0.f, 0.f, 0.f, 0.f);

    if (deg > 0) {
        const float4* el4 = reinterpret_cast<const float4*>(g_el);
        float4 erd = reinterpret_cast<const float4*>(g_er)[warp];

        // pass 1: fused online max + exp-sum (per lane, then warp combine)
        float m0 = -1e30f, m1 = -1e30f, m2 = -1e30f, m3 = -1e30f;
        float q0 = 0.f, q1 = 0.f, q2 = 0.f, q3 = 0.f;
        for (int i = lane; i < deg; i += 32) {
            int s = __ldg(&g_esrc[s0 + i]);
            float4 ev = __ldg(&el4[s]);
            float e0 = lrelu(ev.x + erd.x), e1 = lrelu(ev.y + erd.y);
            float e2 = lrelu(ev.z + erd.z), e3 = lrelu(ev.w + erd.w);
            if (e0 > m0) { q0 = q0 * __expf(m0 - e0) + 1.f; m0 = e0; } else q0 += __expf(e0 - m0);
            if (e1 > m1) { q1 = q1 * __expf(m1 - e1) + 1.f; m1 = e1; } else q1 += __expf(e1 - m1);
            if (e2 > m2) { q2 = q2 * __expf(m2 - e2) + 1.f; m2 = e2; } else q2 += __expf(e2 - m2);
            if (e3 > m3) { q3 = q3 * __expf(m3 - e3) + 1.f; m3 = e3; } else q3 += __expf(e3 - m3);
        }
#pragma unroll
        for (int o = 16; o; o >>= 1) {
            float mo, qo, mn;
            mo = __shfl_xor_sync(0xffffffffu, m0, o); qo = __shfl_xor_sync(0xffffffffu, q0, o);
            mn = fmaxf(m0, mo); q0 = q0 * __expf(m0 - mn) + qo * __expf(mo - mn); m0 = mn;
            mo = __shfl_xor_sync(0xffffffffu, m1, o); qo = __shfl_xor_sync(0xffffffffu, q1, o);
            mn = fmaxf(m1, mo); q1 = q1 * __expf(m1 - mn) + qo * __expf(mo - mn); m1 = mn;
            mo = __shfl_xor_sync(0xffffffffu, m2, o); qo = __shfl_xor_sync(0xffffffffu, q2, o);
            mn = fmaxf(m2, mo); q2 = q2 * __expf(m2 - mn) + qo * __expf(mo - mn); m2 = mn;
            mo = __shfl_xor_sync(0xffffffffu, m3, o); qo = __shfl_xor_sync(0xffffffffu, q3, o);
            mn = fmaxf(m3, mo); q3 = q3 * __expf(m3 - mn) + qo * __expf(mo - mn); m3 = mn;
        }
        float i0 = 1.f / q0, i1 = 1.f / q1, i2 = 1.f / q2, i3 = 1.f / q3;

        // pass 2: weighted gather-accumulate. lane owns float4 (head = lane>>3)
        int h = lane >> 3;
        const float4* feat4 = reinterpret_cast<const float4*>(g_feat);
        for (int base = 0; base < deg; base += 32) {
            int idx = base + lane;
            int s = 0;
            float a0 = 0.f, a1 = 0.f, a2 = 0.f, a3 = 0.f;
            if (idx < deg) {
                s = __ldg(&g_esrc[s0 + idx]);
                float4 ev = __ldg(&el4[s]);
                a0 = __expf(lrelu(ev.x + erd.x) - m0) * i0;
                a1 = __expf(lrelu(ev.y + erd.y) - m1) * i1;
                a2 = __expf(lrelu(ev.z + erd.z) - m2) * i2;
                a3 = __expf(lrelu(ev.w + erd.w) - m3) * i3;
            }
            int cnt = min(32, deg - base);
#pragma unroll 4
            for (int j = 0; j < cnt; j++) {
                int   sj = __shfl_sync(0xffffffffu, s,  j);
                float b0 = __shfl_sync(0xffffffffu, a0, j);
                float b1 = __shfl_sync(0xffffffffu, a1, j);
                float b2 = __shfl_sync(0xffffffffu, a2, j);
                float b3 = __shfl_sync(0xffffffffu, a3, j);
                float aa = (h == 0) ? b0 : ((h == 1) ? b1 : ((h == 2) ? b2 : b3));
                float4 f = __ldg(&feat4[(size_t)sj * 32 + lane]);
                acc.x += f.x * aa; acc.y += f.y * aa;
                acc.z += f.z * aa; acc.w += f.w * aa;
            }
        }
    }
    float4 o;       // ReLU for every layer (layer 3: reference applies relu right after)
    o.x = fmaxf(acc.x, 0.f); o.y = fmaxf(acc.y, 0.f);
    o.z = fmaxf(acc.z, 0.f); o.w = fmaxf(acc.w, 0.f);
    reinterpret_cast<float4*>(outp)[(size_t)warp * 32 + lane] = o;
}

// ---------------- graph max-pool over g_actA ----------------
__global__ void pool_kernel() {
    int c = threadIdx.x;                 // 128 columns
    float m = 0.f;                       // inputs are post-relu (>=0)
    for (int r = blockIdx.x; r < N_NODES; r += gridDim.x)
        m = fmaxf(m, g_actA[(size_t)r * 128 + c]);
    atomicMax(reinterpret_cast<int*>(&g_pooled[c]), __float_as_int(m));
}

// ---------------- FC + softmax head ----------------
__global__ void head_kernel(const float* __restrict__ Wfc, const float* __restrict__ bfc,
                            float* __restrict__ out) {
    __shared__ float lg[8];
    int t = threadIdx.x;
    if (t < 8) {
        float acc = bfc[t];
        for (int k = 0; k < 128; k++) acc += g_pooled[k] * Wfc[k * 8 + t];
        lg[t] = acc;
    }
    __syncthreads();
    if (t == 0) {
        float m = lg[0];
        for (int i = 1; i < 8; i++) m = fmaxf(m, lg[i]);
        float e[8], s = 0.f;
        for (int i = 0; i < 8; i++) { e[i] = expf(lg[i] - m); s += e[i]; }
        for (int i = 0; i < 8; i++) out[i] = e[i] / s;
    }
}

// ---------------- launch ----------------
extern "C" void kernel_launch(void* const* d_in, const int* in_sizes, int n_in,
                              void* d_out, int out_size) {
    (void)in_sizes; (void)n_in; (void)out_size;
    const float* x   = (const float*)d_in[0];
    const int*   src = (const int*)d_in[1];
    const int*   dst = (const int*)d_in[2];
    const float* W1  = (const float*)d_in[3];
    const float* al1 = (const float*)d_in[4];
    const float* ar1 = (const float*)d_in[5];
    const float* W2  = (const float*)d_in[6];
    const float* al2 = (const float*)d_in[7];
    const float* ar2 = (const float*)d_in[8];
    const float* W3  = (const float*)d_in[9];
    const float* al3 = (const float*)d_in[10];
    const float* ar3 = (const float*)d_in[11];
    const float* Wfc = (const float*)d_in[12];
    const float* bfc = (const float*)d_in[13];
    float* out = (float*)d_out;

    init_kernel<<<(N_NODES + 255) / 256, 256>>>();
    count_kernel<<<(N_EDGES + 255) / 256, 256>>>(dst);
    scan_kernel<<<1, 1024>>>();
    fill_kernel<<<(N_EDGES + 255) / 256, 256>>>(src, dst);

    // layer 1: x -> feat -> actA
    gemm_kernel<<<N_NODES / 32, 256>>>(x, 0, W1, al1, ar1);
    aggregate_kernel<<<N_NODES / 8, 256>>>(1);
    // layer 2: actA -> feat -> actB
    gemm_kernel<<<N_NODES / 32, 256>>>(nullptr, 1, W2, al2, ar2);
    aggregate_kernel<<<N_NODES / 8, 256>>>(2);
    // layer 3: actB -> feat -> actA
    gemm_kernel<<<N_NODES / 32, 256>>>(nullptr, 2, W3, al3, ar3);
    aggregate_kernel<<<N_NODES / 8, 256>>>(1);

    pool_kernel<<<512, 128>>>();
    head_kernel<<<1, 32>>>(Wfc, bfc, out);
}

// round 3
// speedup vs baseline: 1.2014x; 1.2014x over previous
#include <cuda_runtime.h>

#define N_NODES 100000
#define N_EDGES 1600000
#define NBLK_SCAN 98   // ceil(100000/1024)

typedef unsigned long long u64;

// ---------------- scratch (allocation-free: __device__ globals) ----------------
__device__ __align__(16) float g_feat[N_NODES * 128];
__device__ __align__(16) float g_actA[N_NODES * 128];
__device__ __align__(16) float g_actB[N_NODES * 128];
__device__ __align__(16) float g_el[N_NODES * 4];
__device__ __align__(16) float g_er[N_NODES * 4];
__device__ int   g_rowptr[N_NODES + 1];
__device__ int   g_cursor[N_NODES];
__device__ int   g_deg[N_NODES];
__device__ int   g_esrc[N_EDGES];
__device__ int   g_bsum[128];
__device__ float g_pooled[128];

__device__ __forceinline__ float lrelu(float x) { return x > 0.f ? x : 0.2f * x; }

__device__ __forceinline__ u64 pk(float a, float b) {
    u64 r; asm("mov.b64 %0,{%1,%2};" : "=l"(r) : "f"(a), "f"(b)); return r;
}
__device__ __forceinline__ void fma2(u64& d, u64 a, u64 b) {
    asm("fma.rn.f32x2 %0,%1,%2,%3;" : "=l"(d) : "l"(a), "l"(b), "l"(d));
}
__device__ __forceinline__ float2 up(u64 v) {
    float2 r; asm("mov.b64 {%0,%1},%2;" : "=f"(r.x), "=f"(r.y) : "l"(v)); return r;
}

// ---------------- init: zero degree counts + pooled ----------------
__global__ void init_kernel() {
    int i = blockIdx.x * blockDim.x + threadIdx.x;
    if (i < N_NODES) g_deg[i] = 0;
    if (i < 128)     g_pooled[i] = 0.f;
}

// ---------------- CSR build ----------------
__global__ void count_kernel(const int* __restrict__ dst) {
    int e = blockIdx.x * blockDim.x + threadIdx.x;
    if (e < N_EDGES) atomicAdd(&g_deg[dst[e]], 1);
}

// parallel scan, 3 stages
__global__ void scan1_kernel() {          // NBLK_SCAN blocks x 1024
    __shared__ int wsum[32];
    int t = threadIdx.x, lane = t & 31, w = t >> 5;
    int i = blockIdx.x * 1024 + t;
    int v = (i < N_NODES) ? g_deg[i] : 0;
    int x = v;
#pragma unroll
    for (int o = 1; o < 32; o <<= 1) {
        int y = __shfl_up_sync(0xffffffffu, x, o);
        if (lane >= o) x += y;
    }
    if (lane == 31) wsum[w] = x;
    __syncthreads();
    if (w == 0) {
        int sv = wsum[lane];
#pragma unroll
        for (int o = 1; o < 32; o <<= 1) {
            int y = __shfl_up_sync(0xffffffffu, sv, o);
            if (lane >= o) sv += y;
        }
        wsum[lane] = sv;
    }
    __syncthreads();
    int incl = x + (w > 0 ? wsum[w - 1] : 0);
    if (i < N_NODES) g_rowptr[i + 1] = incl;          // block-local inclusive
    if (t == 1023)   g_bsum[blockIdx.x] = incl;       // block total
}

__global__ void scan2_kernel() {          // 1 block, 128 threads
    __shared__ int s[128];
    int t = threadIdx.x;
    int v = (t < NBLK_SCAN) ? g_bsum[t] : 0;
    s[t] = v; __syncthreads();
    for (int o = 1; o < 128; o <<= 1) {
        int y = (t >= o) ? s[t - o] : 0;
        __syncthreads();
        s[t] += y;
        __syncthreads();
    }
    if (t < NBLK_SCAN) g_bsum[t] = s[t] - v;          // exclusive block offset
}

__global__ void scan3_kernel() {
    int i = blockIdx.x * blockDim.x + threadIdx.x;
    if (i < N_NODES) {
        int r = g_rowptr[i + 1] + g_bsum[i >> 10];
        g_rowptr[i + 1] = r;
        g_cursor[i] = r - g_deg[i];
        if (i == 0) g_rowptr[0] = 0;
    }
}

__global__ void fill_kernel(const int* __restrict__ src, const int* __restrict__ dst) {
    int e = blockIdx.x * blockDim.x + threadIdx.x;
    if (e < N_EDGES) {
        int p = atomicAdd(&g_cursor[dst[e]], 1);
        g_esrc[p] = src[e];
    }
}

// ---------------- GEMM feat = A @ W (f32x2 packed FMA), fused el/er epilogue ----------------
__global__ void gemm_kernel(const float* __restrict__ Axin, int inWhich,
                            const float* __restrict__ W,
                            const float* __restrict__ al, const float* __restrict__ ar) {
    const float* A = (inWhich == 0) ? Axin : (inWhich == 1 ? g_actA : g_actB);
    __shared__ float4 sx[32 * 32];       // 32 rows x 128 floats
    int t  = threadIdx.x;
    int rb = blockIdx.x * 32;
    const float4* A4 = reinterpret_cast<const float4*>(A) + (size_t)rb * 32;
#pragma unroll
    for (int i = 0; i < 4; i++) sx[t + 256 * i] = A4[t + 256 * i];
    __syncthreads();

    int cg = t & 31, rq = t >> 5;        // cg: float4 col-group, rq: row quartet
    const float4* W4 = reinterpret_cast<const float4*>(W);
    u64 aL[4], aH[4];
#pragma unroll
    for (int j = 0; j < 4; j++) { aL[j] = 0ull; aH[j] = 0ull; }

#pragma unroll 2
    for (int k4 = 0; k4 < 32; k4++) {
        float4 w0 = __ldg(&W4[(k4 * 4 + 0) * 32 + cg]);
        float4 w1 = __ldg(&W4[(k4 * 4 + 1) * 32 + cg]);
        float4 w2 = __ldg(&W4[(k4 * 4 + 2) * 32 + cg]);
        float4 w3 = __ldg(&W4[(k4 * 4 + 3) * 32 + cg]);
        u64 wl0 = pk(w0.x, w0.y), wh0 = pk(w0.z, w0.w);
        u64 wl1 = pk(w1.x, w1.y), wh1 = pk(w1.z, w1.w);
        u64 wl2 = pk(w2.x, w2.y), wh2 = pk(w2.z, w2.w);
        u64 wl3 = pk(w3.x, w3.y), wh3 = pk(w3.z, w3.w);
#pragma unroll
        for (int j = 0; j < 4; j++) {
            float4 xv = sx[(rq * 4 + j) * 32 + k4];
            u64 x0 = pk(xv.x, xv.x), x1 = pk(xv.y, xv.y);
            u64 x2 = pk(xv.z, xv.z), x3 = pk(xv.w, xv.w);
            fma2(aL[j], x0, wl0); fma2(aH[j], x0, wh0);
            fma2(aL[j], x1, wl1); fma2(aH[j], x1, wh1);
            fma2(aL[j], x2, wl2); fma2(aH[j], x2, wh2);
            fma2(aL[j], x3, wl3); fma2(aH[j], x3, wh3);
        }
    }

    int h = cg >> 3;
    float4 alv = __ldg(&reinterpret_cast<const float4*>(al)[h * 8 + (cg & 7)]);
    float4 arv = __ldg(&reinterpret_cast<const float4*>(ar)[h * 8 + (cg & 7)]);
#pragma unroll
    for (int j = 0; j < 4; j++) {
        float2 lo = up(aL[j]), hi = up(aH[j]);
        float4 acc = make_float4(lo.x, lo.y, hi.x, hi.y);
        int row = rb + rq * 4 + j;
        reinterpret_cast<float4*>(g_feat)[(size_t)row * 32 + cg] = acc;
        float pl = acc.x * alv.x + acc.y * alv.y + acc.z * alv.z + acc.w * alv.w;
        float pr = acc.x * arv.x + acc.y * arv.y + acc.z * arv.z + acc.w * arv.w;
#pragma unroll
        for (int o = 4; o; o >>= 1) {
            pl += __shfl_down_sync(0xffffffffu, pl, o, 8);
            pr += __shfl_down_sync(0xffffffffu, pr, o, 8);
        }
        if ((cg & 7) == 0) {
            g_el[row * 4 + h] = pl;
            g_er[row * 4 + h] = pr;
        }
    }
}

// ---------------- aggregation: one warp per dst node ----------------
// grid is exactly N_NODES/8 blocks x 256 threads (100000 warps, no remainder)
__global__ void aggregate_kernel(int outWhich, int doPool) {
    __shared__ float  s_alpha[8][4][33];
    __shared__ int    s_src[8][32];
    __shared__ float4 s_red[256];
    float* outp = (outWhich == 1) ? g_actA : g_actB;
    int node = (blockIdx.x * blockDim.x + threadIdx.x) >> 5;
    int lane = threadIdx.x & 31;
    int w    = threadIdx.x >> 5;

    int s0  = g_rowptr[node];
    int deg = g_rowptr[node + 1] - s0;
    float4 acc = make_float4(0.f, 0.f, 0.f, 0.f);

    if (deg > 0) {
        const float4* el4 = reinterpret_cast<const float4*>(g_el);
        float4 erd = reinterpret_cast<const float4*>(g_er)[node];

        // pass 1: fused online max + exp-sum
        float m0 = -1e30f, m1 = -1e30f, m2 = -1e30f, m3 = -1e30f;
        float q0 = 0.f, q1 = 0.f, q2 = 0.f, q3 = 0.f;
        for (int i = lane; i < deg; i += 32) {
            int s = __ldg(&g_esrc[s0 + i]);
            float4 ev = __ldg(&el4[s]);
            float e0 = lrelu(ev.x + erd.x), e1 = lrelu(ev.y + erd.y);
            float e2 = lrelu(ev.z + erd.z), e3 = lrelu(ev.w + erd.w);
            if (e0 > m0) { q0 = q0 * __expf(m0 - e0) + 1.f; m0 = e0; } else q0 += __expf(e0 - m0);
            if (e1 > m1) { q1 = q1 * __expf(m1 - e1) + 1.f; m1 = e1; } else q1 += __expf(e1 - m1);
            if (e2 > m2) { q2 = q2 * __expf(m2 - e2) + 1.f; m2 = e2; } else q2 += __expf(e2 - m2);
            if (e3 > m3) { q3 = q3 * __expf(m3 - e3) + 1.f; m3 = e3; } else q3 += __expf(e3 - m3);
        }
#pragma unroll
        for (int o = 16; o; o >>= 1) {
            float mo, qo, mn;
            mo = __shfl_xor_sync(0xffffffffu, m0, o); qo = __shfl_xor_sync(0xffffffffu, q0, o);
            mn = fmaxf(m0, mo); q0 = q0 * __expf(m0 - mn) + qo * __expf(mo - mn); m0 = mn;
            mo = __shfl_xor_sync(0xffffffffu, m1, o); qo = __shfl_xor_sync(0xffffffffu, q1, o);
            mn = fmaxf(m1, mo); q1 = q1 * __expf(m1 - mn) + qo * __expf(mo - mn); m1 = mn;
            mo = __shfl_xor_sync(0xffffffffu, m2, o); qo = __shfl_xor_sync(0xffffffffu, q2, o);
            mn = fmaxf(m2, mo); q2 = q2 * __expf(m2 - mn) + qo * __expf(mo - mn); m2 = mn;
            mo = __shfl_xor_sync(0xffffffffu, m3, o); qo = __shfl_xor_sync(0xffffffffu, q3, o);
            mn = fmaxf(m3, mo); q3 = q3 * __expf(m3 - mn) + qo * __expf(mo - mn); m3 = mn;
        }
        float i0 = 1.f / q0, i1 = 1.f / q1, i2 = 1.f / q2, i3 = 1.f / q3;

        // pass 2: stage 32 edges' (src, alpha) in smem, then gather-accumulate
        int h = lane >> 3;
        const float4* feat4 = reinterpret_cast<const float4*>(g_feat);
        for (int base = 0; base < deg; base += 32) {
            int idx = base + lane;
            int s = 0;
            float a0 = 0.f, a1 = 0.f, a2 = 0.f, a3 = 0.f;
            if (idx < deg) {
                s = __ldg(&g_esrc[s0 + idx]);
                float4 ev = __ldg(&el4[s]);
                a0 = __expf(lrelu(ev.x + erd.x) - m0) * i0;
                a1 = __expf(lrelu(ev.y + erd.y) - m1) * i1;
                a2 = __expf(lrelu(ev.z + erd.z) - m2) * i2;
                a3 = __expf(lrelu(ev.w + erd.w) - m3) * i3;
            }
            __syncwarp();
            s_src[w][lane] = s;
            s_alpha[w][0][lane] = a0; s_alpha[w][1][lane] = a1;
            s_alpha[w][2][lane] = a2; s_alpha[w][3][lane] = a3;
            __syncwarp();
            int cnt = min(32, deg - base);
#pragma unroll 4
            for (int j = 0; j < cnt; j++) {
                int   sj = s_src[w][j];
                float aa = s_alpha[w][h][j];
                float4 f = __ldg(&feat4[(size_t)sj * 32 + lane]);
                acc.x += f.x * aa; acc.y += f.y * aa;
                acc.z += f.z * aa; acc.w += f.w * aa;
            }
        }
    }
    float4 o;       // ReLU every layer (layer 3: reference applies relu before pooling)
    o.x = fmaxf(acc.x, 0.f); o.y = fmaxf(acc.y, 0.f);
    o.z = fmaxf(acc.z, 0.f); o.w = fmaxf(acc.w, 0.f);

    if (!doPool) {
        reinterpret_cast<float4*>(outp)[(size_t)node * 32 + lane] = o;
    } else {
        // fused graph max-pool: block reduction + 1 atomicMax per column per block
        int t = threadIdx.x;
        s_red[t] = o;
        __syncthreads();
        if (t < 32) {
            float4 m = s_red[t];
#pragma unroll
            for (int i = 1; i < 8; i++) {
                float4 v = s_red[t + 32 * i];
                m.x = fmaxf(m.x, v.x); m.y = fmaxf(m.y, v.y);
                m.z = fmaxf(m.z, v.z); m.w = fmaxf(m.w, v.w);
            }
            atomicMax(reinterpret_cast<int*>(&g_pooled[t * 4 + 0]), __float_as_int(m.x));
            atomicMax(reinterpret_cast<int*>(&g_pooled[t * 4 + 1]), __float_as_int(m.y));
            atomicMax(reinterpret_cast<int*>(&g_pooled[t * 4 + 2]), __float_as_int(m.z));
            atomicMax(reinterpret_cast<int*>(&g_pooled[t * 4 + 3]), __float_as_int(m.w));
        }
    }
}

// ---------------- FC + softmax head ----------------
__global__ void head_kernel(const float* __restrict__ Wfc, const float* __restrict__ bfc,
                            float* __restrict__ out) {
    __shared__ float lg[8];
    int t = threadIdx.x;
    if (t < 8) {
        float acc = bfc[t];
        for (int k = 0; k < 128; k++) acc += g_pooled[k] * Wfc[k * 8 + t];
        lg[t] = acc;
    }
    __syncthreads();
    if (t == 0) {
        float m = lg[0];
        for (int i = 1; i < 8; i++) m = fmaxf(m, lg[i]);
        float e[8], s = 0.f;
        for (int i = 0; i < 8; i++) { e[i] = expf(lg[i] - m); s += e[i]; }
        for (int i = 0; i < 8; i++) out[i] = e[i] / s;
    }
}

// ---------------- launch ----------------
extern "C" void kernel_launch(void* const* d_in, const int* in_sizes, int n_in,
                              void* d_out, int out_size) {
    (void)in_sizes; (void)n_in; (void)out_size;
    const float* x   = (const float*)d_in[0];
    const int*   src = (const int*)d_in[1];
    const int*   dst = (const int*)d_in[2];
    const float* W1  = (const float*)d_in[3];
    const float* al1 = (const float*)d_in[4];
    const float* ar1 = (const float*)d_in[5];
    const float* W2  = (const float*)d_in[6];
    const float* al2 = (const float*)d_in[7];
    const float* ar2 = (const float*)d_in[8];
    const float* W3  = (const float*)d_in[9];
    const float* al3 = (const float*)d_in[10];
    const float* ar3 = (const float*)d_in[11];
    const float* Wfc = (const float*)d_in[12];
    const float* bfc = (const float*)d_in[13];
    float* out = (float*)d_out;

    init_kernel<<<(N_NODES + 255) / 256, 256>>>();
    count_kernel<<<(N_EDGES + 255) / 256, 256>>>(dst);
    scan1_kernel<<<NBLK_SCAN, 1024>>>();
    scan2_kernel<<<1, 128>>>();
    scan3_kernel<<<(N_NODES + 255) / 256, 256>>>();
    fill_kernel<<<(N_EDGES + 255) / 256, 256>>>(src, dst);

    // layer 1: x -> feat -> actA
    gemm_kernel<<<N_NODES / 32, 256>>>(x, 0, W1, al1, ar1);
    aggregate_kernel<<<N_NODES / 8, 256>>>(1, 0);
    // layer 2: actA -> feat -> actB
    gemm_kernel<<<N_NODES / 32, 256>>>(nullptr, 1, W2, al2, ar2);
    aggregate_kernel<<<N_NODES / 8, 256>>>(2, 0);
    // layer 3: actB -> feat -> (fused max-pool)
    gemm_kernel<<<N_NODES / 32, 256>>>(nullptr, 2, W3, al3, ar3);
    aggregate_kernel<<<N_NODES / 8, 256>>>(1, 1);

    head_kernel<<<1, 32>>>(Wfc, bfc, out);
}

// round 4
// speedup vs baseline: 1.3056x; 1.0868x over previous
#include <cuda_runtime.h>

#define N_NODES 100000
#define N_EDGES 1600000
#define NBLK_SCAN 98   // ceil(100000/1024)

typedef unsigned long long u64;

// ---------------- scratch (allocation-free: __device__ globals) ----------------
__device__ __align__(16) float g_feat[N_NODES * 128];
__device__ __align__(16) float g_actA[N_NODES * 128];
__device__ __align__(16) float g_actB[N_NODES * 128];
__device__ __align__(16) float g_el[N_NODES * 4];
__device__ __align__(16) float g_er[N_NODES * 4];
__device__ int   g_rowptr[N_NODES + 1];
__device__ int   g_cursor[N_NODES];
__device__ int   g_deg[N_NODES];
__device__ int   g_esrc[N_EDGES];
__device__ int   g_bsum[128];
__device__ float g_pooled[128];

__device__ __forceinline__ float lrelu(float x) { return x > 0.f ? x : 0.2f * x; }

__device__ __forceinline__ u64 pk(float a, float b) {
    u64 r; asm("mov.b64 %0,{%1,%2};" : "=l"(r) : "f"(a), "f"(b)); return r;
}
__device__ __forceinline__ void fma2(u64& d, u64 a, u64 b) {
    asm("fma.rn.f32x2 %0,%1,%2,%3;" : "=l"(d) : "l"(a), "l"(b), "l"(d));
}
__device__ __forceinline__ float2 up(u64 v) {
    float2 r; asm("mov.b64 {%0,%1},%2;" : "=f"(r.x), "=f"(r.y) : "l"(v)); return r;
}

// ---------------- init: zero degree counts + pooled ----------------
__global__ void init_kernel() {
    int i = blockIdx.x * blockDim.x + threadIdx.x;
    if (i < N_NODES) g_deg[i] = 0;
    if (i < 128)     g_pooled[i] = 0.f;
}

// ---------------- CSR build ----------------
__global__ void count_kernel(const int* __restrict__ dst) {
    int e = blockIdx.x * blockDim.x + threadIdx.x;
    if (e < N_EDGES) atomicAdd(&g_deg[dst[e]], 1);
}

// parallel scan, 3 stages
__global__ void scan1_kernel() {          // NBLK_SCAN blocks x 1024
    __shared__ int wsum[32];
    int t = threadIdx.x, lane = t & 31, w = t >> 5;
    int i = blockIdx.x * 1024 + t;
    int v = (i < N_NODES) ? g_deg[i] : 0;
    int x = v;
#pragma unroll
    for (int o = 1; o < 32; o <<= 1) {
        int y = __shfl_up_sync(0xffffffffu, x, o);
        if (lane >= o) x += y;
    }
    if (lane == 31) wsum[w] = x;
    __syncthreads();
    if (w == 0) {
        int sv = wsum[lane];
#pragma unroll
        for (int o = 1; o < 32; o <<= 1) {
            int y = __shfl_up_sync(0xffffffffu, sv, o);
            if (lane >= o) sv += y;
        }
        wsum[lane] = sv;
    }
    __syncthreads();
    int incl = x + (w > 0 ? wsum[w - 1] : 0);
    if (i < N_NODES) g_rowptr[i + 1] = incl;          // block-local inclusive
    if (t == 1023)   g_bsum[blockIdx.x] = incl;       // block total
}

__global__ void scan2_kernel() {          // 1 block, 128 threads
    __shared__ int s[128];
    int t = threadIdx.x;
    int v = (t < NBLK_SCAN) ? g_bsum[t] : 0;
    s[t] = v; __syncthreads();
    for (int o = 1; o < 128; o <<= 1) {
        int y = (t >= o) ? s[t - o] : 0;
        __syncthreads();
        s[t] += y;
        __syncthreads();
    }
    if (t < NBLK_SCAN) g_bsum[t] = s[t] - v;          // exclusive block offset
}

__global__ void scan3_kernel() {
    int i = blockIdx.x * blockDim.x + threadIdx.x;
    if (i < N_NODES) {
        int r = g_rowptr[i + 1] + g_bsum[i >> 10];
        g_rowptr[i + 1] = r;
        g_cursor[i] = r - g_deg[i];
        if (i == 0) g_rowptr[0] = 0;
    }
}

__global__ void fill_kernel(const int* __restrict__ src, const int* __restrict__ dst) {
    int e = blockIdx.x * blockDim.x + threadIdx.x;
    if (e < N_EDGES) {
        int p = atomicAdd(&g_cursor[dst[e]], 1);
        g_esrc[p] = src[e];
    }
}

// ---------------- GEMM feat = A @ W (f32x2 packed FMA), fused el/er epilogue ----------------
__global__ void gemm_kernel(const float* __restrict__ Axin, int inWhich,
                            const float* __restrict__ W,
                            const float* __restrict__ al, const float* __restrict__ ar) {
    const float* A = (inWhich == 0) ? Axin : (inWhich == 1 ? g_actA : g_actB);
    __shared__ float4 sx[32 * 32];       // 32 rows x 128 floats
    int t  = threadIdx.x;
    int rb = blockIdx.x * 32;
    const float4* A4 = reinterpret_cast<const float4*>(A) + (size_t)rb * 32;
#pragma unroll
    for (int i = 0; i < 4; i++) sx[t + 256 * i] = A4[t + 256 * i];
    __syncthreads();

    int cg = t & 31, rq = t >> 5;        // cg: float4 col-group, rq: row quartet
    const float4* W4 = reinterpret_cast<const float4*>(W);
    u64 aL[4], aH[4];
#pragma unroll
    for (int j = 0; j < 4; j++) { aL[j] = 0ull; aH[j] = 0ull; }

#pragma unroll 2
    for (int k4 = 0; k4 < 32; k4++) {
        float4 w0 = __ldg(&W4[(k4 * 4 + 0) * 32 + cg]);
        float4 w1 = __ldg(&W4[(k4 * 4 + 1) * 32 + cg]);
        float4 w2 = __ldg(&W4[(k4 * 4 + 2) * 32 + cg]);
        float4 w3 = __ldg(&W4[(k4 * 4 + 3) * 32 + cg]);
        u64 wl0 = pk(w0.x, w0.y), wh0 = pk(w0.z, w0.w);
        u64 wl1 = pk(w1.x, w1.y), wh1 = pk(w1.z, w1.w);
        u64 wl2 = pk(w2.x, w2.y), wh2 = pk(w2.z, w2.w);
        u64 wl3 = pk(w3.x, w3.y), wh3 = pk(w3.z, w3.w);
#pragma unroll
        for (int j = 0; j < 4; j++) {
            float4 xv = sx[(rq * 4 + j) * 32 + k4];
            u64 x0 = pk(xv.x, xv.x), x1 = pk(xv.y, xv.y);
            u64 x2 = pk(xv.z, xv.z), x3 = pk(xv.w, xv.w);
            fma2(aL[j], x0, wl0); fma2(aH[j], x0, wh0);
            fma2(aL[j], x1, wl1); fma2(aH[j], x1, wh1);
            fma2(aL[j], x2, wl2); fma2(aH[j], x2, wh2);
            fma2(aL[j], x3, wl3); fma2(aH[j], x3, wh3);
        }
    }

    int h = cg >> 3;
    float4 alv = __ldg(&reinterpret_cast<const float4*>(al)[h * 8 + (cg & 7)]);
    float4 arv = __ldg(&reinterpret_cast<const float4*>(ar)[h * 8 + (cg & 7)]);
#pragma unroll
    for (int j = 0; j < 4; j++) {
        float2 lo = up(aL[j]), hi = up(aH[j]);
        float4 acc = make_float4(lo.x, lo.y, hi.x, hi.y);
        int row = rb + rq * 4 + j;
        reinterpret_cast<float4*>(g_feat)[(size_t)row * 32 + cg] = acc;
        float pl = acc.x * alv.x + acc.y * alv.y + acc.z * alv.z + acc.w * alv.w;
        float pr = acc.x * arv.x + acc.y * arv.y + acc.z * arv.z + acc.w * arv.w;
#pragma unroll
        for (int o = 4; o; o >>= 1) {
            pl += __shfl_down_sync(0xffffffffu, pl, o, 8);
            pr += __shfl_down_sync(0xffffffffu, pr, o, 8);
        }
        if ((cg & 7) == 0) {
            g_el[row * 4 + h] = pl;
            g_er[row * 4 + h] = pr;
        }
    }
}

// ---------------- aggregation: one warp per dst node, SINGLE PASS ----------------
// out = sum_e exp(e)*feat[src] / sum_e exp(e)  (softmax shift-invariance; no max pass)
__global__ void aggregate_kernel(int outWhich, int doPool) {
    __shared__ float  s_w[8][4][33];
    __shared__ int    s_src[8][32];
    __shared__ float4 s_red[256];
    float* outp = (outWhich == 1) ? g_actA : g_actB;
    int node = (blockIdx.x * blockDim.x + threadIdx.x) >> 5;
    int lane = threadIdx.x & 31;
    int w    = threadIdx.x >> 5;

    int s0  = g_rowptr[node];
    int deg = g_rowptr[node + 1] - s0;
    float4 acc = make_float4(0.f, 0.f, 0.f, 0.f);
    float q0 = 0.f, q1 = 0.f, q2 = 0.f, q3 = 0.f;

    if (deg > 0) {
        const float4* el4 = reinterpret_cast<const float4*>(g_el);
        float4 erd = reinterpret_cast<const float4*>(g_er)[node];
        int h = lane >> 3;
        const float4* feat4 = reinterpret_cast<const float4*>(g_feat);

        for (int base = 0; base < deg; base += 32) {
            int idx = base + lane;
            int s = 0;
            float w0 = 0.f, w1 = 0.f, w2 = 0.f, w3 = 0.f;
            if (idx < deg) {
                s = __ldg(&g_esrc[s0 + idx]);
                float4 ev = __ldg(&el4[s]);
                w0 = __expf(lrelu(ev.x + erd.x));
                w1 = __expf(lrelu(ev.y + erd.y));
                w2 = __expf(lrelu(ev.z + erd.z));
                w3 = __expf(lrelu(ev.w + erd.w));
                q0 += w0; q1 += w1; q2 += w2; q3 += w3;
            }
            __syncwarp();
            s_src[w][lane] = s;
            s_w[w][0][lane] = w0; s_w[w][1][lane] = w1;
            s_w[w][2][lane] = w2; s_w[w][3][lane] = w3;
            __syncwarp();
            int cnt = min(32, deg - base);
#pragma unroll 4
            for (int j = 0; j < cnt; j++) {
                int   sj = s_src[w][j];
                float aa = s_w[w][h][j];
                float4 f = __ldg(&feat4[(size_t)sj * 32 + lane]);
                acc.x += f.x * aa; acc.y += f.y * aa;
                acc.z += f.z * aa; acc.w += f.w * aa;
            }
        }
        // total weight across the warp's edges
#pragma unroll
        for (int o = 16; o; o >>= 1) {
            q0 += __shfl_xor_sync(0xffffffffu, q0, o);
            q1 += __shfl_xor_sync(0xffffffffu, q1, o);
            q2 += __shfl_xor_sync(0xffffffffu, q2, o);
            q3 += __shfl_xor_sync(0xffffffffu, q3, o);
        }
        float qh = (h == 0) ? q0 : ((h == 1) ? q1 : ((h == 2) ? q2 : q3));
        float inv = 1.f / qh;
        acc.x *= inv; acc.y *= inv; acc.z *= inv; acc.w *= inv;
    }
    float4 o;       // ReLU every layer (layer 3: reference applies relu before pooling)
    o.x = fmaxf(acc.x, 0.f); o.y = fmaxf(acc.y, 0.f);
    o.z = fmaxf(acc.z, 0.f); o.w = fmaxf(acc.w, 0.f);

    if (!doPool) {
        reinterpret_cast<float4*>(outp)[(size_t)node * 32 + lane] = o;
    } else {
        // fused graph max-pool: block reduction + 1 atomicMax per column per block
        int t = threadIdx.x;
        s_red[t] = o;
        __syncthreads();
        if (t < 32) {
            float4 m = s_red[t];
#pragma unroll
            for (int i = 1; i < 8; i++) {
                float4 v = s_red[t + 32 * i];
                m.x = fmaxf(m.x, v.x); m.y = fmaxf(m.y, v.y);
                m.z = fmaxf(m.z, v.z); m.w = fmaxf(m.w, v.w);
            }
            atomicMax(reinterpret_cast<int*>(&g_pooled[t * 4 + 0]), __float_as_int(m.x));
            atomicMax(reinterpret_cast<int*>(&g_pooled[t * 4 + 1]), __float_as_int(m.y));
            atomicMax(reinterpret_cast<int*>(&g_pooled[t * 4 + 2]), __float_as_int(m.z));
            atomicMax(reinterpret_cast<int*>(&g_pooled[t * 4 + 3]), __float_as_int(m.w));
        }
    }
}

// ---------------- FC + softmax head ----------------
__global__ void head_kernel(const float* __restrict__ Wfc, const float* __restrict__ bfc,
                            float* __restrict__ out) {
    __shared__ float lg[8];
    int t = threadIdx.x;
    if (t < 8) {
        float acc = bfc[t];
        for (int k = 0; k < 128; k++) acc += g_pooled[k] * Wfc[k * 8 + t];
        lg[t] = acc;
    }
    __syncthreads();
    if (t == 0) {
        float m = lg[0];
        for (int i = 1; i < 8; i++) m = fmaxf(m, lg[i]);
        float e[8], s = 0.f;
        for (int i = 0; i < 8; i++) { e[i] = expf(lg[i] - m); s += e[i]; }
        for (int i = 0; i < 8; i++) out[i] = e[i] / s;
    }
}

// ---------------- launch ----------------
extern "C" void kernel_launch(void* const* d_in, const int* in_sizes, int n_in,
                              void* d_out, int out_size) {
    (void)in_sizes; (void)n_in; (void)out_size;
    const float* x   = (const float*)d_in[0];
    const int*   src = (const int*)d_in[1];
    const int*   dst = (const int*)d_in[2];
    const float* W1  = (const float*)d_in[3];
    const float* al1 = (const float*)d_in[4];
    const float* ar1 = (const float*)d_in[5];
    const float* W2  = (const float*)d_in[6];
    const float* al2 = (const float*)d_in[7];
    const float* ar2 = (const float*)d_in[8];
    const float* W3  = (const float*)d_in[9];
    const float* al3 = (const float*)d_in[10];
    const float* ar3 = (const float*)d_in[11];
    const float* Wfc = (const float*)d_in[12];
    const float* bfc = (const float*)d_in[13];
    float* out = (float*)d_out;

    init_kernel<<<(N_NODES + 255) / 256, 256>>>();
    count_kernel<<<(N_EDGES + 255) / 256, 256>>>(dst);
    scan1_kernel<<<NBLK_SCAN, 1024>>>();
    scan2_kernel<<<1, 128>>>();
    scan3_kernel<<<(N_NODES + 255) / 256, 256>>>();
    fill_kernel<<<(N_EDGES + 255) / 256, 256>>>(src, dst);

    // layer 1: x -> feat -> actA
    gemm_kernel<<<N_NODES / 32, 256>>>(x, 0, W1, al1, ar1);
    aggregate_kernel<<<N_NODES / 8, 256>>>(1, 0);
    // layer 2: actA -> feat -> actB
    gemm_kernel<<<N_NODES / 32, 256>>>(nullptr, 1, W2, al2, ar2);
    aggregate_kernel<<<N_NODES / 8, 256>>>(2, 0);
    // layer 3: actB -> feat -> (fused max-pool)
    gemm_kernel<<<N_NODES / 32, 256>>>(nullptr, 2, W3, al3, ar3);
    aggregate_kernel<<<N_NODES / 8, 256>>>(1, 1);

    head_kernel<<<1, 32>>>(Wfc, bfc, out);
}

// round 6
// speedup vs baseline: 1.4307x; 1.0958x over previous
#include <cuda_runtime.h>
#include <cuda_fp16.h>

#define N_NODES 100000
#define N_EDGES 1600000
#define NBLK_SCAN 98   // ceil(100000/1024)

typedef unsigned long long u64;

// ---------------- scratch (allocation-free: __device__ globals) ----------------
__device__ __align__(16) __half g_feat[N_NODES * 128];   // fp16 transformed features
__device__ __align__(16) float g_actA[N_NODES * 128];
__device__ __align__(16) float g_actB[N_NODES * 128];
__device__ __align__(16) float g_el[N_NODES * 4];
__device__ __align__(16) float g_er[N_NODES * 4];
__device__ int   g_rowptr[N_NODES + 1];
__device__ int   g_cursor[N_NODES];
__device__ int   g_deg[N_NODES];
__device__ int   g_esrc[N_EDGES];
__device__ int   g_bsum[128];
__device__ float g_pooled[128];

__device__ __forceinline__ float lrelu(float x) { return x > 0.f ? x : 0.2f * x; }

__device__ __forceinline__ u64 pk(float a, float b) {
    u64 r; asm("mov.b64 %0,{%1,%2};" : "=l"(r) : "f"(a), "f"(b)); return r;
}
__device__ __forceinline__ void fma2(u64& d, u64 a, u64 b) {
    asm("fma.rn.f32x2 %0,%1,%2,%3;" : "=l"(d) : "l"(a), "l"(b), "l"(d));
}
__device__ __forceinline__ float2 up(u64 v) {
    float2 r; asm("mov.b64 {%0,%1},%2;" : "=f"(r.x), "=f"(r.y) : "l"(v)); return r;
}

// ---------------- init: zero degree counts + pooled ----------------
__global__ void init_kernel() {
    int i = blockIdx.x * blockDim.x + threadIdx.x;
    if (i < N_NODES) g_deg[i] = 0;
    if (i < 128)     g_pooled[i] = 0.f;
}

// ---------------- CSR build (int4-vectorized edge reads) ----------------
__global__ void count_kernel(const int* __restrict__ dst) {
    int e4 = blockIdx.x * blockDim.x + threadIdx.x;
    if (e4 < N_EDGES / 4) {
        int4 d = __ldg(&reinterpret_cast<const int4*>(dst)[e4]);
        atomicAdd(&g_deg[d.x], 1);
        atomicAdd(&g_deg[d.y], 1);
        atomicAdd(&g_deg[d.z], 1);
        atomicAdd(&g_deg[d.w], 1);
    }
}

// parallel scan, 3 stages
__global__ void scan1_kernel() {          // NBLK_SCAN blocks x 1024
    __shared__ int wsum[32];
    int t = threadIdx.x, lane = t & 31, w = t >> 5;
    int i = blockIdx.x * 1024 + t;
    int v = (i < N_NODES) ? g_deg[i] : 0;
    int x = v;
#pragma unroll
    for (int o = 1; o < 32; o <<= 1) {
        int y = __shfl_up_sync(0xffffffffu, x, o);
        if (lane >= o) x += y;
    }
    if (lane == 31) wsum[w] = x;
    __syncthreads();
    if (w == 0) {
        int sv = wsum[lane];
#pragma unroll
        for (int o = 1; o < 32; o <<= 1) {
            int y = __shfl_up_sync(0xffffffffu, sv, o);
            if (lane >= o) sv += y;
        }
        wsum[lane] = sv;
    }
    __syncthreads();
    int incl = x + (w > 0 ? wsum[w - 1] : 0);
    if (i < N_NODES) g_rowptr[i + 1] = incl;          // block-local inclusive
    if (t == 1023)   g_bsum[blockIdx.x] = incl;       // block total
}

__global__ void scan2_kernel() {          // 1 block, 128 threads
    __shared__ int s[128];
    int t = threadIdx.x;
    int v = (t < NBLK_SCAN) ? g_bsum[t] : 0;
    s[t] = v; __syncthreads();
    for (int o = 1; o < 128; o <<= 1) {
        int y = (t >= o) ? s[t - o] : 0;
        __syncthreads();
        s[t] += y;
        __syncthreads();
    }
    if (t < NBLK_SCAN) g_bsum[t] = s[t] - v;          // exclusive block offset
}

__global__ void scan3_kernel() {
    int i = blockIdx.x * blockDim.x + threadIdx.x;
    if (i < N_NODES) {
        int r = g_rowptr[i + 1] + g_bsum[i >> 10];
        g_rowptr[i + 1] = r;
        g_cursor[i] = r - g_deg[i];
        if (i == 0) g_rowptr[0] = 0;
    }
}

__global__ void fill_kernel(const int* __restrict__ src, const int* __restrict__ dst) {
    int e4 = blockIdx.x * blockDim.x + threadIdx.x;
    if (e4 < N_EDGES / 4) {
        int4 s = __ldg(&reinterpret_cast<const int4*>(src)[e4]);
        int4 d = __ldg(&reinterpret_cast<const int4*>(dst)[e4]);
        g_esrc[atomicAdd(&g_cursor[d.x], 1)] = s.x;
        g_esrc[atomicAdd(&g_cursor[d.y], 1)] = s.y;
        g_esrc[atomicAdd(&g_cursor[d.z], 1)] = s.z;
        g_esrc[atomicAdd(&g_cursor[d.w], 1)] = s.w;
    }
}

// ---------------- GEMM feat = A @ W (f32x2 packed FMA), fused el/er epilogue ----------------
// fp32 accumulation; feat stored fp16; el/er from fp32 acc (exact logits)
__global__ void gemm_kernel(const float* __restrict__ Axin, int inWhich,
                            const float* __restrict__ W,
                            const float* __restrict__ al, const float* __restrict__ ar) {
    const float* A = (inWhich == 0) ? Axin : (inWhich == 1 ? g_actA : g_actB);
    __shared__ float4 sx[32 * 32];       // 32 rows x 128 floats
    int t  = threadIdx.x;
    int rb = blockIdx.x * 32;
    const float4* A4 = reinterpret_cast<const float4*>(A) + (size_t)rb * 32;
#pragma unroll
    for (int i = 0; i < 4; i++) sx[t + 256 * i] = A4[t + 256 * i];
    __syncthreads();

    int cg = t & 31, rq = t >> 5;        // cg: float4 col-group, rq: row quartet
    const float4* W4 = reinterpret_cast<const float4*>(W);
    u64 aL[4], aH[4];
#pragma unroll
    for (int j = 0; j < 4; j++) { aL[j] = 0ull; aH[j] = 0ull; }

#pragma unroll 2
    for (int k4 = 0; k4 < 32; k4++) {
        float4 w0 = __ldg(&W4[(k4 * 4 + 0) * 32 + cg]);
        float4 w1 = __ldg(&W4[(k4 * 4 + 1) * 32 + cg]);
        float4 w2 = __ldg(&W4[(k4 * 4 + 2) * 32 + cg]);
        float4 w3 = __ldg(&W4[(k4 * 4 + 3) * 32 + cg]);
        u64 wl0 = pk(w0.x, w0.y), wh0 = pk(w0.z, w0.w);
        u64 wl1 = pk(w1.x, w1.y), wh1 = pk(w1.z, w1.w);
        u64 wl2 = pk(w2.x, w2.y), wh2 = pk(w2.z, w2.w);
        u64 wl3 = pk(w3.x, w3.y), wh3 = pk(w3.z, w3.w);
#pragma unroll
        for (int j = 0; j < 4; j++) {
            float4 xv = sx[(rq * 4 + j) * 32 + k4];
            u64 x0 = pk(xv.x, xv.x), x1 = pk(xv.y, xv.y);
            u64 x2 = pk(xv.z, xv.z), x3 = pk(xv.w, xv.w);
            fma2(aL[j], x0, wl0); fma2(aH[j], x0, wh0);
            fma2(aL[j], x1, wl1); fma2(aH[j], x1, wh1);
            fma2(aL[j], x2, wl2); fma2(aH[j], x2, wh2);
            fma2(aL[j], x3, wl3); fma2(aH[j], x3, wh3);
        }
    }

    int h = cg >> 3;
    float4 alv = __ldg(&reinterpret_cast<const float4*>(al)[h * 8 + (cg & 7)]);
    float4 arv = __ldg(&reinterpret_cast<const float4*>(ar)[h * 8 + (cg & 7)]);
#pragma unroll
    for (int j = 0; j < 4; j++) {
        float2 lo = up(aL[j]), hi = up(aH[j]);
        float4 acc = make_float4(lo.x, lo.y, hi.x, hi.y);
        int row = rb + rq * 4 + j;
        // fp16 store: 4 halfs = uint2 per lane
        __half2 p0 = __float22half2_rn(make_float2(acc.x, acc.y));
        __half2 p1 = __float22half2_rn(make_float2(acc.z, acc.w));
        uint2 pkh;
        pkh.x = *reinterpret_cast<unsigned*>(&p0);
        pkh.y = *reinterpret_cast<unsigned*>(&p1);
        reinterpret_cast<uint2*>(g_feat)[(size_t)row * 32 + cg] = pkh;
        float pl = acc.x * alv.x + acc.y * alv.y + acc.z * alv.z + acc.w * alv.w;
        float pr = acc.x * arv.x + acc.y * arv.y + acc.z * arv.z + acc.w * arv.w;
#pragma unroll
        for (int o = 4; o; o >>= 1) {
            pl += __shfl_down_sync(0xffffffffu, pl, o, 8);
            pr += __shfl_down_sync(0xffffffffu, pr, o, 8);
        }
        if ((cg & 7) == 0) {
            g_el[row * 4 + h] = pl;
            g_er[row * 4 + h] = pr;
        }
    }
}

// ---------------- aggregation: one warp per dst node, single pass ----------------
// out = sum_e exp(e)*feat[src] / sum_e exp(e)  (softmax shift-invariance; no max pass)
__global__ void aggregate_kernel(int outWhich, int doPool) {
    __shared__ float  s_w[8][4][33];
    __shared__ int    s_src[8][32];
    __shared__ float4 s_red[256];
    float* outp = (outWhich == 1) ? g_actA : g_actB;
    int node = (blockIdx.x * blockDim.x + threadIdx.x) >> 5;
    int lane = threadIdx.x & 31;
    int w    = threadIdx.x >> 5;

    int s0  = g_rowptr[node];
    int deg = g_rowptr[node + 1] - s0;
    float4 acc = make_float4(0.f, 0.f, 0.f, 0.f);
    float q0 = 0.f, q1 = 0.f, q2 = 0.f, q3 = 0.f;

    if (deg > 0) {
        const float4* el4 = reinterpret_cast<const float4*>(g_el);
        float4 erd = reinterpret_cast<const float4*>(g_er)[node];
        int h = lane >> 3;
        const uint2* feat2 = reinterpret_cast<const uint2*>(g_feat);

        for (int base = 0; base < deg; base += 32) {
            int idx = base + lane;
            int s = 0;
            float w0 = 0.f, w1 = 0.f, w2 = 0.f, w3 = 0.f;
            if (idx < deg) {
                s = __ldg(&g_esrc[s0 + idx]);
                float4 ev = __ldg(&el4[s]);
                w0 = __expf(lrelu(ev.x + erd.x));
                w1 = __expf(lrelu(ev.y + erd.y));
                w2 = __expf(lrelu(ev.z + erd.z));
                w3 = __expf(lrelu(ev.w + erd.w));
                q0 += w0; q1 += w1; q2 += w2; q3 += w3;
            }
            __syncwarp();
            s_src[w][lane] = s;
            s_w[w][0][lane] = w0; s_w[w][1][lane] = w1;
            s_w[w][2][lane] = w2; s_w[w][3][lane] = w3;
            __syncwarp();
            int cnt = min(32, deg - base);
#pragma unroll 4
            for (int j = 0; j < cnt; j++) {
                int   sj = s_src[w][j];
                float aa = s_w[w][h][j];
                uint2 fraw = __ldg(&feat2[(size_t)sj * 32 + lane]);
                float2 f01 = __half22float2(*reinterpret_cast<__half2*>(&fraw.x));
                float2 f23 = __half22float2(*reinterpret_cast<__half2*>(&fraw.y));
                acc.x += f01.x * aa; acc.y += f01.y * aa;
                acc.z += f23.x * aa; acc.w += f23.y * aa;
            }
        }
        // total weight across the warp's edges
#pragma unroll
        for (int o = 16; o; o >>= 1) {
            q0 += __shfl_xor_sync(0xffffffffu, q0, o);
            q1 += __shfl_xor_sync(0xffffffffu, q1, o);
            q2 += __shfl_xor_sync(0xffffffffu, q2, o);
            q3 += __shfl_xor_sync(0xffffffffu, q3, o);
        }
        float qh = (h == 0) ? q0 : ((h == 1) ? q1 : ((h == 2) ? q2 : q3));
        float inv = 1.f / qh;
        acc.x *= inv; acc.y *= inv; acc.z *= inv; acc.w *= inv;
    }
    float4 o;       // ReLU every layer (layer 3: reference applies relu before pooling)
    o.x = fmaxf(acc.x, 0.f); o.y = fmaxf(acc.y, 0.f);
    o.z = fmaxf(acc.z, 0.f); o.w = fmaxf(acc.w, 0.f);

    if (!doPool) {
        reinterpret_cast<float4*>(outp)[(size_t)node * 32 + lane] = o;
    } else {
        // fused graph max-pool: block reduction + 1 atomicMax per column per block
        int t = threadIdx.x;
        s_red[t] = o;
        __syncthreads();
        if (t < 32) {
            float4 m = s_red[t];
#pragma unroll
            for (int i = 1; i < 8; i++) {
                float4 v = s_red[t + 32 * i];
                m.x = fmaxf(m.x, v.x); m.y = fmaxf(m.y, v.y);
                m.z = fmaxf(m.z, v.z); m.w = fmaxf(m.w, v.w);
            }
            atomicMax(reinterpret_cast<int*>(&g_pooled[t * 4 + 0]), __float_as_int(m.x));
            atomicMax(reinterpret_cast<int*>(&g_pooled[t * 4 + 1]), __float_as_int(m.y));
            atomicMax(reinterpret_cast<int*>(&g_pooled[t * 4 + 2]), __float_as_int(m.z));
            atomicMax(reinterpret_cast<int*>(&g_pooled[t * 4 + 3]), __float_as_int(m.w));
        }
    }
}

// ---------------- FC + softmax head ----------------
__global__ void head_kernel(const float* __restrict__ Wfc, const float* __restrict__ bfc,
                            float* __restrict__ out) {
    __shared__ float lg[8];
    int t = threadIdx.x;
    if (t < 8) {
        float acc = bfc[t];
        for (int k = 0; k < 128; k++) acc += g_pooled[k] * Wfc[k * 8 + t];
        lg[t] = acc;
    }
    __syncthreads();
    if (t == 0) {
        float m = lg[0];
        for (int i = 1; i < 8; i++) m = fmaxf(m, lg[i]);
        float e[8], s = 0.f;
        for (int i = 0; i < 8; i++) { e[i] = expf(lg[i] - m); s += e[i]; }
        for (int i = 0; i < 8; i++) out[i] = e[i] / s;
    }
}

// ---------------- launch ----------------
extern "C" void kernel_launch(void* const* d_in, const int* in_sizes, int n_in,
                              void* d_out, int out_size) {
    (void)in_sizes; (void)n_in; (void)out_size;
    const float* x   = (const float*)d_in[0];
    const int*   src = (const int*)d_in[1];
    const int*   dst = (const int*)d_in[2];
    const float* W1  = (const float*)d_in[3];
    const float* al1 = (const float*)d_in[4];
    const float* ar1 = (const float*)d_in[5];
    const float* W2  = (const float*)d_in[6];
    const float* al2 = (const float*)d_in[7];
    const float* ar2 = (const float*)d_in[8];
    const float* W3  = (const float*)d_in[9];
    const float* al3 = (const float*)d_in[10];
    const float* ar3 = (const float*)d_in[11];
    const float* Wfc = (const float*)d_in[12];
    const float* bfc = (const float*)d_in[13];
    float* out = (float*)d_out;

    init_kernel<<<(N_NODES + 255) / 256, 256>>>();
    count_kernel<<<(N_EDGES / 4 + 255) / 256, 256>>>(dst);
    scan1_kernel<<<NBLK_SCAN, 1024>>>();
    scan2_kernel<<<1, 128>>>();
    scan3_kernel<<<(N_NODES + 255) / 256, 256>>>();
    fill_kernel<<<(N_EDGES / 4 + 255) / 256, 256>>>(src, dst);

    // layer 1: x -> feat -> actA
    gemm_kernel<<<N_NODES / 32, 256>>>(x, 0, W1, al1, ar1);
    aggregate_kernel<<<N_NODES / 8, 256>>>(1, 0);
    // layer 2: actA -> feat -> actB
    gemm_kernel<<<N_NODES / 32, 256>>>(nullptr, 1, W2, al2, ar2);
    aggregate_kernel<<<N_NODES / 8, 256>>>(2, 0);
    // layer 3: actB -> feat -> (fused max-pool)
    gemm_kernel<<<N_NODES / 32, 256>>>(nullptr, 2, W3, al3, ar3);
    aggregate_kernel<<<N_NODES / 8, 256>>>(1, 1);

    head_kernel<<<1, 32>>>(Wfc, bfc, out);
}

// round 7
// speedup vs baseline: 1.6279x; 1.1378x over previous
#include <cuda_runtime.h>
#include <cuda_fp16.h>
#include <mma.h>
using namespace nvcuda;

#define N_NODES 100000
#define N_EDGES 1600000
#define NBLK_SCAN 98   // ceil(100000/1024)

// ---------------- scratch (allocation-free: __device__ globals) ----------------
__device__ __align__(16) __half g_feat[N_NODES * 128];   // fp16 transformed features
__device__ __align__(16) __half g_actA[N_NODES * 128];   // fp16 activations
__device__ __align__(16) __half g_actB[N_NODES * 128];
__device__ __align__(16) __half g_xh[N_NODES * 128];     // fp16 copy of input x
__device__ __align__(16) __half g_Wh[3][128 * 128];      // fp16 weights
__device__ __align__(16) float g_el[N_NODES * 4];
__device__ __align__(16) float g_er[N_NODES * 4];
__device__ int   g_rowptr[N_NODES + 1];
__device__ int   g_cursor[N_NODES];
__device__ int   g_deg[N_NODES];
__device__ int   g_esrc[N_EDGES];
__device__ int   g_bsum[128];
__device__ float g_pooled[128];

__device__ __forceinline__ float lrelu(float x) { return x > 0.f ? x : 0.2f * x; }

// ---------------- converts ----------------
__global__ void convW_kernel(const float* __restrict__ W1, const float* __restrict__ W2,
                             const float* __restrict__ W3) {
    int i = blockIdx.x * blockDim.x + threadIdx.x;
    if (i < 128 * 128) {
        g_Wh[0][i] = __float2half_rn(W1[i]);
        g_Wh[1][i] = __float2half_rn(W2[i]);
        g_Wh[2][i] = __float2half_rn(W3[i]);
    }
}

__global__ void convX_kernel(const float* __restrict__ x) {
    int i = blockIdx.x * blockDim.x + threadIdx.x;   // float4 index
    if (i < N_NODES * 32) {
        float4 v = __ldg(&reinterpret_cast<const float4*>(x)[i]);
        __half2 h0 = __float22half2_rn(make_float2(v.x, v.y));
        __half2 h1 = __float22half2_rn(make_float2(v.z, v.w));
        uint2 u;
        u.x = *reinterpret_cast<unsigned*>(&h0);
        u.y = *reinterpret_cast<unsigned*>(&h1);
        reinterpret_cast<uint2*>(g_xh)[i] = u;
    }
}

// ---------------- init: zero degree counts + pooled ----------------
__global__ void init_kernel() {
    int i = blockIdx.x * blockDim.x + threadIdx.x;
    if (i < N_NODES) g_deg[i] = 0;
    if (i < 128)     g_pooled[i] = 0.f;
}

// ---------------- CSR build (int4-vectorized edge reads) ----------------
__global__ void count_kernel(const int* __restrict__ dst) {
    int e4 = blockIdx.x * blockDim.x + threadIdx.x;
    if (e4 < N_EDGES / 4) {
        int4 d = __ldg(&reinterpret_cast<const int4*>(dst)[e4]);
        atomicAdd(&g_deg[d.x], 1);
        atomicAdd(&g_deg[d.y], 1);
        atomicAdd(&g_deg[d.z], 1);
        atomicAdd(&g_deg[d.w], 1);
    }
}

// parallel scan, 3 stages
__global__ void scan1_kernel() {          // NBLK_SCAN blocks x 1024
    __shared__ int wsum[32];
    int t = threadIdx.x, lane = t & 31, w = t >> 5;
    int i = blockIdx.x * 1024 + t;
    int v = (i < N_NODES) ? g_deg[i] : 0;
    int x = v;
#pragma unroll
    for (int o = 1; o < 32; o <<= 1) {
        int y = __shfl_up_sync(0xffffffffu, x, o);
        if (lane >= o) x += y;
    }
    if (lane == 31) wsum[w] = x;
    __syncthreads();
    if (w == 0) {
        int sv = wsum[lane];
#pragma unroll
        for (int o = 1; o < 32; o <<= 1) {
            int y = __shfl_up_sync(0xffffffffu, sv, o);
            if (lane >= o) sv += y;
        }
        wsum[lane] = sv;
    }
    __syncthreads();
    int incl = x + (w > 0 ? wsum[w - 1] : 0);
    if (i < N_NODES) g_rowptr[i + 1] = incl;          // block-local inclusive
    if (t == 1023)   g_bsum[blockIdx.x] = incl;       // block total
}

__global__ void scan2_kernel() {          // 1 block, 128 threads
    __shared__ int s[128];
    int t = threadIdx.x;
    int v = (t < NBLK_SCAN) ? g_bsum[t] : 0;
    s[t] = v; __syncthreads();
    for (int o = 1; o < 128; o <<= 1) {
        int y = (t >= o) ? s[t - o] : 0;
        __syncthreads();
        s[t] += y;
        __syncthreads();
    }
    if (t < NBLK_SCAN) g_bsum[t] = s[t] - v;          // exclusive block offset
}

__global__ void scan3_kernel() {
    int i = blockIdx.x * blockDim.x + threadIdx.x;
    if (i < N_NODES) {
        int r = g_rowptr[i + 1] + g_bsum[i >> 10];
        g_rowptr[i + 1] = r;
        g_cursor[i] = r - g_deg[i];
        if (i == 0) g_rowptr[0] = 0;
    }
}

__global__ void fill_kernel(const int* __restrict__ src, const int* __restrict__ dst) {
    int e4 = blockIdx.x * blockDim.x + threadIdx.x;
    if (e4 < N_EDGES / 4) {
        int4 s = __ldg(&reinterpret_cast<const int4*>(src)[e4]);
        int4 d = __ldg(&reinterpret_cast<const int4*>(dst)[e4]);
        g_esrc[atomicAdd(&g_cursor[d.x], 1)] = s.x;
        g_esrc[atomicAdd(&g_cursor[d.y], 1)] = s.y;
        g_esrc[atomicAdd(&g_cursor[d.z], 1)] = s.z;
        g_esrc[atomicAdd(&g_cursor[d.w], 1)] = s.w;
    }
}

// ---------------- tensor-core GEMM: feat = A @ W, fp16 in / fp32 acc ----------------
// BM=64 rows/block, 256 threads (8 warps). Warp w: row-tile rt=w&3 (16 rows),
// col-tiles ch*4..ch*4+3 (ch=w>>2, 4 x 16 cols). K=128 in 2 phases of 64.
// Epilogue: fp16 feat store + el/er dot-products from fp32 acc.
__global__ void gemm_mma_kernel(int which,
                                const float* __restrict__ al, const float* __restrict__ ar) {
    __shared__ __align__(16) char sbuf[35840];
    __half* sA = reinterpret_cast<__half*>(sbuf);            // 64 x 136 halfs (17408 B)
    __half* sB = reinterpret_cast<__half*>(sbuf + 17408);    // 64 x 136 halfs
    float*  sC = reinterpret_cast<float*>(sbuf);             // 64 x 128 f32 (reuses sA/sB)

    const __half* A  = (which == 0) ? g_xh : ((which == 1) ? g_actA : g_actB);
    const __half* Wh = g_Wh[which];

    int t  = threadIdx.x;
    int rb = blockIdx.x * 64;
    int w  = t >> 5;
    int rt = w & 3, ch = w >> 2;

    // load A tile: 64 rows x 128 halfs (16B chunks), zero-pad OOB rows
    for (int i = t; i < 1024; i += 256) {
        int r = i >> 4, s = i & 15;
        uint4 v = make_uint4(0, 0, 0, 0);
        if (rb + r < N_NODES)
            v = *reinterpret_cast<const uint4*>(&A[(size_t)(rb + r) * 128 + s * 8]);
        *reinterpret_cast<uint4*>(&sA[r * 136 + s * 8]) = v;
    }

    wmma::fragment<wmma::matrix_a, 16, 16, 16, __half, wmma::row_major> af;
    wmma::fragment<wmma::matrix_b, 16, 16, 16, __half, wmma::row_major> bf;
    wmma::fragment<wmma::accumulator, 16, 16, 16, float> acc[4];
#pragma unroll
    for (int i = 0; i < 4; i++) wmma::fill_fragment(acc[i], 0.f);

#pragma unroll
    for (int p = 0; p < 2; p++) {
        for (int i = t; i < 1024; i += 256) {      // load W rows p*64..p*64+63
            int r = i >> 4, s = i & 15;
            *reinterpret_cast<uint4*>(&sB[r * 136 + s * 8]) =
                *reinterpret_cast<const uint4*>(&Wh[(p * 64 + r) * 128 + s * 8]);
        }
        __syncthreads();
#pragma unroll
        for (int k = 0; k < 4; k++) {
            wmma::load_matrix_sync(af, sA + rt * 16 * 136 + p * 64 + k * 16, 136);
#pragma unroll
            for (int i = 0; i < 4; i++) {
                wmma::load_matrix_sync(bf, sB + (k * 16) * 136 + (ch * 4 + i) * 16, 136);
                wmma::mma_sync(acc[i], af, bf, acc[i]);
            }
        }
        __syncthreads();
    }

    // stage fp32 results in smem (aliases sA/sB — all mma done)
#pragma unroll
    for (int i = 0; i < 4; i++)
        wmma::store_matrix_sync(sC + rt * 16 * 128 + (ch * 4 + i) * 16, acc[i],
                                128, wmma::mem_row_major);
    __syncthreads();

    // epilogue A: fp16 feat store. thread t -> row r=t>>2, col-quarter part=t&3
    {
        int r = t >> 2, part = t & 3;
        if (rb + r < N_NODES) {
            uint2* dstp = reinterpret_cast<uint2*>(g_feat) + (size_t)(rb + r) * 32 + part * 8;
#pragma unroll
            for (int c8 = 0; c8 < 8; c8++) {
                float4 v = *reinterpret_cast<float4*>(&sC[r * 128 + part * 32 + c8 * 4]);
                __half2 h0 = __float22half2_rn(make_float2(v.x, v.y));
                __half2 h1 = __float22half2_rn(make_float2(v.z, v.w));
                uint2 u;
                u.x = *reinterpret_cast<unsigned*>(&h0);
                u.y = *reinterpret_cast<unsigned*>(&h1);
                dstp[c8] = u;
            }
        }
    }
    // epilogue B: el/er. thread t -> row r=t>>2, head h=t&3 (32-elem dots)
    {
        int r = t >> 2, h = t & 3;
        if (rb + r < N_NODES) {
            float pl = 0.f, pr = 0.f;
            const float* row = &sC[r * 128 + h * 32];
#pragma unroll
            for (int c = 0; c < 32; c++) {
                float f = row[c];
                pl += f * __ldg(&al[h * 32 + c]);
                pr += f * __ldg(&ar[h * 32 + c]);
            }
            g_el[(rb + r) * 4 + h] = pl;
            g_er[(rb + r) * 4 + h] = pr;
        }
    }
}

// ---------------- aggregation: one warp per dst node, single pass ----------------
// out = sum_e exp(e)*feat[src] / sum_e exp(e)  (softmax shift-invariance; no max pass)
__global__ void aggregate_kernel(int outWhich, int doPool) {
    __shared__ float  s_w[8][4][33];
    __shared__ int    s_src[8][32];
    __shared__ float4 s_red[256];
    __half* outp = (outWhich == 1) ? g_actA : g_actB;
    int node = (blockIdx.x * blockDim.x + threadIdx.x) >> 5;
    int lane = threadIdx.x & 31;
    int w    = threadIdx.x >> 5;

    int s0  = g_rowptr[node];
    int deg = g_rowptr[node + 1] - s0;
    float4 acc = make_float4(0.f, 0.f, 0.f, 0.f);
    float q0 = 0.f, q1 = 0.f, q2 = 0.f, q3 = 0.f;
    int h = lane >> 3;

    if (deg > 0) {
        const float4* el4 = reinterpret_cast<const float4*>(g_el);
        float4 erd = reinterpret_cast<const float4*>(g_er)[node];
        const uint2* feat2 = reinterpret_cast<const uint2*>(g_feat);

        for (int base = 0; base < deg; base += 32) {
            int idx = base + lane;
            int s = 0;
            float w0 = 0.f, w1 = 0.f, w2 = 0.f, w3 = 0.f;
            if (idx < deg) {
                s = __ldg(&g_esrc[s0 + idx]);
                float4 ev = __ldg(&el4[s]);
                w0 = __expf(lrelu(ev.x + erd.x));
                w1 = __expf(lrelu(ev.y + erd.y));
                w2 = __expf(lrelu(ev.z + erd.z));
                w3 = __expf(lrelu(ev.w + erd.w));
                q0 += w0; q1 += w1; q2 += w2; q3 += w3;
            }
            __syncwarp();
            s_src[w][lane] = s;
            s_w[w][0][lane] = w0; s_w[w][1][lane] = w1;
            s_w[w][2][lane] = w2; s_w[w][3][lane] = w3;
            __syncwarp();
            int cnt = min(32, deg - base);
#pragma unroll 4
            for (int j = 0; j < cnt; j++) {
                int   sj = s_src[w][j];
                float aa = s_w[w][h][j];
                uint2 fraw = __ldg(&feat2[(size_t)sj * 32 + lane]);
                float2 f01 = __half22float2(*reinterpret_cast<__half2*>(&fraw.x));
                float2 f23 = __half22float2(*reinterpret_cast<__half2*>(&fraw.y));
                acc.x += f01.x * aa; acc.y += f01.y * aa;
                acc.z += f23.x * aa; acc.w += f23.y * aa;
            }
        }
        // total weight across the warp's edges
#pragma unroll
        for (int o = 16; o; o >>= 1) {
            q0 += __shfl_xor_sync(0xffffffffu, q0, o);
            q1 += __shfl_xor_sync(0xffffffffu, q1, o);
            q2 += __shfl_xor_sync(0xffffffffu, q2, o);
            q3 += __shfl_xor_sync(0xffffffffu, q3, o);
        }
        float qh = (h == 0) ? q0 : ((h == 1) ? q1 : ((h == 2) ? q2 : q3));
        float inv = 1.f / qh;
        acc.x *= inv; acc.y *= inv; acc.z *= inv; acc.w *= inv;
    }
    float4 o;       // ReLU every layer (layer 3: reference applies relu before pooling)
    o.x = fmaxf(acc.x, 0.f); o.y = fmaxf(acc.y, 0.f);
    o.z = fmaxf(acc.z, 0.f); o.w = fmaxf(acc.w, 0.f);

    if (!doPool) {
        __half2 h0 = __float22half2_rn(make_float2(o.x, o.y));
        __half2 h1 = __float22half2_rn(make_float2(o.z, o.w));
        uint2 u;
        u.x = *reinterpret_cast<unsigned*>(&h0);
        u.y = *reinterpret_cast<unsigned*>(&h1);
        reinterpret_cast<uint2*>(outp)[(size_t)node * 32 + lane] = u;
    } else {
        // fused graph max-pool: block reduction + 1 atomicMax per column per block
        int t = threadIdx.x;
        s_red[t] = o;
        __syncthreads();
        if (t < 32) {
            float4 m = s_red[t];
#pragma unroll
            for (int i = 1; i < 8; i++) {
                float4 v = s_red[t + 32 * i];
                m.x = fmaxf(m.x, v.x); m.y = fmaxf(m.y, v.y);
                m.z = fmaxf(m.z, v.z); m.w = fmaxf(m.w, v.w);
            }
            atomicMax(reinterpret_cast<int*>(&g_pooled[t * 4 + 0]), __float_as_int(m.x));
            atomicMax(reinterpret_cast<int*>(&g_pooled[t * 4 + 1]), __float_as_int(m.y));
            atomicMax(reinterpret_cast<int*>(&g_pooled[t * 4 + 2]), __float_as_int(m.z));
            atomicMax(reinterpret_cast<int*>(&g_pooled[t * 4 + 3]), __float_as_int(m.w));
        }
    }
}

// ---------------- FC + softmax head ----------------
__global__ void head_kernel(const float* __restrict__ Wfc, const float* __restrict__ bfc,
                            float* __restrict__ out) {
    __shared__ float lg[8];
    int t = threadIdx.x;
    if (t < 8) {
        float acc = bfc[t];
        for (int k = 0; k < 128; k++) acc += g_pooled[k] * Wfc[k * 8 + t];
        lg[t] = acc;
    }
    __syncthreads();
    if (t == 0) {
        float m = lg[0];
        for (int i = 1; i < 8; i++) m = fmaxf(m, lg[i]);
        float e[8], s = 0.f;
        for (int i = 0; i < 8; i++) { e[i] = expf(lg[i] - m); s += e[i]; }
        for (int i = 0; i < 8; i++) out[i] = e[i] / s;
    }
}

// ---------------- launch ----------------
extern "C" void kernel_launch(void* const* d_in, const int* in_sizes, int n_in,
                              void* d_out, int out_size) {
    (void)in_sizes; (void)n_in; (void)out_size;
    const float* x   = (const float*)d_in[0];
    const int*   src = (const int*)d_in[1];
    const int*   dst = (const int*)d_in[2];
    const float* W1  = (const float*)d_in[3];
    const float* al1 = (const float*)d_in[4];
    const float* ar1 = (const float*)d_in[5];
    const float* W2  = (const float*)d_in[6];
    const float* al2 = (const float*)d_in[7];
    const float* ar2 = (const float*)d_in[8];
    const float* W3  = (const float*)d_in[9];
    const float* al3 = (const float*)d_in[10];
    const float* ar3 = (const float*)d_in[11];
    const float* Wfc = (const float*)d_in[12];
    const float* bfc = (const float*)d_in[13];
    float* out = (float*)d_out;

    const int GEMM_BLOCKS = (N_NODES + 63) / 64;   // 1563

    // ordered so launch #4 (the ncu-captured one) is gemm_mma layer 1
    convW_kernel<<<64, 256>>>(W1, W2, W3);
    convX_kernel<<<(N_NODES * 32 + 255) / 256, 256>>>(x);
    init_kernel<<<(N_NODES + 255) / 256, 256>>>();
    gemm_mma_kernel<<<GEMM_BLOCKS, 256>>>(0, al1, ar1);     // layer 1 GEMM (profiled)

    count_kernel<<<(N_EDGES / 4 + 255) / 256, 256>>>(dst);
    scan1_kernel<<<NBLK_SCAN, 1024>>>();
    scan2_kernel<<<1, 128>>>();
    scan3_kernel<<<(N_NODES + 255) / 256, 256>>>();
    fill_kernel<<<(N_EDGES / 4 + 255) / 256, 256>>>(src, dst);

    aggregate_kernel<<<N_NODES / 8, 256>>>(1, 0);           // layer 1 -> actA
    gemm_mma_kernel<<<GEMM_BLOCKS, 256>>>(1, al2, ar2);     // layer 2 GEMM
    aggregate_kernel<<<N_NODES / 8, 256>>>(2, 0);           // layer 2 -> actB
    gemm_mma_kernel<<<GEMM_BLOCKS, 256>>>(2, al3, ar3);     // layer 3 GEMM
    aggregate_kernel<<<N_NODES / 8, 256>>>(1, 1);           // layer 3 + fused pool

    head_kernel<<<1, 32>>>(Wfc, bfc, out);
}

// round 9
// speedup vs baseline: 1.7413x; 1.0697x over previous
#include <cuda_runtime.h>
#include <cuda_fp16.h>
#include <mma.h>
using namespace nvcuda;

#define N_NODES 100000
#define N_EDGES 1600000
#define NBLK_SCAN 98   // ceil(100000/1024)

// ---------------- scratch (allocation-free: __device__ globals) ----------------
__device__ __align__(16) __half g_feat[N_NODES * 128];   // fp16 transformed features
__device__ __align__(16) __half g_actA[N_NODES * 128];   // fp16 activations
__device__ __align__(16) __half g_actB[N_NODES * 128];
__device__ __align__(16) __half g_xh[N_NODES * 128];     // fp16 copy of input x
__device__ __align__(16) __half g_Wh[3][128 * 128];      // fp16 weights
__device__ __align__(16) float g_el[N_NODES * 4];
__device__ __align__(16) float g_er[N_NODES * 4];
__device__ int   g_rowptr[N_NODES + 1];
__device__ int   g_cursor[N_NODES];
__device__ int   g_deg[N_NODES];
__device__ int   g_esrc[N_EDGES];
__device__ int   g_bsum[128];
__device__ float g_pooled[128];

__device__ __forceinline__ float lrelu(float x) { return x > 0.f ? x : 0.2f * x; }

// ---------------- converts ----------------
__global__ void convW_kernel(const float* __restrict__ W1, const float* __restrict__ W2,
                             const float* __restrict__ W3) {
    int i = blockIdx.x * blockDim.x + threadIdx.x;
    if (i < 128 * 128) {
        g_Wh[0][i] = __float2half_rn(W1[i]);
        g_Wh[1][i] = __float2half_rn(W2[i]);
        g_Wh[2][i] = __float2half_rn(W3[i]);
    }
}

__global__ void convX_kernel(const float* __restrict__ x) {
    int i = blockIdx.x * blockDim.x + threadIdx.x;   // float4 index
    if (i < N_NODES * 32) {
        float4 v = __ldg(&reinterpret_cast<const float4*>(x)[i]);
        __half2 h0 = __float22half2_rn(make_float2(v.x, v.y));
        __half2 h1 = __float22half2_rn(make_float2(v.z, v.w));
        uint2 u;
        u.x = *reinterpret_cast<unsigned*>(&h0);
        u.y = *reinterpret_cast<unsigned*>(&h1);
        reinterpret_cast<uint2*>(g_xh)[i] = u;
    }
}

// ---------------- init: zero degree counts + pooled ----------------
__global__ void init_kernel() {
    int i = blockIdx.x * blockDim.x + threadIdx.x;
    if (i < N_NODES) g_deg[i] = 0;
    if (i < 128)     g_pooled[i] = 0.f;
}

// ---------------- CSR build (int4-vectorized edge reads) ----------------
__global__ void count_kernel(const int* __restrict__ dst) {
    int e4 = blockIdx.x * blockDim.x + threadIdx.x;
    if (e4 < N_EDGES / 4) {
        int4 d = __ldg(&reinterpret_cast<const int4*>(dst)[e4]);
        atomicAdd(&g_deg[d.x], 1);
        atomicAdd(&g_deg[d.y], 1);
        atomicAdd(&g_deg[d.z], 1);
        atomicAdd(&g_deg[d.w], 1);
    }
}

// parallel scan, 3 stages
__global__ void scan1_kernel() {          // NBLK_SCAN blocks x 1024
    __shared__ int wsum[32];
    int t = threadIdx.x, lane = t & 31, w = t >> 5;
    int i = blockIdx.x * 1024 + t;
    int v = (i < N_NODES) ? g_deg[i] : 0;
    int x = v;
#pragma unroll
    for (int o = 1; o < 32; o <<= 1) {
        int y = __shfl_up_sync(0xffffffffu, x, o);
        if (lane >= o) x += y;
    }
    if (lane == 31) wsum[w] = x;
    __syncthreads();
    if (w == 0) {
        int sv = wsum[lane];
#pragma unroll
        for (int o = 1; o < 32; o <<= 1) {
            int y = __shfl_up_sync(0xffffffffu, sv, o);
            if (lane >= o) sv += y;
        }
        wsum[lane] = sv;
    }
    __syncthreads();
    int incl = x + (w > 0 ? wsum[w - 1] : 0);
    if (i < N_NODES) g_rowptr[i + 1] = incl;          // block-local inclusive
    if (t == 1023)   g_bsum[blockIdx.x] = incl;       // block total
}

__global__ void scan2_kernel() {          // 1 block, 128 threads
    __shared__ int s[128];
    int t = threadIdx.x;
    int v = (t < NBLK_SCAN) ? g_bsum[t] : 0;
    s[t] = v; __syncthreads();
    for (int o = 1; o < 128; o <<= 1) {
        int y = (t >= o) ? s[t - o] : 0;
        __syncthreads();
        s[t] += y;
        __syncthreads();
    }
    if (t < NBLK_SCAN) g_bsum[t] = s[t] - v;          // exclusive block offset
}

__global__ void scan3_kernel() {
    int i = blockIdx.x * blockDim.x + threadIdx.x;
    if (i < N_NODES) {
        int r = g_rowptr[i + 1] + g_bsum[i >> 10];
        g_rowptr[i + 1] = r;
        g_cursor[i] = r - g_deg[i];
        if (i == 0) g_rowptr[0] = 0;
    }
}

__global__ void fill_kernel(const int* __restrict__ src, const int* __restrict__ dst) {
    int e4 = blockIdx.x * blockDim.x + threadIdx.x;
    if (e4 < N_EDGES / 4) {
        int4 s = __ldg(&reinterpret_cast<const int4*>(src)[e4]);
        int4 d = __ldg(&reinterpret_cast<const int4*>(dst)[e4]);
        g_esrc[atomicAdd(&g_cursor[d.x], 1)] = s.x;
        g_esrc[atomicAdd(&g_cursor[d.y], 1)] = s.y;
        g_esrc[atomicAdd(&g_cursor[d.z], 1)] = s.z;
        g_esrc[atomicAdd(&g_cursor[d.w], 1)] = s.w;
    }
}

// ---------------- tensor-core GEMM: feat = A @ W, fp16 in / fp32 acc ----------------
// BM=128, 256 threads (8 warps), warp tile 32x64 (2x4 warp grid: wr=w&3, wc=w>>2).
// W loaded once (full K=128). sC staged at stride 132 (conflict-free), fused
// vectorized epilogue: fp16 feat store + el/er dots with al/ar cached in smem.
#define SMEM_GEMM (69632 + 1024)
__global__ void gemm_mma_kernel(int which,
                                const float* __restrict__ al, const float* __restrict__ ar) {
    extern __shared__ __align__(16) char sbuf[];
    __half* sA  = reinterpret_cast<__half*>(sbuf);            // 128 x 136 halfs (34816 B)
    __half* sB  = reinterpret_cast<__half*>(sbuf + 34816);    // 128 x 136 halfs
    float*  sC  = reinterpret_cast<float*>(sbuf);             // 128 x 132 f32 (aliases sA/sB)
    float*  sal = reinterpret_cast<float*>(sbuf + 69632);     // 128 f32
    float*  sar = sal + 128;

    const __half* A  = (which == 0) ? g_xh : ((which == 1) ? g_actA : g_actB);
    const __half* Wh = g_Wh[which];

    int t  = threadIdx.x;
    int rb = blockIdx.x * 128;
    int w  = t >> 5;
    int wr = w & 3, wc = w >> 2;

    // stage al/ar (256 threads -> 256 floats)
    if (t < 128) sal[t] = __ldg(&al[t]);
    else         sar[t - 128] = __ldg(&ar[t - 128]);

    // load A tile: 128 rows x 128 halfs (16B chunks), zero-pad OOB rows
    for (int i = t; i < 2048; i += 256) {
        int r = i >> 4, s = i & 15;
        uint4 v = make_uint4(0, 0, 0, 0);
        if (rb + r < N_NODES)
            v = *reinterpret_cast<const uint4*>(&A[(size_t)(rb + r) * 128 + s * 8]);
        *reinterpret_cast<uint4*>(&sA[r * 136 + s * 8]) = v;
    }
    // load full W: 128 x 128 halfs
    for (int i = t; i < 2048; i += 256) {
        int r = i >> 4, s = i & 15;
        *reinterpret_cast<uint4*>(&sB[r * 136 + s * 8]) =
            *reinterpret_cast<const uint4*>(&Wh[r * 128 + s * 8]);
    }
    __syncthreads();

    wmma::fragment<wmma::matrix_a, 16, 16, 16, __half, wmma::row_major> af0, af1;
    wmma::fragment<wmma::matrix_b, 16, 16, 16, __half, wmma::row_major> bf;
    wmma::fragment<wmma::accumulator, 16, 16, 16, float> acc[2][4];
#pragma unroll
    for (int r2 = 0; r2 < 2; r2++)
#pragma unroll
        for (int i = 0; i < 4; i++) wmma::fill_fragment(acc[r2][i], 0.f);

#pragma unroll
    for (int k = 0; k < 8; k++) {
        wmma::load_matrix_sync(af0, sA + (wr * 32 +  0) * 136 + k * 16, 136);
        wmma::load_matrix_sync(af1, sA + (wr * 32 + 16) * 136 + k * 16, 136);
#pragma unroll
        for (int i = 0; i < 4; i++) {
            wmma::load_matrix_sync(bf, sB + (k * 16) * 136 + (wc * 64 + i * 16), 136);
            wmma::mma_sync(acc[0][i], af0, bf, acc[0][i]);
            wmma::mma_sync(acc[1][i], af1, bf, acc[1][i]);
        }
    }
    __syncthreads();   // done reading sA/sB; sC aliases them

#pragma unroll
    for (int r2 = 0; r2 < 2; r2++)
#pragma unroll
        for (int i = 0; i < 4; i++)
            wmma::store_matrix_sync(sC + (wr * 32 + r2 * 16) * 132 + (wc * 64 + i * 16),
                                    acc[r2][i], 132, wmma::mem_row_major);
    __syncthreads();

    // fused epilogue: thread t -> rows {t>>2, t>>2+64}, head h=t&3 (32 cols = 4 uint4)
    int h = t & 3;
    float4 al4[8], ar4[8];
#pragma unroll
    for (int c4 = 0; c4 < 8; c4++) {
        al4[c4] = *reinterpret_cast<float4*>(&sal[h * 32 + c4 * 4]);
        ar4[c4] = *reinterpret_cast<float4*>(&sar[h * 32 + c4 * 4]);
    }
#pragma unroll
    for (int half_ = 0; half_ < 2; half_++) {
        int r = (t >> 2) + half_ * 64;
        int row = rb + r;
        if (row < N_NODES) {
            float pl = 0.f, pr = 0.f;
            uint4 packo[4];                      // 32 halfs = 16 unsigned = 4 uint4
            unsigned* pw = reinterpret_cast<unsigned*>(packo);
#pragma unroll
            for (int c4 = 0; c4 < 8; c4++) {
                float4 v = *reinterpret_cast<float4*>(&sC[r * 132 + h * 32 + c4 * 4]);
                pl += v.x * al4[c4].x + v.y * al4[c4].y + v.z * al4[c4].z + v.w * al4[c4].w;
                pr += v.x * ar4[c4].x + v.y * ar4[c4].y + v.z * ar4[c4].z + v.w * ar4[c4].w;
                __half2 h0 = __float22half2_rn(make_float2(v.x, v.y));
                __half2 h1 = __float22half2_rn(make_float2(v.z, v.w));
                pw[c4 * 2 + 0] = *reinterpret_cast<unsigned*>(&h0);
                pw[c4 * 2 + 1] = *reinterpret_cast<unsigned*>(&h1);
            }
            uint4* dstp = reinterpret_cast<uint4*>(g_feat) + (size_t)row * 16 + h * 4;
            dstp[0] = packo[0];
            dstp[1] = packo[1];
            dstp[2] = packo[2];
            dstp[3] = packo[3];
            g_el[row * 4 + h] = pl;
            g_er[row * 4 + h] = pr;
        }
    }
}

// ---------------- aggregation: one warp per dst node, single pass ----------------
// out = sum_e exp(e)*feat[src] / sum_e exp(e)  (softmax shift-invariance; no max pass)
__global__ void aggregate_kernel(int outWhich, int doPool) {
    __shared__ float  s_w[8][4][33];
    __shared__ int    s_src[8][32];
    __shared__ float4 s_red[256];
    __half* outp = (outWhich == 1) ? g_actA : g_actB;
    int node = (blockIdx.x * blockDim.x + threadIdx.x) >> 5;
    int lane = threadIdx.x & 31;
    int w    = threadIdx.x >> 5;

    int s0  = g_rowptr[node];
    int deg = g_rowptr[node + 1] - s0;
    float4 acc = make_float4(0.f, 0.f, 0.f, 0.f);
    float q0 = 0.f, q1 = 0.f, q2 = 0.f, q3 = 0.f;
    int h = lane >> 3;

    if (deg > 0) {
        const float4* el4 = reinterpret_cast<const float4*>(g_el);
        float4 erd = reinterpret_cast<const float4*>(g_er)[node];
        const uint2* feat2 = reinterpret_cast<const uint2*>(g_feat);

        for (int base = 0; base < deg; base += 32) {
            int idx = base + lane;
            int s = 0;
            float w0 = 0.f, w1 = 0.f, w2 = 0.f, w3 = 0.f;
            if (idx < deg) {
                s = __ldg(&g_esrc[s0 + idx]);
                float4 ev = __ldg(&el4[s]);
                w0 = __expf(lrelu(ev.x + erd.x));
                w1 = __expf(lrelu(ev.y + erd.y));
                w2 = __expf(lrelu(ev.z + erd.z));
                w3 = __expf(lrelu(ev.w + erd.w));
                q0 += w0; q1 += w1; q2 += w2; q3 += w3;
            }
            __syncwarp();
            s_src[w][lane] = s;
            s_w[w][0][lane] = w0; s_w[w][1][lane] = w1;
            s_w[w][2][lane] = w2; s_w[w][3][lane] = w3;
            __syncwarp();
            int cnt = min(32, deg - base);
#pragma unroll 4
            for (int j = 0; j < cnt; j++) {
                int   sj = s_src[w][j];
                float aa = s_w[w][h][j];
                uint2 fraw = __ldg(&feat2[(size_t)sj * 32 + lane]);
                float2 f01 = __half22float2(*reinterpret_cast<__half2*>(&fraw.x));
                float2 f23 = __half22float2(*reinterpret_cast<__half2*>(&fraw.y));
                acc.x += f01.x * aa; acc.y += f01.y * aa;
                acc.z += f23.x * aa; acc.w += f23.y * aa;
            }
        }
        // total weight across the warp's edges
#pragma unroll
        for (int o = 16; o; o >>= 1) {
            q0 += __shfl_xor_sync(0xffffffffu, q0, o);
            q1 += __shfl_xor_sync(0xffffffffu, q1, o);
            q2 += __shfl_xor_sync(0xffffffffu, q2, o);
            q3 += __shfl_xor_sync(0xffffffffu, q3, o);
        }
        float qh = (h == 0) ? q0 : ((h == 1) ? q1 : ((h == 2) ? q2 : q3));
        float inv = 1.f / qh;
        acc.x *= inv; acc.y *= inv; acc.z *= inv; acc.w *= inv;
    }
    float4 o;       // ReLU every layer (layer 3: reference applies relu before pooling)
    o.x = fmaxf(acc.x, 0.f); o.y = fmaxf(acc.y, 0.f);
    o.z = fmaxf(acc.z, 0.f); o.w = fmaxf(acc.w, 0.f);

    if (!doPool) {
        __half2 h0 = __float22half2_rn(make_float2(o.x, o.y));
        __half2 h1 = __float22half2_rn(make_float2(o.z, o.w));
        uint2 u;
        u.x = *reinterpret_cast<unsigned*>(&h0);
        u.y = *reinterpret_cast<unsigned*>(&h1);
        reinterpret_cast<uint2*>(outp)[(size_t)node * 32 + lane] = u;
    } else {
        // fused graph max-pool: block reduction + 1 atomicMax per column per block
        int t = threadIdx.x;
        s_red[t] = o;
        __syncthreads();
        if (t < 32) {
            float4 m = s_red[t];
#pragma unroll
            for (int i = 1; i < 8; i++) {
                float4 v = s_red[t + 32 * i];
                m.x = fmaxf(m.x, v.x); m.y = fmaxf(m.y, v.y);
                m.z = fmaxf(m.z, v.z); m.w = fmaxf(m.w, v.w);
            }
            atomicMax(reinterpret_cast<int*>(&g_pooled[t * 4 + 0]), __float_as_int(m.x));
            atomicMax(reinterpret_cast<int*>(&g_pooled[t * 4 + 1]), __float_as_int(m.y));
            atomicMax(reinterpret_cast<int*>(&g_pooled[t * 4 + 2]), __float_as_int(m.z));
            atomicMax(reinterpret_cast<int*>(&g_pooled[t * 4 + 3]), __float_as_int(m.w));
        }
    }
}

// ---------------- FC + softmax head ----------------
__global__ void head_kernel(const float* __restrict__ Wfc, const float* __restrict__ bfc,
                            float* __restrict__ out) {
    __shared__ float lg[8];
    int t = threadIdx.x;
    if (t < 8) {
        float acc = bfc[t];
        for (int k = 0; k < 128; k++) acc += g_pooled[k] * Wfc[k * 8 + t];
        lg[t] = acc;
    }
    __syncthreads();
    if (t == 0) {
        float m = lg[0];
        for (int i = 1; i < 8; i++) m = fmaxf(m, lg[i]);
        float e[8], s = 0.f;
        for (int i = 0; i < 8; i++) { e[i] = expf(lg[i] - m); s += e[i]; }
        for (int i = 0; i < 8; i++) out[i] = e[i] / s;
    }
}

// ---------------- launch ----------------
extern "C" void kernel_launch(void* const* d_in, const int* in_sizes, int n_in,
                              void* d_out, int out_size) {
    (void)in_sizes; (void)n_in; (void)out_size;
    const float* x   = (const float*)d_in[0];
    const int*   src = (const int*)d_in[1];
    const int*   dst = (const int*)d_in[2];
    const float* W1  = (const float*)d_in[3];
    const float* al1 = (const float*)d_in[4];
    const float* ar1 = (const float*)d_in[5];
    const float* W2  = (const float*)d_in[6];
    const float* al2 = (const float*)d_in[7];
    const float* ar2 = (const float*)d_in[8];
    const float* W3  = (const float*)d_in[9];
    const float* al3 = (const float*)d_in[10];
    const float* ar3 = (const float*)d_in[11];
    const float* Wfc = (const float*)d_in[12];
    const float* bfc = (const float*)d_in[13];
    float* out = (float*)d_out;

    cudaFuncSetAttribute(gemm_mma_kernel,
                         cudaFuncAttributeMaxDynamicSharedMemorySize, SMEM_GEMM);

    const int GEMM_BLOCKS = (N_NODES + 127) / 128;   // 782

    // ordered so launch #4 (the ncu-captured slot) is gemm_mma layer 1
    convW_kernel<<<64, 256>>>(W1, W2, W3);
    convX_kernel<<<(N_NODES * 32 + 255) / 256, 256>>>(x);
    init_kernel<<<(N_NODES + 255) / 256, 256>>>();
    gemm_mma_kernel<<<GEMM_BLOCKS, 256, SMEM_GEMM>>>(0, al1, ar1);   // layer 1 (profiled)

    count_kernel<<<(N_EDGES / 4 + 255) / 256, 256>>>(dst);
    scan1_kernel<<<NBLK_SCAN, 1024>>>();
    scan2_kernel<<<1, 128>>>();
    scan3_kernel<<<(N_NODES + 255) / 256, 256>>>();
    fill_kernel<<<(N_EDGES / 4 + 255) / 256, 256>>>(src, dst);

    aggregate_kernel<<<N_NODES / 8, 256>>>(1, 0);                    // layer 1 -> actA
    gemm_mma_kernel<<<GEMM_BLOCKS, 256, SMEM_GEMM>>>(1, al2, ar2);   // layer 2
    aggregate_kernel<<<N_NODES / 8, 256>>>(2, 0);                    // layer 2 -> actB
    gemm_mma_kernel<<<GEMM_BLOCKS, 256, SMEM_GEMM>>>(2, al3, ar3);   // layer 3
    aggregate_kernel<<<N_NODES / 8, 256>>>(1, 1);                    // layer 3 + fused pool

    head_kernel<<<1, 32>>>(Wfc, bfc, out);
}

// round 10
// speedup vs baseline: 2.5073x; 1.4399x over previous
#include <cuda_runtime.h>
#include <cuda_fp16.h>
#include <mma.h>
using namespace nvcuda;

#define N_NODES 100000
#define N_EDGES 1600000
#define NBLK_SCAN 98   // ceil(100000/1024)

// ---------------- scratch (allocation-free: __device__ globals) ----------------
__device__ __align__(16) __half g_feat[N_NODES * 128];   // fp16 transformed features
__device__ __align__(16) __half g_actA[N_NODES * 128];   // fp16 activations
__device__ __align__(16) __half g_actB[N_NODES * 128];
__device__ __align__(16) __half g_Wh[3][128 * 128];      // fp16 weights
__device__ __align__(16) float g_el[N_NODES * 4];
__device__ __align__(16) float g_er[N_NODES * 4];
__device__ int   g_rowptr[N_NODES + 1];
__device__ int   g_cursor[N_NODES];
__device__ int   g_deg[N_NODES];
__device__ int   g_esrc[N_EDGES];
__device__ int   g_bsum[128];
__device__ float g_pooled[128];

__device__ __forceinline__ float lrelu(float x) { return x > 0.f ? x : 0.2f * x; }

// ---------------- converts ----------------
__global__ void convW_kernel(const float* __restrict__ W1, const float* __restrict__ W2,
                             const float* __restrict__ W3) {
    int i = blockIdx.x * blockDim.x + threadIdx.x;
    if (i < 128 * 128) {
        g_Wh[0][i] = __float2half_rn(W1[i]);
        g_Wh[1][i] = __float2half_rn(W2[i]);
        g_Wh[2][i] = __float2half_rn(W3[i]);
    }
}

// ---------------- init: zero degree counts + pooled ----------------
__global__ void init_kernel() {
    int i = blockIdx.x * blockDim.x + threadIdx.x;
    if (i < N_NODES) g_deg[i] = 0;
    if (i < 128)     g_pooled[i] = 0.f;
}

// ---------------- CSR build (int4-vectorized edge reads) ----------------
__global__ void count_kernel(const int* __restrict__ dst) {
    int e4 = blockIdx.x * blockDim.x + threadIdx.x;
    if (e4 < N_EDGES / 4) {
        int4 d = __ldg(&reinterpret_cast<const int4*>(dst)[e4]);
        atomicAdd(&g_deg[d.x], 1);
        atomicAdd(&g_deg[d.y], 1);
        atomicAdd(&g_deg[d.z], 1);
        atomicAdd(&g_deg[d.w], 1);
    }
}

// parallel scan, 3 stages
__global__ void scan1_kernel() {          // NBLK_SCAN blocks x 1024
    __shared__ int wsum[32];
    int t = threadIdx.x, lane = t & 31, w = t >> 5;
    int i = blockIdx.x * 1024 + t;
    int v = (i < N_NODES) ? g_deg[i] : 0;
    int x = v;
#pragma unroll
    for (int o = 1; o < 32; o <<= 1) {
        int y = __shfl_up_sync(0xffffffffu, x, o);
        if (lane >= o) x += y;
    }
    if (lane == 31) wsum[w] = x;
    __syncthreads();
    if (w == 0) {
        int sv = wsum[lane];
#pragma unroll
        for (int o = 1; o < 32; o <<= 1) {
            int y = __shfl_up_sync(0xffffffffu, sv, o);
            if (lane >= o) sv += y;
        }
        wsum[lane] = sv;
    }
    __syncthreads();
    int incl = x + (w > 0 ? wsum[w - 1] : 0);
    if (i < N_NODES) g_rowptr[i + 1] = incl;          // block-local inclusive
    if (t == 1023)   g_bsum[blockIdx.x] = incl;       // block total
}

__global__ void scan2_kernel() {          // 1 block, 128 threads
    __shared__ int s[128];
    int t = threadIdx.x;
    int v = (t < NBLK_SCAN) ? g_bsum[t] : 0;
    s[t] = v; __syncthreads();
    for (int o = 1; o < 128; o <<= 1) {
        int y = (t >= o) ? s[t - o] : 0;
        __syncthreads();
        s[t] += y;
        __syncthreads();
    }
    if (t < NBLK_SCAN) g_bsum[t] = s[t] - v;          // exclusive block offset
}

__global__ void scan3_kernel() {
    int i = blockIdx.x * blockDim.x + threadIdx.x;
    if (i < N_NODES) {
        int r = g_rowptr[i + 1] + g_bsum[i >> 10];
        g_rowptr[i + 1] = r;
        g_cursor[i] = r - g_deg[i];
        if (i == 0) g_rowptr[0] = 0;
    }
}

__global__ void fill_kernel(const int* __restrict__ src, const int* __restrict__ dst) {
    int e4 = blockIdx.x * blockDim.x + threadIdx.x;
    if (e4 < N_EDGES / 4) {
        int4 s = __ldg(&reinterpret_cast<const int4*>(src)[e4]);
        int4 d = __ldg(&reinterpret_cast<const int4*>(dst)[e4]);
        g_esrc[atomicAdd(&g_cursor[d.x], 1)] = s.x;
        g_esrc[atomicAdd(&g_cursor[d.y], 1)] = s.y;
        g_esrc[atomicAdd(&g_cursor[d.z], 1)] = s.z;
        g_esrc[atomicAdd(&g_cursor[d.w], 1)] = s.w;
    }
}

// ---------------- tensor-core GEMM: feat = A @ W, fp16 in / fp32 acc ----------------
// BM=128, 256 threads (8 warps), warp tile 32x64 (2x4 warp grid: wr=w&3, wc=w>>2).
// which==0 reads x fp32 directly (converts while staging). sC staged at stride 132,
// fused vectorized epilogue: fp16 feat store + el/er dots with al/ar cached in smem.
#define SMEM_GEMM (69632 + 1024)
__global__ void gemm_mma_kernel(int which, const float* __restrict__ xin,
                                const float* __restrict__ al, const float* __restrict__ ar) {
    extern __shared__ __align__(16) char sbuf[];
    __half* sA  = reinterpret_cast<__half*>(sbuf);            // 128 x 136 halfs (34816 B)
    __half* sB  = reinterpret_cast<__half*>(sbuf + 34816);    // 128 x 136 halfs
    float*  sC  = reinterpret_cast<float*>(sbuf);             // 128 x 132 f32 (aliases sA/sB)
    float*  sal = reinterpret_cast<float*>(sbuf + 69632);     // 128 f32
    float*  sar = sal + 128;

    const __half* Wh = g_Wh[which];

    int t  = threadIdx.x;
    int rb = blockIdx.x * 128;
    int w  = t >> 5;
    int wr = w & 3, wc = w >> 2;

    // stage al/ar (256 threads -> 256 floats)
    if (t < 128) sal[t] = __ldg(&al[t]);
    else         sar[t - 128] = __ldg(&ar[t - 128]);

    // load A tile: 128 rows x 128 halfs (16B chunks), zero-pad OOB rows
    if (which == 0) {
        for (int i = t; i < 2048; i += 256) {
            int r = i >> 4, s = i & 15;
            float4 a = make_float4(0.f, 0.f, 0.f, 0.f), b = a;
            if (rb + r < N_NODES) {
                const float4* xr =
                    reinterpret_cast<const float4*>(xin + (size_t)(rb + r) * 128 + s * 8);
                a = __ldg(xr); b = __ldg(xr + 1);
            }
            __half2 h0 = __float22half2_rn(make_float2(a.x, a.y));
            __half2 h1 = __float22half2_rn(make_float2(a.z, a.w));
            __half2 h2 = __float22half2_rn(make_float2(b.x, b.y));
            __half2 h3 = __float22half2_rn(make_float2(b.z, b.w));
            uint4 u;
            u.x = *reinterpret_cast<unsigned*>(&h0);
            u.y = *reinterpret_cast<unsigned*>(&h1);
            u.z = *reinterpret_cast<unsigned*>(&h2);
            u.w = *reinterpret_cast<unsigned*>(&h3);
            *reinterpret_cast<uint4*>(&sA[r * 136 + s * 8]) = u;
        }
    } else {
        const __half* A = (which == 1) ? g_actA : g_actB;
        for (int i = t; i < 2048; i += 256) {
            int r = i >> 4, s = i & 15;
            uint4 v = make_uint4(0, 0, 0, 0);
            if (rb + r < N_NODES)
                v = *reinterpret_cast<const uint4*>(&A[(size_t)(rb + r) * 128 + s * 8]);
            *reinterpret_cast<uint4*>(&sA[r * 136 + s * 8]) = v;
        }
    }
    // load full W: 128 x 128 halfs
    for (int i = t; i < 2048; i += 256) {
        int r = i >> 4, s = i & 15;
        *reinterpret_cast<uint4*>(&sB[r * 136 + s * 8]) =
            *reinterpret_cast<const uint4*>(&Wh[r * 128 + s * 8]);
    }
    __syncthreads();

    wmma::fragment<wmma::matrix_a, 16, 16, 16, __half, wmma::row_major> af0, af1;
    wmma::fragment<wmma::matrix_b, 16, 16, 16, __half, wmma::row_major> bf;
    wmma::fragment<wmma::accumulator, 16, 16, 16, float> acc[2][4];
#pragma unroll
    for (int r2 = 0; r2 < 2; r2++)
#pragma unroll
        for (int i = 0; i < 4; i++) wmma::fill_fragment(acc[r2][i], 0.f);

#pragma unroll
    for (int k = 0; k < 8; k++) {
        wmma::load_matrix_sync(af0, sA + (wr * 32 +  0) * 136 + k * 16, 136);
        wmma::load_matrix_sync(af1, sA + (wr * 32 + 16) * 136 + k * 16, 136);
#pragma unroll
        for (int i = 0; i < 4; i++) {
            wmma::load_matrix_sync(bf, sB + (k * 16) * 136 + (wc * 64 + i * 16), 136);
            wmma::mma_sync(acc[0][i], af0, bf, acc[0][i]);
            wmma::mma_sync(acc[1][i], af1, bf, acc[1][i]);
        }
    }
    __syncthreads();   // done reading sA/sB; sC aliases them

#pragma unroll
    for (int r2 = 0; r2 < 2; r2++)
#pragma unroll
        for (int i = 0; i < 4; i++)
            wmma::store_matrix_sync(sC + (wr * 32 + r2 * 16) * 132 + (wc * 64 + i * 16),
                                    acc[r2][i], 132, wmma::mem_row_major);
    __syncthreads();

    // fused epilogue: thread t -> rows {t>>2, t>>2+64}, head h=t&3 (32 cols = 4 uint4)
    int h = t & 3;
    float4 al4[8], ar4[8];
#pragma unroll
    for (int c4 = 0; c4 < 8; c4++) {
        al4[c4] = *reinterpret_cast<float4*>(&sal[h * 32 + c4 * 4]);
        ar4[c4] = *reinterpret_cast<float4*>(&sar[h * 32 + c4 * 4]);
    }
#pragma unroll
    for (int half_ = 0; half_ < 2; half_++) {
        int r = (t >> 2) + half_ * 64;
        int row = rb + r;
        if (row < N_NODES) {
            float pl = 0.f, pr = 0.f;
            uint4 packo[4];                      // 32 halfs = 16 unsigned = 4 uint4
            unsigned* pw = reinterpret_cast<unsigned*>(packo);
#pragma unroll
            for (int c4 = 0; c4 < 8; c4++) {
                float4 v = *reinterpret_cast<float4*>(&sC[r * 132 + h * 32 + c4 * 4]);
                pl += v.x * al4[c4].x + v.y * al4[c4].y + v.z * al4[c4].z + v.w * al4[c4].w;
                pr += v.x * ar4[c4].x + v.y * ar4[c4].y + v.z * ar4[c4].z + v.w * ar4[c4].w;
                __half2 h0 = __float22half2_rn(make_float2(v.x, v.y));
                __half2 h1 = __float22half2_rn(make_float2(v.z, v.w));
                pw[c4 * 2 + 0] = *reinterpret_cast<unsigned*>(&h0);
                pw[c4 * 2 + 1] = *reinterpret_cast<unsigned*>(&h1);
            }
            uint4* dstp = reinterpret_cast<uint4*>(g_feat) + (size_t)row * 16 + h * 4;
            dstp[0] = packo[0];
            dstp[1] = packo[1];
            dstp[2] = packo[2];
            dstp[3] = packo[3];
            g_el[row * 4 + h] = pl;
            g_er[row * 4 + h] = pr;
        }
    }
}

// ---------------- aggregation v2: one warp/node, 2 edges per iteration ----------------
// lanes 0-15 process even edge, lanes 16-31 odd edge; each lane owns 8 features.
// out = sum_e exp(e)*feat[src] / sum_e exp(e)  (softmax shift-invariance)
__global__ void aggregate_kernel(int outWhich, int doPool) {
    __shared__ float s_w[8][4][33];
    __shared__ int   s_src[8][32];
    __shared__ float s_pool[8][128];
    __half* outp = (outWhich == 1) ? g_actA : g_actB;
    int node = (blockIdx.x * blockDim.x + threadIdx.x) >> 5;
    int lane = threadIdx.x & 31;
    int w    = threadIdx.x >> 5;
    int sub  = lane & 15, hf = lane >> 4;
    int hh   = sub >> 2;                    // head owning my 8 features

    int s0  = g_rowptr[node];
    int deg = g_rowptr[node + 1] - s0;
    float acc8[8];
#pragma unroll
    for (int i = 0; i < 8; i++) acc8[i] = 0.f;
    float q0 = 0.f, q1 = 0.f, q2 = 0.f, q3 = 0.f;

    if (deg > 0) {
        const float4* el4 = reinterpret_cast<const float4*>(g_el);
        float4 erd = reinterpret_cast<const float4*>(g_er)[node];
        const uint4* feat4 = reinterpret_cast<const uint4*>(g_feat);

        for (int base = 0; base < deg; base += 32) {
            int idx = base + lane;
            int s = 0;
            float w0 = 0.f, w1 = 0.f, w2 = 0.f, w3 = 0.f;
            if (idx < deg) {
                s = __ldg(&g_esrc[s0 + idx]);
                float4 ev = __ldg(&el4[s]);
                w0 = __expf(lrelu(ev.x + erd.x));
                w1 = __expf(lrelu(ev.y + erd.y));
                w2 = __expf(lrelu(ev.z + erd.z));
                w3 = __expf(lrelu(ev.w + erd.w));
                q0 += w0; q1 += w1; q2 += w2; q3 += w3;
            }
            __syncwarp();
            s_src[w][lane] = s;
            s_w[w][0][lane] = w0; s_w[w][1][lane] = w1;
            s_w[w][2][lane] = w2; s_w[w][3][lane] = w3;
            __syncwarp();
            int cnt = min(32, deg - base);
#pragma unroll 4
            for (int j = 0; j < cnt; j += 2) {
                int jj = j + hf;
                int   sj = 0;
                float aa = 0.f;
                if (jj < cnt) {
                    sj = s_src[w][jj];
                    aa = s_w[w][hh][jj];
                }
                uint4 fr = __ldg(&feat4[(size_t)sj * 16 + sub]);
                float2 f0 = __half22float2(*reinterpret_cast<__half2*>(&fr.x));
                float2 f1 = __half22float2(*reinterpret_cast<__half2*>(&fr.y));
                float2 f2 = __half22float2(*reinterpret_cast<__half2*>(&fr.z));
                float2 f3 = __half22float2(*reinterpret_cast<__half2*>(&fr.w));
                acc8[0] += f0.x * aa; acc8[1] += f0.y * aa;
                acc8[2] += f1.x * aa; acc8[3] += f1.y * aa;
                acc8[4] += f2.x * aa; acc8[5] += f2.y * aa;
                acc8[6] += f3.x * aa; acc8[7] += f3.y * aa;
            }
        }
        // combine the two edge-halves
#pragma unroll
        for (int i = 0; i < 8; i++)
            acc8[i] += __shfl_down_sync(0xffffffffu, acc8[i], 16);
        // total weight per head (full-warp sums)
#pragma unroll
        for (int o = 16; o; o >>= 1) {
            q0 += __shfl_xor_sync(0xffffffffu, q0, o);
            q1 += __shfl_xor_sync(0xffffffffu, q1, o);
            q2 += __shfl_xor_sync(0xffffffffu, q2, o);
            q3 += __shfl_xor_sync(0xffffffffu, q3, o);
        }
        float qh = (hh == 0) ? q0 : ((hh == 1) ? q1 : ((hh == 2) ? q2 : q3));
        float inv = 1.f / qh;
#pragma unroll
        for (int i = 0; i < 8; i++) acc8[i] *= inv;
    }
#pragma unroll
    for (int i = 0; i < 8; i++) acc8[i] = fmaxf(acc8[i], 0.f);   // ReLU every layer

    if (!doPool) {
        if (hf == 0) {
            uint4 u;
            unsigned* pw = reinterpret_cast<unsigned*>(&u);
#pragma unroll
            for (int p = 0; p < 4; p++) {
                __half2 hp = __float22half2_rn(make_float2(acc8[p * 2], acc8[p * 2 + 1]));
                pw[p] = *reinterpret_cast<unsigned*>(&hp);
            }
            reinterpret_cast<uint4*>(outp)[(size_t)node * 16 + sub] = u;
        }
    } else {
        // fused graph max-pool: per-warp row -> block max -> 1 atomicMax/col/block
        if (hf == 0) {
#pragma unroll
            for (int i = 0; i < 8; i++) s_pool[w][sub * 8 + i] = acc8[i];
        }
        __syncthreads();
        int t = threadIdx.x;
        if (t < 128) {
            float m = s_pool[0][t];
#pragma unroll
            for (int i = 1; i < 8; i++) m = fmaxf(m, s_pool[i][t]);
            atomicMax(reinterpret_cast<int*>(&g_pooled[t]), __float_as_int(m));
        }
    }
}

// ---------------- FC + softmax head ----------------
__global__ void head_kernel(const float* __restrict__ Wfc, const float* __restrict__ bfc,
                            float* __restrict__ out) {
    __shared__ float lg[8];
    int t = threadIdx.x;
    if (t < 8) {
        float acc = bfc[t];
        for (int k = 0; k < 128; k++) acc += g_pooled[k] * Wfc[k * 8 + t];
        lg[t] = acc;
    }
    __syncthreads();
    if (t == 0) {
        float m = lg[0];
        for (int i = 1; i < 8; i++) m = fmaxf(m, lg[i]);
        float e[8], s = 0.f;
        for (int i = 0; i < 8; i++) { e[i] = expf(lg[i] - m); s += e[i]; }
        for (int i = 0; i < 8; i++) out[i] = e[i] / s;
    }
}

// ---------------- launch ----------------
extern "C" void kernel_launch(void* const* d_in, const int* in_sizes, int n_in,
                              void* d_out, int out_size) {
    (void)in_sizes; (void)n_in; (void)out_size;
    const float* x   = (const float*)d_in[0];
    const int*   src = (const int*)d_in[1];
    const int*   dst = (const int*)d_in[2];
    const float* W1  = (const float*)d_in[3];
    const float* al1 = (const float*)d_in[4];
    const float* ar1 = (const float*)d_in[5];
    const float* W2  = (const float*)d_in[6];
    const float* al2 = (const float*)d_in[7];
    const float* ar2 = (const float*)d_in[8];
    const float* W3  = (const float*)d_in[9];
    const float* al3 = (const float*)d_in[10];
    const float* ar3 = (const float*)d_in[11];
    const float* Wfc = (const float*)d_in[12];
    const float* bfc = (const float*)d_in[13];
    float* out = (float*)d_out;

    cudaFuncSetAttribute(gemm_mma_kernel,
                         cudaFuncAttributeMaxDynamicSharedMemorySize, SMEM_GEMM);

    const int GEMM_BLOCKS = (N_NODES + 127) / 128;   // 782

    // ordered so launch #4 (the ncu-captured slot) is gemm_mma layer 1
    convW_kernel<<<64, 256>>>(W1, W2, W3);
    init_kernel<<<(N_NODES + 255) / 256, 256>>>();
    count_kernel<<<(N_EDGES / 4 + 255) / 256, 256>>>(dst);
    gemm_mma_kernel<<<GEMM_BLOCKS, 256, SMEM_GEMM>>>(0, x, al1, ar1);   // layer 1 (profiled)

    scan1_kernel<<<NBLK_SCAN, 1024>>>();
    scan2_kernel<<<1, 128>>>();
    scan3_kernel<<<(N_NODES + 255) / 256, 256>>>();
    fill_kernel<<<(N_EDGES / 4 + 255) / 256, 256>>>(src, dst);

    aggregate_kernel<<<N_NODES / 8, 256>>>(1, 0);                       // layer 1 -> actA
    gemm_mma_kernel<<<GEMM_BLOCKS, 256, SMEM_GEMM>>>(1, nullptr, al2, ar2);
    aggregate_kernel<<<N_NODES / 8, 256>>>(2, 0);                       // layer 2 -> actB
    gemm_mma_kernel<<<GEMM_BLOCKS, 256, SMEM_GEMM>>>(2, nullptr, al3, ar3);
    aggregate_kernel<<<N_NODES / 8, 256>>>(1, 1);                       // layer 3 + pool

    head_kernel<<<1, 32>>>(Wfc, bfc, out);
}

// round 13
// speedup vs baseline: 2.5736x; 1.0264x over previous
#include <cuda_runtime.h>
#include <cuda_fp16.h>
#include <mma.h>
using namespace nvcuda;

#define N_NODES 100000
#define N_EDGES 1600000
#define NBLK_SCAN 98   // ceil(100000/1024)

// ---------------- scratch (allocation-free: __device__ globals) ----------------
__device__ __align__(16) __half g_feat[N_NODES * 128];   // fp16 transformed features
__device__ __align__(16) __half g_actA[N_NODES * 128];   // fp16 activations
__device__ __align__(16) __half g_actB[N_NODES * 128];
__device__ __align__(16) __half g_Wh[3][128 * 128];      // fp16 weights
__device__ __align__(16) float g_el[N_NODES * 4];
__device__ __align__(16) float g_er[N_NODES * 4];
__device__ int   g_rowptr[N_NODES + 1];
__device__ int   g_cursor[N_NODES];
__device__ int   g_deg[N_NODES];
__device__ int   g_esrc[N_EDGES];
__device__ int   g_bsum[128];
__device__ float g_pooled[128];

__device__ __forceinline__ float lrelu(float x) { return x > 0.f ? x : 0.2f * x; }

// ---------------- converts ----------------
__global__ void convW_kernel(const float* __restrict__ W1, const float* __restrict__ W2,
                             const float* __restrict__ W3) {
    int i = blockIdx.x * blockDim.x + threadIdx.x;
    if (i < 128 * 128) {
        g_Wh[0][i] = __float2half_rn(W1[i]);
        g_Wh[1][i] = __float2half_rn(W2[i]);
        g_Wh[2][i] = __float2half_rn(W3[i]);
    }
}

// ---------------- init: zero degree counts + pooled ----------------
__global__ void init_kernel() {
    int i = blockIdx.x * blockDim.x + threadIdx.x;
    if (i < N_NODES) g_deg[i] = 0;
    if (i < 128)     g_pooled[i] = 0.f;
}

// ---------------- CSR build (int4-vectorized edge reads) ----------------
__global__ void count_kernel(const int* __restrict__ dst) {
    int e4 = blockIdx.x * blockDim.x + threadIdx.x;
    if (e4 < N_EDGES / 4) {
        int4 d = __ldg(&reinterpret_cast<const int4*>(dst)[e4]);
        atomicAdd(&g_deg[d.x], 1);
        atomicAdd(&g_deg[d.y], 1);
        atomicAdd(&g_deg[d.z], 1);
        atomicAdd(&g_deg[d.w], 1);
    }
}

// parallel scan, 3 stages
__global__ void scan1_kernel() {          // NBLK_SCAN blocks x 1024
    __shared__ int wsum[32];
    int t = threadIdx.x, lane = t & 31, w = t >> 5;
    int i = blockIdx.x * 1024 + t;
    int v = (i < N_NODES) ? g_deg[i] : 0;
    int x = v;
#pragma unroll
    for (int o = 1; o < 32; o <<= 1) {
        int y = __shfl_up_sync(0xffffffffu, x, o);
        if (lane >= o) x += y;
    }
    if (lane == 31) wsum[w] = x;
    __syncthreads();
    if (w == 0) {
        int sv = wsum[lane];
#pragma unroll
        for (int o = 1; o < 32; o <<= 1) {
            int y = __shfl_up_sync(0xffffffffu, sv, o);
            if (lane >= o) sv += y;
        }
        wsum[lane] = sv;
    }
    __syncthreads();
    int incl = x + (w > 0 ? wsum[w - 1] : 0);
    if (i < N_NODES) g_rowptr[i + 1] = incl;          // block-local inclusive
    if (t == 1023)   g_bsum[blockIdx.x] = incl;       // block total
}

__global__ void scan2_kernel() {          // 1 block, 128 threads
    __shared__ int s[128];
    int t = threadIdx.x;
    int v = (t < NBLK_SCAN) ? g_bsum[t] : 0;
    s[t] = v; __syncthreads();
    for (int o = 1; o < 128; o <<= 1) {
        int y = (t >= o) ? s[t - o] : 0;
        __syncthreads();
        s[t] += y;
        __syncthreads();
    }
    if (t < NBLK_SCAN) g_bsum[t] = s[t] - v;          // exclusive block offset
}

__global__ void scan3_kernel() {
    int i = blockIdx.x * blockDim.x + threadIdx.x;
    if (i < N_NODES) {
        int r = g_rowptr[i + 1] + g_bsum[i >> 10];
        g_rowptr[i + 1] = r;
        g_cursor[i] = r - g_deg[i];
        if (i == 0) g_rowptr[0] = 0;
    }
}

__global__ void fill_kernel(const int* __restrict__ src, const int* __restrict__ dst) {
    int e4 = blockIdx.x * blockDim.x + threadIdx.x;
    if (e4 < N_EDGES / 4) {
        int4 s = __ldg(&reinterpret_cast<const int4*>(src)[e4]);
        int4 d = __ldg(&reinterpret_cast<const int4*>(dst)[e4]);
        g_esrc[atomicAdd(&g_cursor[d.x], 1)] = s.x;
        g_esrc[atomicAdd(&g_cursor[d.y], 1)] = s.y;
        g_esrc[atomicAdd(&g_cursor[d.z], 1)] = s.z;
        g_esrc[atomicAdd(&g_cursor[d.w], 1)] = s.w;
    }
}

// ---------------- tensor-core GEMM: feat = A @ W, fp16 in / fp32 acc ----------------
// BM=128, 256 threads (8 warps), warp tile 32x64 (wr=w&3, wc=w>>2).
// Warp (wr,wc) owns rows wr*32..+31, cols wc*64..+63 = heads 2wc,2wc+1 ->
// fully warp-local epilogue (per-warp sC scratch 32x68 f32, lane = row).
#define SMEM_GEMM (69632 + 1024)
__global__ void __launch_bounds__(256, 3)
gemm_mma_kernel(int which, const float* __restrict__ xin,
                const float* __restrict__ al, const float* __restrict__ ar) {
    extern __shared__ __align__(16) char sbuf[];
    __half* sA  = reinterpret_cast<__half*>(sbuf);            // 128 x 136 halfs (34816 B)
    __half* sB  = reinterpret_cast<__half*>(sbuf + 34816);    // 128 x 136 halfs
    float*  sC  = reinterpret_cast<float*>(sbuf);             // 8 x (32 x 68) f32, aliases
    float*  sal = reinterpret_cast<float*>(sbuf + 69632);     // 128 f32
    float*  sar = sal + 128;

    const __half* Wh = g_Wh[which];

    int t  = threadIdx.x;
    int rb = blockIdx.x * 128;
    int w  = t >> 5;
    int lane = t & 31;
    int wr = w & 3, wc = w >> 2;

    // stage al/ar (256 threads -> 256 floats)
    if (t < 128) sal[t] = __ldg(&al[t]);
    else         sar[t - 128] = __ldg(&ar[t - 128]);

    // load A tile: 128 rows x 128 halfs (16B chunks), zero-pad OOB rows
    if (which == 0) {
        for (int i = t; i < 2048; i += 256) {
            int r = i >> 4, s = i & 15;
            float4 a = make_float4(0.f, 0.f, 0.f, 0.f), b = a;
            if (rb + r < N_NODES) {
                const float4* xr =
                    reinterpret_cast<const float4*>(xin + (size_t)(rb + r) * 128 + s * 8);
                a = __ldg(xr); b = __ldg(xr + 1);
            }
            __half2 h0 = __float22half2_rn(make_float2(a.x, a.y));
            __half2 h1 = __float22half2_rn(make_float2(a.z, a.w));
            __half2 h2 = __float22half2_rn(make_float2(b.x, b.y));
            __half2 h3 = __float22half2_rn(make_float2(b.z, b.w));
            uint4 u;
            u.x = *reinterpret_cast<unsigned*>(&h0);
            u.y = *reinterpret_cast<unsigned*>(&h1);
            u.z = *reinterpret_cast<unsigned*>(&h2);
            u.w = *reinterpret_cast<unsigned*>(&h3);
            *reinterpret_cast<uint4*>(&sA[r * 136 + s * 8]) = u;
        }
    } else {
        const __half* A = (which == 1) ? g_actA : g_actB;
        for (int i = t; i < 2048; i += 256) {
            int r = i >> 4, s = i & 15;
            uint4 v = make_uint4(0, 0, 0, 0);
            if (rb + r < N_NODES)
                v = *reinterpret_cast<const uint4*>(&A[(size_t)(rb + r) * 128 + s * 8]);
            *reinterpret_cast<uint4*>(&sA[r * 136 + s * 8]) = v;
        }
    }
    // load full W: 128 x 128 halfs
    for (int i = t; i < 2048; i += 256) {
        int r = i >> 4, s = i & 15;
        *reinterpret_cast<uint4*>(&sB[r * 136 + s * 8]) =
            *reinterpret_cast<const uint4*>(&Wh[r * 128 + s * 8]);
    }
    __syncthreads();

    wmma::fragment<wmma::matrix_a, 16, 16, 16, __half, wmma::row_major> af0, af1;
    wmma::fragment<wmma::matrix_b, 16, 16, 16, __half, wmma::row_major> bf;
    wmma::fragment<wmma::accumulator, 16, 16, 16, float> acc[2][4];
#pragma unroll
    for (int r2 = 0; r2 < 2; r2++)
#pragma unroll
        for (int i = 0; i < 4; i++) wmma::fill_fragment(acc[r2][i], 0.f);

#pragma unroll
    for (int k = 0; k < 8; k++) {
        wmma::load_matrix_sync(af0, sA + (wr * 32 +  0) * 136 + k * 16, 136);
        wmma::load_matrix_sync(af1, sA + (wr * 32 + 16) * 136 + k * 16, 136);
#pragma unroll
        for (int i = 0; i < 4; i++) {
            wmma::load_matrix_sync(bf, sB + (k * 16) * 136 + (wc * 64 + i * 16), 136);
            wmma::mma_sync(acc[0][i], af0, bf, acc[0][i]);
            wmma::mma_sync(acc[1][i], af1, bf, acc[1][i]);
        }
    }
    __syncthreads();   // all warps done reading sA/sB; sC aliases them

    // per-warp scratch: 32 rows x 68 floats (8704 B)
    float* myC = sC + w * (32 * 68);
#pragma unroll
    for (int r2 = 0; r2 < 2; r2++)
#pragma unroll
        for (int i = 0; i < 4; i++)
            wmma::store_matrix_sync(myC + (r2 * 16) * 68 + i * 16, acc[r2][i],
                                    68, wmma::mem_row_major);
    __syncwarp();

    // warp-local epilogue: lane = row wr*32+lane, cols wc*64..+63 (heads 2wc, 2wc+1)
    {
        int row = rb + wr * 32 + lane;
        const float* rowC = myC + lane * 68;
        if (row < N_NODES) {
            uint4 packo[8];                  // 64 halfs = 32 unsigned
            unsigned* pw = reinterpret_cast<unsigned*>(packo);
#pragma unroll
            for (int hi = 0; hi < 2; hi++) {
                int h = 2 * wc + hi;
                float pl = 0.f, pr = 0.f;
#pragma unroll
                for (int c4 = 0; c4 < 8; c4++) {
                    float4 v = *reinterpret_cast<const float4*>(&rowC[hi * 32 + c4 * 4]);
                    float4 a = *reinterpret_cast<float4*>(&sal[h * 32 + c4 * 4]);
                    float4 b = *reinterpret_cast<float4*>(&sar[h * 32 + c4 * 4]);
                    pl += v.x * a.x + v.y * a.y + v.z * a.z + v.w * a.w;
                    pr += v.x * b.x + v.y * b.y + v.z * b.z + v.w * b.w;
                    __half2 p0 = __float22half2_rn(make_float2(v.x, v.y));
                    __half2 p1 = __float22half2_rn(make_float2(v.z, v.w));
                    pw[hi * 16 + c4 * 2 + 0] = *reinterpret_cast<unsigned*>(&p0);
                    pw[hi * 16 + c4 * 2 + 1] = *reinterpret_cast<unsigned*>(&p1);
                }
                g_el[row * 4 + h] = pl;
                g_er[row * 4 + h] = pr;
            }
            uint4* dstp = reinterpret_cast<uint4*>(g_feat) + (size_t)row * 16 + wc * 8;
#pragma unroll
            for (int i = 0; i < 8; i++) dstp[i] = packo[i];
        }
    }
}

// ---------------- aggregation v2: one warp/node, 2 edges per iteration ----------------
// lanes 0-15 process even edge, lanes 16-31 odd edge; each lane owns 8 features.
// out = sum_e exp(e)*feat[src] / sum_e exp(e)  (softmax shift-invariance)
__global__ void aggregate_kernel(int outWhich, int doPool) {
    __shared__ float s_w[8][4][33];
    __shared__ int   s_src[8][32];
    __shared__ float s_pool[8][128];
    __half* outp = (outWhich == 1) ? g_actA : g_actB;
    int node = (blockIdx.x * blockDim.x + threadIdx.x) >> 5;
    int lane = threadIdx.x & 31;
    int w    = threadIdx.x >> 5;
    int sub  = lane & 15, hf = lane >> 4;
    int hh   = sub >> 2;                    // head owning my 8 features

    int s0  = g_rowptr[node];
    int deg = g_rowptr[node + 1] - s0;
    float acc8[8];
#pragma unroll
    for (int i = 0; i < 8; i++) acc8[i] = 0.f;
    float q0 = 0.f, q1 = 0.f, q2 = 0.f, q3 = 0.f;

    if (deg > 0) {
        const float4* el4 = reinterpret_cast<const float4*>(g_el);
        float4 erd = reinterpret_cast<const float4*>(g_er)[node];
        const uint4* feat4 = reinterpret_cast<const uint4*>(g_feat);

        for (int base = 0; base < deg; base += 32) {
            int idx = base + lane;
            int s = 0;
            float w0 = 0.f, w1 = 0.f, w2 = 0.f, w3 = 0.f;
            if (idx < deg) {
                s = __ldg(&g_esrc[s0 + idx]);
                float4 ev = __ldg(&el4[s]);
                w0 = __expf(lrelu(ev.x + erd.x));
                w1 = __expf(lrelu(ev.y + erd.y));
                w2 = __expf(lrelu(ev.z + erd.z));
                w3 = __expf(lrelu(ev.w + erd.w));
                q0 += w0; q1 += w1; q2 += w2; q3 += w3;
            }
            __syncwarp();
            s_src[w][lane] = s;
            s_w[w][0][lane] = w0; s_w[w][1][lane] = w1;
            s_w[w][2][lane] = w2; s_w[w][3][lane] = w3;
            __syncwarp();
            int cnt = min(32, deg - base);
#pragma unroll 4
            for (int j = 0; j < cnt; j += 2) {
                int jj = j + hf;
                int   sj = 0;
                float aa = 0.f;
                if (jj < cnt) {
                    sj = s_src[w][jj];
                    aa = s_w[w][hh][jj];
                }
                uint4 fr = __ldg(&feat4[(size_t)sj * 16 + sub]);
                float2 f0 = __half22float2(*reinterpret_cast<__half2*>(&fr.x));
                float2 f1 = __half22float2(*reinterpret_cast<__half2*>(&fr.y));
                float2 f2 = __half22float2(*reinterpret_cast<__half2*>(&fr.z));
                float2 f3 = __half22float2(*reinterpret_cast<__half2*>(&fr.w));
                acc8[0] += f0.x * aa; acc8[1] += f0.y * aa;
                acc8[2] += f1.x * aa; acc8[3] += f1.y * aa;
                acc8[4] += f2.x * aa; acc8[5] += f2.y * aa;
                acc8[6] += f3.x * aa; acc8[7] += f3.y * aa;
            }
        }
        // combine the two edge-halves
#pragma unroll
        for (int i = 0; i < 8; i++)
            acc8[i] += __shfl_down_sync(0xffffffffu, acc8[i], 16);
        // total weight per head (full-warp sums)
#pragma unroll
        for (int o = 16; o; o >>= 1) {
            q0 += __shfl_xor_sync(0xffffffffu, q0, o);
            q1 += __shfl_xor_sync(0xffffffffu, q1, o);
            q2 += __shfl_xor_sync(0xffffffffu, q2, o);
            q3 += __shfl_xor_sync(0xffffffffu, q3, o);
        }
        float qh = (hh == 0) ? q0 : ((hh == 1) ? q1 : ((hh == 2) ? q2 : q3));
        float inv = 1.f / qh;
#pragma unroll
        for (int i = 0; i < 8; i++) acc8[i] *= inv;
    }
#pragma unroll
    for (int i = 0; i < 8; i++) acc8[i] = fmaxf(acc8[i], 0.f);   // ReLU every layer

    if (!doPool) {
        if (hf == 0) {
            uint4 u;
            unsigned* pw = reinterpret_cast<unsigned*>(&u);
#pragma unroll
            for (int p = 0; p < 4; p++) {
                __half2 hp = __float22half2_rn(make_float2(acc8[p * 2], acc8[p * 2 + 1]));
                pw[p] = *reinterpret_cast<unsigned*>(&hp);
            }
            reinterpret_cast<uint4*>(outp)[(size_t)node * 16 + sub] = u;
        }
    } else {
        // fused graph max-pool: per-warp row -> block max -> 1 atomicMax/col/block
        if (hf == 0) {
#pragma unroll
            for (int i = 0; i < 8; i++) s_pool[w][sub * 8 + i] = acc8[i];
        }
        __syncthreads();
        int t = threadIdx.x;
        if (t < 128) {
            float m = s_pool[0][t];
#pragma unroll
            for (int i = 1; i < 8; i++) m = fmaxf(m, s_pool[i][t]);
            atomicMax(reinterpret_cast<int*>(&g_pooled[t]), __float_as_int(m));
        }
    }
}

// ---------------- FC + softmax head ----------------
__global__ void head_kernel(const float* __restrict__ Wfc, const float* __restrict__ bfc,
                            float* __restrict__ out) {
    __shared__ float lg[8];
    int t = threadIdx.x;
    if (t < 8) {
        float acc = bfc[t];
        for (int k = 0; k < 128; k++) acc += g_pooled[k] * Wfc[k * 8 + t];
        lg[t] = acc;
    }
    __syncthreads();
    if (t == 0) {
        float m = lg[0];
        for (int i = 1; i < 8; i++) m = fmaxf(m, lg[i]);
        float e[8], s = 0.f;
        for (int i = 0; i < 8; i++) { e[i] = expf(lg[i] - m); s += e[i]; }
        for (int i = 0; i < 8; i++) out[i] = e[i] / s;
    }
}

// ---------------- launch ----------------
extern "C" void kernel_launch(void* const* d_in, const int* in_sizes, int n_in,
                              void* d_out, int out_size) {
    (void)in_sizes; (void)n_in; (void)out_size;
    const float* x   = (const float*)d_in[0];
    const int*   src = (const int*)d_in[1];
    const int*   dst = (const int*)d_in[2];
    const float* W1  = (const float*)d_in[3];
    const float* al1 = (const float*)d_in[4];
    const float* ar1 = (const float*)d_in[5];
    const float* W2  = (const float*)d_in[6];
    const float* al2 = (const float*)d_in[7];
    const float* ar2 = (const float*)d_in[8];
    const float* W3  = (const float*)d_in[9];
    const float* al3 = (const float*)d_in[10];
    const float* ar3 = (const float*)d_in[11];
    const float* Wfc = (const float*)d_in[12];
    const float* bfc = (const float*)d_in[13];
    float* out = (float*)d_out;

    cudaFuncSetAttribute(gemm_mma_kernel,
                         cudaFuncAttributeMaxDynamicSharedMemorySize, SMEM_GEMM);

    const int GEMM_BLOCKS = (N_NODES + 127) / 128;   // 782

    // ordered so launch #4 (the ncu-captured slot) is gemm_mma layer 1
    convW_kernel<<<64, 256>>>(W1, W2, W3);
    init_kernel<<<(N_NODES + 255) / 256, 256>>>();
    count_kernel<<<(N_EDGES / 4 + 255) / 256, 256>>>(dst);
    gemm_mma_kernel<<<GEMM_BLOCKS, 256, SMEM_GEMM>>>(0, x, al1, ar1);   // layer 1 (profiled)

    scan1_kernel<<<NBLK_SCAN, 1024>>>();
    scan2_kernel<<<1, 128>>>();
    scan3_kernel<<<(N_NODES + 255) / 256, 256>>>();
    fill_kernel<<<(N_EDGES / 4 + 255) / 256, 256>>>(src, dst);

    aggregate_kernel<<<N_NODES / 8, 256>>>(1, 0);                       // layer 1 -> actA
    gemm_mma_kernel<<<GEMM_BLOCKS, 256, SMEM_GEMM>>>(1, nullptr, al2, ar2);
    aggregate_kernel<<<N_NODES / 8, 256>>>(2, 0);                       // layer 2 -> actB
    gemm_mma_kernel<<<GEMM_BLOCKS, 256, SMEM_GEMM>>>(2, nullptr, al3, ar3);
    aggregate_kernel<<<N_NODES / 8, 256>>>(1, 1);                       // layer 3 + pool

    head_kernel<<<1, 32>>>(Wfc, bfc, out);
}

// round 14
// speedup vs baseline: 2.6904x; 1.0454x over previous
#include <cuda_runtime.h>
#include <cuda_fp16.h>
#include <mma.h>
using namespace nvcuda;

#define N_NODES 100000
#define N_EDGES 1600000
#define NBLK_SCAN 98   // ceil(100000/1024)

// ---------------- scratch (allocation-free: __device__ globals) ----------------
__device__ __align__(16) __half g_featA[100096 * 128];   // double-buffered fp16 features
__device__ __align__(16) __half g_featB[100096 * 128];
__device__ __align__(16) __half g_Wh[3][128 * 128];      // fp16 weights
__device__ __align__(16) float g_elA[N_NODES * 4];
__device__ __align__(16) float g_erA[N_NODES * 4];
__device__ __align__(16) float g_elB[N_NODES * 4];
__device__ __align__(16) float g_erB[N_NODES * 4];
__device__ int   g_rowptr[N_NODES + 1];
__device__ int   g_cursor[N_NODES];
__device__ int   g_deg[N_NODES];
__device__ int   g_esrc[N_EDGES];
__device__ int   g_bsum[128];
__device__ float g_pooled[128];

__device__ __forceinline__ float lrelu(float x) { return x > 0.f ? x : 0.2f * x; }

// ---------------- converts ----------------
__global__ void convW_kernel(const float* __restrict__ W1, const float* __restrict__ W2,
                             const float* __restrict__ W3) {
    int i = blockIdx.x * blockDim.x + threadIdx.x;
    if (i < 128 * 128) {
        g_Wh[0][i] = __float2half_rn(W1[i]);
        g_Wh[1][i] = __float2half_rn(W2[i]);
        g_Wh[2][i] = __float2half_rn(W3[i]);
    }
}

// ---------------- init: zero degree counts + pooled ----------------
__global__ void init_kernel() {
    int i = blockIdx.x * blockDim.x + threadIdx.x;
    if (i < N_NODES) g_deg[i] = 0;
    if (i < 128)     g_pooled[i] = 0.f;
}

// ---------------- CSR build (int4-vectorized edge reads) ----------------
__global__ void count_kernel(const int* __restrict__ dst) {
    int e4 = blockIdx.x * blockDim.x + threadIdx.x;
    if (e4 < N_EDGES / 4) {
        int4 d = __ldg(&reinterpret_cast<const int4*>(dst)[e4]);
        atomicAdd(&g_deg[d.x], 1);
        atomicAdd(&g_deg[d.y], 1);
        atomicAdd(&g_deg[d.z], 1);
        atomicAdd(&g_deg[d.w], 1);
    }
}

__global__ void scan1_kernel() {          // NBLK_SCAN blocks x 1024
    __shared__ int wsum[32];
    int t = threadIdx.x, lane = t & 31, w = t >> 5;
    int i = blockIdx.x * 1024 + t;
    int v = (i < N_NODES) ? g_deg[i] : 0;
    int x = v;
#pragma unroll
    for (int o = 1; o < 32; o <<= 1) {
        int y = __shfl_up_sync(0xffffffffu, x, o);
        if (lane >= o) x += y;
    }
    if (lane == 31) wsum[w] = x;
    __syncthreads();
    if (w == 0) {
        int sv = wsum[lane];
#pragma unroll
        for (int o = 1; o < 32; o <<= 1) {
            int y = __shfl_up_sync(0xffffffffu, sv, o);
            if (lane >= o) sv += y;
        }
        wsum[lane] = sv;
    }
    __syncthreads();
    int incl = x + (w > 0 ? wsum[w - 1] : 0);
    if (i < N_NODES) g_rowptr[i + 1] = incl;
    if (t == 1023)   g_bsum[blockIdx.x] = incl;
}

__global__ void scan2_kernel() {          // 1 block, 128 threads
    __shared__ int s[128];
    int t = threadIdx.x;
    int v = (t < NBLK_SCAN) ? g_bsum[t] : 0;
    s[t] = v; __syncthreads();
    for (int o = 1; o < 128; o <<= 1) {
        int y = (t >= o) ? s[t - o] : 0;
        __syncthreads();
        s[t] += y;
        __syncthreads();
    }
    if (t < NBLK_SCAN) g_bsum[t] = s[t] - v;
}

__global__ void scan3_kernel() {
    int i = blockIdx.x * blockDim.x + threadIdx.x;
    if (i < N_NODES) {
        int r = g_rowptr[i + 1] + g_bsum[i >> 10];
        g_rowptr[i + 1] = r;
        g_cursor[i] = r - g_deg[i];
        if (i == 0) g_rowptr[0] = 0;
    }
}

__global__ void fill_kernel(const int* __restrict__ src, const int* __restrict__ dst) {
    int e4 = blockIdx.x * blockDim.x + threadIdx.x;
    if (e4 < N_EDGES / 4) {
        int4 s = __ldg(&reinterpret_cast<const int4*>(src)[e4]);
        int4 d = __ldg(&reinterpret_cast<const int4*>(dst)[e4]);
        g_esrc[atomicAdd(&g_cursor[d.x], 1)] = s.x;
        g_esrc[atomicAdd(&g_cursor[d.y], 1)] = s.y;
        g_esrc[atomicAdd(&g_cursor[d.z], 1)] = s.z;
        g_esrc[atomicAdd(&g_cursor[d.w], 1)] = s.w;
    }
}

// ---------------- shared GEMM core (mainloop + epilogue), called with sA filled ----
#define SMEM_GEMM (69632 + 1024)

__device__ __forceinline__ void gemm_core(char* sbuf, int which, int rb,
                                          __half* featOut, float* elOut, float* erOut) {
    __half* sA  = reinterpret_cast<__half*>(sbuf);
    __half* sB  = reinterpret_cast<__half*>(sbuf + 34816);
    float*  sC  = reinterpret_cast<float*>(sbuf);
    float*  sal = reinterpret_cast<float*>(sbuf + 69632);
    float*  sar = sal + 128;
    int t = threadIdx.x, w = t >> 5, lane = t & 31;
    int wr = w & 3, wc = w >> 2;

    // load full W: 128 x 128 halfs (sA already holds the act tile)
    const __half* Wh = g_Wh[which];
    for (int i = t; i < 2048; i += 256) {
        int r = i >> 4, s = i & 15;
        *reinterpret_cast<uint4*>(&sB[r * 136 + s * 8]) =
            *reinterpret_cast<const uint4*>(&Wh[r * 128 + s * 8]);
    }
    __syncthreads();

    wmma::fragment<wmma::matrix_a, 16, 16, 16, __half, wmma::row_major> af0, af1;
    wmma::fragment<wmma::matrix_b, 16, 16, 16, __half, wmma::row_major> bf;
    wmma::fragment<wmma::accumulator, 16, 16, 16, float> acc[2][4];
#pragma unroll
    for (int r2 = 0; r2 < 2; r2++)
#pragma unroll
        for (int i = 0; i < 4; i++) wmma::fill_fragment(acc[r2][i], 0.f);

#pragma unroll
    for (int k = 0; k < 8; k++) {
        wmma::load_matrix_sync(af0, sA + (wr * 32 +  0) * 136 + k * 16, 136);
        wmma::load_matrix_sync(af1, sA + (wr * 32 + 16) * 136 + k * 16, 136);
#pragma unroll
        for (int i = 0; i < 4; i++) {
            wmma::load_matrix_sync(bf, sB + (k * 16) * 136 + (wc * 64 + i * 16), 136);
            wmma::mma_sync(acc[0][i], af0, bf, acc[0][i]);
            wmma::mma_sync(acc[1][i], af1, bf, acc[1][i]);
        }
    }
    __syncthreads();   // all warps done reading sA/sB; sC aliases them

    float* myC = sC + w * (32 * 68);
#pragma unroll
    for (int r2 = 0; r2 < 2; r2++)
#pragma unroll
        for (int i = 0; i < 4; i++)
            wmma::store_matrix_sync(myC + (r2 * 16) * 68 + i * 16, acc[r2][i],
                                    68, wmma::mem_row_major);
    __syncwarp();

    // warp-local epilogue: lane = row wr*32+lane, cols wc*64..+63 (heads 2wc, 2wc+1)
    int row = rb + wr * 32 + lane;
    const float* rowC = myC + lane * 68;
    if (row < N_NODES) {
        uint4 packo[8];                      // 64 halfs = 32 unsigned
        unsigned* pw = reinterpret_cast<unsigned*>(packo);
#pragma unroll
        for (int hi = 0; hi < 2; hi++) {
            int h = 2 * wc + hi;
            float pl = 0.f, pr = 0.f;
#pragma unroll
            for (int c4 = 0; c4 < 8; c4++) {
                float4 v = *reinterpret_cast<const float4*>(&rowC[hi * 32 + c4 * 4]);
                float4 a = *reinterpret_cast<float4*>(&sal[h * 32 + c4 * 4]);
                float4 b = *reinterpret_cast<float4*>(&sar[h * 32 + c4 * 4]);
                pl += v.x * a.x + v.y * a.y + v.z * a.z + v.w * a.w;
                pr += v.x * b.x + v.y * b.y + v.z * b.z + v.w * b.w;
                __half2 p0 = __float22half2_rn(make_float2(v.x, v.y));
                __half2 p1 = __float22half2_rn(make_float2(v.z, v.w));
                pw[hi * 16 + c4 * 2 + 0] = *reinterpret_cast<unsigned*>(&p0);
                pw[hi * 16 + c4 * 2 + 1] = *reinterpret_cast<unsigned*>(&p1);
            }
            elOut[row * 4 + h] = pl;
            erOut[row * 4 + h] = pr;
        }
        uint4* dstp = reinterpret_cast<uint4*>(featOut) + (size_t)row * 16 + wc * 8;
#pragma unroll
        for (int i = 0; i < 8; i++) dstp[i] = packo[i];
    }
}

// ---------------- layer-1 GEMM: feat = x @ W1 (fp32 x converted in-flight) ----------
__global__ void __launch_bounds__(256, 3)
gemm1_kernel(const float* __restrict__ xin,
             const float* __restrict__ al, const float* __restrict__ ar) {
    extern __shared__ __align__(16) char sbuf[];
    __half* sA  = reinterpret_cast<__half*>(sbuf);
    float*  sal = reinterpret_cast<float*>(sbuf + 69632);
    float*  sar = sal + 128;
    int t = threadIdx.x;
    int rb = blockIdx.x * 128;

    if (t < 128) sal[t] = __ldg(&al[t]);
    else         sar[t - 128] = __ldg(&ar[t - 128]);

    for (int i = t; i < 2048; i += 256) {
        int r = i >> 4, s = i & 15;
        float4 a = make_float4(0.f, 0.f, 0.f, 0.f), b = a;
        if (rb + r < N_NODES) {
            const float4* xr =
                reinterpret_cast<const float4*>(xin + (size_t)(rb + r) * 128 + s * 8);
            a = __ldg(xr); b = __ldg(xr + 1);
        }
        __half2 h0 = __float22half2_rn(make_float2(a.x, a.y));
        __half2 h1 = __float22half2_rn(make_float2(a.z, a.w));
        __half2 h2 = __float22half2_rn(make_float2(b.x, b.y));
        __half2 h3 = __float22half2_rn(make_float2(b.z, b.w));
        uint4 u;
        u.x = *reinterpret_cast<unsigned*>(&h0);
        u.y = *reinterpret_cast<unsigned*>(&h1);
        u.z = *reinterpret_cast<unsigned*>(&h2);
        u.w = *reinterpret_cast<unsigned*>(&h3);
        *reinterpret_cast<uint4*>(&sA[r * 136 + s * 8]) = u;
    }
    __syncthreads();
    gemm_core(sbuf, 0, rb, g_featA, g_elA, g_erA);
}

// ---------------- fused: aggregate(prev layer) into smem act -> GEMM next layer ----
// dir=0: read featA/elA/erA, write featB/elB/erB (whichW=1)
// dir=1: read featB/elB/erB, write featA/elA/erA (whichW=2)
__global__ void __launch_bounds__(256, 3)
fused_agg_gemm_kernel(int dir, int whichW,
                      const float* __restrict__ al, const float* __restrict__ ar) {
    extern __shared__ __align__(16) char sbuf[];
    __half* sA   = reinterpret_cast<__half*>(sbuf);
    float*  s_w  = reinterpret_cast<float*>(sbuf + 34816);        // [8][4][33] (4224 B)
    int*    s_src= reinterpret_cast<int*>(sbuf + 34816 + 4224);   // [8][32]
    float*  sal  = reinterpret_cast<float*>(sbuf + 69632);
    float*  sar  = sal + 128;

    const uint4*  featIn = reinterpret_cast<const uint4*>(dir ? g_featB : g_featA);
    const float4* elIn   = reinterpret_cast<const float4*>(dir ? g_elB : g_elA);
    const float4* erIn   = reinterpret_cast<const float4*>(dir ? g_erB : g_erA);
    __half* featOut = dir ? g_featA : g_featB;
    float*  elOut   = dir ? g_elA : g_elB;
    float*  erOut   = dir ? g_erA : g_erB;

    int t = threadIdx.x, w = t >> 5, lane = t & 31;
    int rb = blockIdx.x * 128;
    int sub = lane & 15, hf = lane >> 4;
    int hh  = sub >> 2;

    if (t < 128) sal[t] = __ldg(&al[t]);
    else         sar[t - 128] = __ldg(&ar[t - 128]);

    // ---- aggregate phase: each warp produces 16 act rows into sA ----
    for (int it = 0; it < 16; it++) {
        int node = rb + it * 8 + w;
        float acc8[8];
#pragma unroll
        for (int i = 0; i < 8; i++) acc8[i] = 0.f;
        float q0 = 0.f, q1 = 0.f, q2 = 0.f, q3 = 0.f;
        int s0 = 0, deg = 0;
        if (node < N_NODES) {
            s0 = g_rowptr[node];
            deg = g_rowptr[node + 1] - s0;
        }
        if (deg > 0) {
            float4 erd = erIn[node];
            for (int base = 0; base < deg; base += 32) {
                int idx = base + lane;
                int s = 0;
                float w0 = 0.f, w1 = 0.f, w2 = 0.f, w3 = 0.f;
                if (idx < deg) {
                    s = __ldg(&g_esrc[s0 + idx]);
                    float4 ev = __ldg(&elIn[s]);
                    w0 = __expf(lrelu(ev.x + erd.x));
                    w1 = __expf(lrelu(ev.y + erd.y));
                    w2 = __expf(lrelu(ev.z + erd.z));
                    w3 = __expf(lrelu(ev.w + erd.w));
                    q0 += w0; q1 += w1; q2 += w2; q3 += w3;
                }
                __syncwarp();
                s_src[w * 32 + lane] = s;
                s_w[(w * 4 + 0) * 33 + lane] = w0;
                s_w[(w * 4 + 1) * 33 + lane] = w1;
                s_w[(w * 4 + 2) * 33 + lane] = w2;
                s_w[(w * 4 + 3) * 33 + lane] = w3;
                __syncwarp();
                int cnt = min(32, deg - base);
#pragma unroll 4
                for (int j = 0; j < cnt; j += 2) {
                    int jj = j + hf;
                    int   sj = 0;
                    float aa = 0.f;
                    if (jj < cnt) {
                        sj = s_src[w * 32 + jj];
                        aa = s_w[(w * 4 + hh) * 33 + jj];
                    }
                    uint4 fr = __ldg(&featIn[(size_t)sj * 16 + sub]);
                    float2 f0 = __half22float2(*reinterpret_cast<__half2*>(&fr.x));
                    float2 f1 = __half22float2(*reinterpret_cast<__half2*>(&fr.y));
                    float2 f2 = __half22float2(*reinterpret_cast<__half2*>(&fr.z));
                    float2 f3 = __half22float2(*reinterpret_cast<__half2*>(&fr.w));
                    acc8[0] += f0.x * aa; acc8[1] += f0.y * aa;
                    acc8[2] += f1.x * aa; acc8[3] += f1.y * aa;
                    acc8[4] += f2.x * aa; acc8[5] += f2.y * aa;
                    acc8[6] += f3.x * aa; acc8[7] += f3.y * aa;
                }
            }
#pragma unroll
            for (int i = 0; i < 8; i++)
                acc8[i] += __shfl_down_sync(0xffffffffu, acc8[i], 16);
#pragma unroll
            for (int o = 16; o; o >>= 1) {
                q0 += __shfl_xor_sync(0xffffffffu, q0, o);
                q1 += __shfl_xor_sync(0xffffffffu, q1, o);
                q2 += __shfl_xor_sync(0xffffffffu, q2, o);
                q3 += __shfl_xor_sync(0xffffffffu, q3, o);
            }
            float qh = (hh == 0) ? q0 : ((hh == 1) ? q1 : ((hh == 2) ? q2 : q3));
            float inv = 1.f / qh;
#pragma unroll
            for (int i = 0; i < 8; i++) acc8[i] *= inv;
        }
        // relu + fp16 pack into sA row (lanes 0-15 hold the combined result)
        if (hf == 0) {
            uint4 u;
            unsigned* pu = reinterpret_cast<unsigned*>(&u);
#pragma unroll
            for (int p = 0; p < 4; p++) {
                float lo = fmaxf(acc8[p * 2], 0.f), hi2 = fmaxf(acc8[p * 2 + 1], 0.f);
                __half2 hp = __float22half2_rn(make_float2(lo, hi2));
                pu[p] = *reinterpret_cast<unsigned*>(&hp);
            }
            *reinterpret_cast<uint4*>(&sA[(it * 8 + w) * 136 + sub * 8]) = u;
        }
    }
    __syncthreads();   // act tile complete; s_w/s_src dead -> sB (W) may load

    gemm_core(sbuf, whichW, rb, featOut, elOut, erOut);
}

// ---------------- final aggregation + fused graph max-pool (reads A buffers) ------
__global__ void aggregate_pool_kernel() {
    __shared__ float s_w[8][4][33];
    __shared__ int   s_src[8][32];
    __shared__ float s_pool[8][128];
    int node = (blockIdx.x * blockDim.x + threadIdx.x) >> 5;
    int lane = threadIdx.x & 31;
    int w    = threadIdx.x >> 5;
    int sub  = lane & 15, hf = lane >> 4;
    int hh   = sub >> 2;

    int s0  = g_rowptr[node];
    int deg = g_rowptr[node + 1] - s0;
    float acc8[8];
#pragma unroll
    for (int i = 0; i < 8; i++) acc8[i] = 0.f;
    float q0 = 0.f, q1 = 0.f, q2 = 0.f, q3 = 0.f;

    if (deg > 0) {
        const float4* el4 = reinterpret_cast<const float4*>(g_elA);
        float4 erd = reinterpret_cast<const float4*>(g_erA)[node];
        const uint4* feat4 = reinterpret_cast<const uint4*>(g_featA);

        for (int base = 0; base < deg; base += 32) {
            int idx = base + lane;
            int s = 0;
            float w0 = 0.f, w1 = 0.f, w2 = 0.f, w3 = 0.f;
            if (idx < deg) {
                s = __ldg(&g_esrc[s0 + idx]);
                float4 ev = __ldg(&el4[s]);
                w0 = __expf(lrelu(ev.x + erd.x));
                w1 = __expf(lrelu(ev.y + erd.y));
                w2 = __expf(lrelu(ev.z + erd.z));
                w3 = __expf(lrelu(ev.w + erd.w));
                q0 += w0; q1 += w1; q2 += w2; q3 += w3;
            }
            __syncwarp();
            s_src[w][lane] = s;
            s_w[w][0][lane] = w0; s_w[w][1][lane] = w1;
            s_w[w][2][lane] = w2; s_w[w][3][lane] = w3;
            __syncwarp();
            int cnt = min(32, deg - base);
#pragma unroll 4
            for (int j = 0; j < cnt; j += 2) {
                int jj = j + hf;
                int   sj = 0;
                float aa = 0.f;
                if (jj < cnt) {
                    sj = s_src[w][jj];
                    aa = s_w[w][hh][jj];
                }
                uint4 fr = __ldg(&feat4[(size_t)sj * 16 + sub]);
                float2 f0 = __half22float2(*reinterpret_cast<__half2*>(&fr.x));
                float2 f1 = __half22float2(*reinterpret_cast<__half2*>(&fr.y));
                float2 f2 = __half22float2(*reinterpret_cast<__half2*>(&fr.z));
                float2 f3 = __half22float2(*reinterpret_cast<__half2*>(&fr.w));
                acc8[0] += f0.x * aa; acc8[1] += f0.y * aa;
                acc8[2] += f1.x * aa; acc8[3] += f1.y * aa;
                acc8[4] += f2.x * aa; acc8[5] += f2.y * aa;
                acc8[6] += f3.x * aa; acc8[7] += f3.y * aa;
            }
        }
#pragma unroll
        for (int i = 0; i < 8; i++)
            acc8[i] += __shfl_down_sync(0xffffffffu, acc8[i], 16);
#pragma unroll
        for (int o = 16; o; o >>= 1) {
            q0 += __shfl_xor_sync(0xffffffffu, q0, o);
            q1 += __shfl_xor_sync(0xffffffffu, q1, o);
            q2 += __shfl_xor_sync(0xffffffffu, q2, o);
            q3 += __shfl_xor_sync(0xffffffffu, q3, o);
        }
        float qh = (hh == 0) ? q0 : ((hh == 1) ? q1 : ((hh == 2) ? q2 : q3));
        float inv = 1.f / qh;
#pragma unroll
        for (int i = 0; i < 8; i++) acc8[i] *= inv;
    }
#pragma unroll
    for (int i = 0; i < 8; i++) acc8[i] = fmaxf(acc8[i], 0.f);

    // block max-pool -> 1 atomicMax per column per block
    if (hf == 0) {
#pragma unroll
        for (int i = 0; i < 8; i++) s_pool[w][sub * 8 + i] = acc8[i];
    }
    __syncthreads();
    int t = threadIdx.x;
    if (t < 128) {
        float m = s_pool[0][t];
#pragma unroll
        for (int i = 1; i < 8; i++) m = fmaxf(m, s_pool[i][t]);
        atomicMax(reinterpret_cast<int*>(&g_pooled[t]), __float_as_int(m));
    }
}

// ---------------- FC + softmax head ----------------
__global__ void head_kernel(const float* __restrict__ Wfc, const float* __restrict__ bfc,
                            float* __restrict__ out) {
    __shared__ float lg[8];
    int t = threadIdx.x;
    if (t < 8) {
        float acc = bfc[t];
        for (int k = 0; k < 128; k++) acc += g_pooled[k] * Wfc[k * 8 + t];
        lg[t] = acc;
    }
    __syncthreads();
    if (t == 0) {
        float m = lg[0];
        for (int i = 1; i < 8; i++) m = fmaxf(m, lg[i]);
        float e[8], s = 0.f;
        for (int i = 0; i < 8; i++) { e[i] = expf(lg[i] - m); s += e[i]; }
        for (int i = 0; i < 8; i++) out[i] = e[i] / s;
    }
}

// ---------------- launch ----------------
extern "C" void kernel_launch(void* const* d_in, const int* in_sizes, int n_in,
                              void* d_out, int out_size) {
    (void)in_sizes; (void)n_in; (void)out_size;
    const float* x   = (const float*)d_in[0];
    const int*   src = (const int*)d_in[1];
    const int*   dst = (const int*)d_in[2];
    const float* W1  = (const float*)d_in[3];
    const float* al1 = (const float*)d_in[4];
    const float* ar1 = (const float*)d_in[5];
    const float* W2  = (const float*)d_in[6];
    const float* al2 = (const float*)d_in[7];
    const float* ar2 = (const float*)d_in[8];
    const float* W3  = (const float*)d_in[9];
    const float* al3 = (const float*)d_in[10];
    const float* ar3 = (const float*)d_in[11];
    const float* Wfc = (const float*)d_in[12];
    const float* bfc = (const float*)d_in[13];
    float* out = (float*)d_out;

    cudaFuncSetAttribute(gemm1_kernel,
                         cudaFuncAttributeMaxDynamicSharedMemorySize, SMEM_GEMM);
    cudaFuncSetAttribute(fused_agg_gemm_kernel,
                         cudaFuncAttributeMaxDynamicSharedMemorySize, SMEM_GEMM);
    cudaFuncSetAttribute(gemm1_kernel,
                         cudaFuncAttributePreferredSharedMemoryCarveout, 100);
    cudaFuncSetAttribute(fused_agg_gemm_kernel,
                         cudaFuncAttributePreferredSharedMemoryCarveout, 100);

    const int GEMM_BLOCKS = (N_NODES + 127) / 128;   // 782

    convW_kernel<<<64, 256>>>(W1, W2, W3);
    init_kernel<<<(N_NODES + 255) / 256, 256>>>();
    count_kernel<<<(N_EDGES / 4 + 255) / 256, 256>>>(dst);
    gemm1_kernel<<<GEMM_BLOCKS, 256, SMEM_GEMM>>>(x, al1, ar1);   // layer 1 (profiled)

    scan1_kernel<<<NBLK_SCAN, 1024>>>();
    scan2_kernel<<<1, 128>>>();
    scan3_kernel<<<(N_NODES + 255) / 256, 256>>>();
    fill_kernel<<<(N_EDGES / 4 + 255) / 256, 256>>>(src, dst);

    // agg(layer1) + gemm(layer2): A -> B
    fused_agg_gemm_kernel<<<GEMM_BLOCKS, 256, SMEM_GEMM>>>(0, 1, al2, ar2);
    // agg(layer2) + gemm(layer3): B -> A
    fused_agg_gemm_kernel<<<GEMM_BLOCKS, 256, SMEM_GEMM>>>(1, 2, al3, ar3);
    // agg(layer3) + max-pool (reads A)
    aggregate_pool_kernel<<<N_NODES / 8, 256>>>();

    head_kernel<<<1, 32>>>(Wfc, bfc, out);
}

// round 15
// speedup vs baseline: 2.9159x; 1.0838x over previous
#include <cuda_runtime.h>
#include <cuda_fp16.h>
#include <mma.h>
using namespace nvcuda;

#define N_NODES 100000
#define N_EDGES 1600000
#define NBLK_SCAN 98   // ceil(100000/1024)

// BM=64 GEMM smem layout
#define OFF_B   17408                     // sA: 64 x 136 halfs
#define OFF_SW  17408                     // s_w aliases sB region (dead until W load)
#define OFF_SSRC (17408 + 4224)
#define OFF_AL  52224                     // after sA+sB
#define SMEM_GEMM (52224 + 1024)

// ---------------- scratch (allocation-free: __device__ globals) ----------------
__device__ __align__(16) __half g_featA[100096 * 128];   // double-buffered fp16 features
__device__ __align__(16) __half g_featB[100096 * 128];
__device__ __align__(16) __half g_Wh[3][128 * 128];      // fp16 weights
__device__ __align__(16) float g_elA[N_NODES * 4];
__device__ __align__(16) float g_erA[N_NODES * 4];
__device__ __align__(16) float g_elB[N_NODES * 4];
__device__ __align__(16) float g_erB[N_NODES * 4];
__device__ int   g_rowptr[N_NODES + 1];
__device__ int   g_cursor[N_NODES];
__device__ int   g_deg[N_NODES];
__device__ int   g_esrc[N_EDGES];
__device__ int   g_bsum[128];
__device__ float g_pooled[128];

__device__ __forceinline__ float lrelu(float x) { return x > 0.f ? x : 0.2f * x; }

// ---------------- converts ----------------
__global__ void convW_kernel(const float* __restrict__ W1, const float* __restrict__ W2,
                             const float* __restrict__ W3) {
    int i = blockIdx.x * blockDim.x + threadIdx.x;
    if (i < 128 * 128) {
        g_Wh[0][i] = __float2half_rn(W1[i]);
        g_Wh[1][i] = __float2half_rn(W2[i]);
        g_Wh[2][i] = __float2half_rn(W3[i]);
    }
}

// ---------------- init: zero degree counts + pooled ----------------
__global__ void init_kernel() {
    int i = blockIdx.x * blockDim.x + threadIdx.x;
    if (i < N_NODES) g_deg[i] = 0;
    if (i < 128)     g_pooled[i] = 0.f;
}

// ---------------- CSR build (int4-vectorized edge reads) ----------------
__global__ void count_kernel(const int* __restrict__ dst) {
    int e4 = blockIdx.x * blockDim.x + threadIdx.x;
    if (e4 < N_EDGES / 4) {
        int4 d = __ldg(&reinterpret_cast<const int4*>(dst)[e4]);
        atomicAdd(&g_deg[d.x], 1);
        atomicAdd(&g_deg[d.y], 1);
        atomicAdd(&g_deg[d.z], 1);
        atomicAdd(&g_deg[d.w], 1);
    }
}

__global__ void scan1_kernel() {          // NBLK_SCAN blocks x 1024
    __shared__ int wsum[32];
    int t = threadIdx.x, lane = t & 31, w = t >> 5;
    int i = blockIdx.x * 1024 + t;
    int v = (i < N_NODES) ? g_deg[i] : 0;
    int x = v;
#pragma unroll
    for (int o = 1; o < 32; o <<= 1) {
        int y = __shfl_up_sync(0xffffffffu, x, o);
        if (lane >= o) x += y;
    }
    if (lane == 31) wsum[w] = x;
    __syncthreads();
    if (w == 0) {
        int sv = wsum[lane];
#pragma unroll
        for (int o = 1; o < 32; o <<= 1) {
            int y = __shfl_up_sync(0xffffffffu, sv, o);
            if (lane >= o) sv += y;
        }
        wsum[lane] = sv;
    }
    __syncthreads();
    int incl = x + (w > 0 ? wsum[w - 1] : 0);
    if (i < N_NODES) g_rowptr[i + 1] = incl;
    if (t == 1023)   g_bsum[blockIdx.x] = incl;
}

__global__ void scan2_kernel() {          // 1 block, 128 threads
    __shared__ int s[128];
    int t = threadIdx.x;
    int v = (t < NBLK_SCAN) ? g_bsum[t] : 0;
    s[t] = v; __syncthreads();
    for (int o = 1; o < 128; o <<= 1) {
        int y = (t >= o) ? s[t - o] : 0;
        __syncthreads();
        s[t] += y;
        __syncthreads();
    }
    if (t < NBLK_SCAN) g_bsum[t] = s[t] - v;
}

__global__ void scan3_kernel() {
    int i = blockIdx.x * blockDim.x + threadIdx.x;
    if (i < N_NODES) {
        int r = g_rowptr[i + 1] + g_bsum[i >> 10];
        g_rowptr[i + 1] = r;
        g_cursor[i] = r - g_deg[i];
        if (i == 0) g_rowptr[0] = 0;
    }
}

__global__ void fill_kernel(const int* __restrict__ src, const int* __restrict__ dst) {
    int e4 = blockIdx.x * blockDim.x + threadIdx.x;
    if (e4 < N_EDGES / 4) {
        int4 s = __ldg(&reinterpret_cast<const int4*>(src)[e4]);
        int4 d = __ldg(&reinterpret_cast<const int4*>(dst)[e4]);
        g_esrc[atomicAdd(&g_cursor[d.x], 1)] = s.x;
        g_esrc[atomicAdd(&g_cursor[d.y], 1)] = s.y;
        g_esrc[atomicAdd(&g_cursor[d.z], 1)] = s.z;
        g_esrc[atomicAdd(&g_cursor[d.w], 1)] = s.w;
    }
}

// ---------------- shared GEMM core (BM=64), called with sA filled ----------------
// 8 warps, warp tile 16x64: wr=w&3 -> rows wr*16..+15, wc=w>>2 -> cols wc*64..+63.
__device__ __forceinline__ void gemm_core(char* sbuf, int which, int rb,
                                          __half* featOut, float* elOut, float* erOut) {
    __half* sA  = reinterpret_cast<__half*>(sbuf);
    __half* sB  = reinterpret_cast<__half*>(sbuf + OFF_B);
    float*  sC  = reinterpret_cast<float*>(sbuf);     // 8 x (16 x 68) f32 = 34816 B
    float*  sal = reinterpret_cast<float*>(sbuf + OFF_AL);
    float*  sar = sal + 128;
    int t = threadIdx.x, w = t >> 5, lane = t & 31;
    int wr = w & 3, wc = w >> 2;

    // load full W: 128 x 128 halfs
    const __half* Wh = g_Wh[which];
    for (int i = t; i < 2048; i += 256) {
        int r = i >> 4, s = i & 15;
        *reinterpret_cast<uint4*>(&sB[r * 136 + s * 8]) =
            *reinterpret_cast<const uint4*>(&Wh[r * 128 + s * 8]);
    }
    __syncthreads();

    wmma::fragment<wmma::matrix_a, 16, 16, 16, __half, wmma::row_major> af;
    wmma::fragment<wmma::matrix_b, 16, 16, 16, __half, wmma::row_major> bf;
    wmma::fragment<wmma::accumulator, 16, 16, 16, float> acc[4];
#pragma unroll
    for (int i = 0; i < 4; i++) wmma::fill_fragment(acc[i], 0.f);

#pragma unroll
    for (int k = 0; k < 8; k++) {
        wmma::load_matrix_sync(af, sA + (wr * 16) * 136 + k * 16, 136);
#pragma unroll
        for (int i = 0; i < 4; i++) {
            wmma::load_matrix_sync(bf, sB + (k * 16) * 136 + (wc * 64 + i * 16), 136);
            wmma::mma_sync(acc[i], af, bf, acc[i]);
        }
    }
    __syncthreads();   // all warps done reading sA/sB; sC aliases them

    float* myC = sC + w * (16 * 68);
#pragma unroll
    for (int i = 0; i < 4; i++)
        wmma::store_matrix_sync(myC + i * 16, acc[i], 68, wmma::mem_row_major);
    __syncwarp();

    // epilogue: lane -> row r=lane&15, head-half hi=lane>>4, head h=2*wc+hi (32 cols)
    int r  = lane & 15, hi = lane >> 4;
    int h  = 2 * wc + hi;
    int row = rb + wr * 16 + r;
    const float* rowC = myC + r * 68 + hi * 32;
    if (row < N_NODES) {
        float pl = 0.f, pr = 0.f;
        uint4 packo[4];                      // 32 halfs = 16 unsigned
        unsigned* pw = reinterpret_cast<unsigned*>(packo);
#pragma unroll
        for (int c4 = 0; c4 < 8; c4++) {
            float4 v = *reinterpret_cast<const float4*>(&rowC[c4 * 4]);
            float4 a = *reinterpret_cast<float4*>(&sal[h * 32 + c4 * 4]);
            float4 b = *reinterpret_cast<float4*>(&sar[h * 32 + c4 * 4]);
            pl += v.x * a.x + v.y * a.y + v.z * a.z + v.w * a.w;
            pr += v.x * b.x + v.y * b.y + v.z * b.z + v.w * b.w;
            __half2 p0 = __float22half2_rn(make_float2(v.x, v.y));
            __half2 p1 = __float22half2_rn(make_float2(v.z, v.w));
            pw[c4 * 2 + 0] = *reinterpret_cast<unsigned*>(&p0);
            pw[c4 * 2 + 1] = *reinterpret_cast<unsigned*>(&p1);
        }
        uint4* dstp = reinterpret_cast<uint4*>(featOut) + (size_t)row * 16 + h * 4;
        dstp[0] = packo[0]; dstp[1] = packo[1];
        dstp[2] = packo[2]; dstp[3] = packo[3];
        elOut[row * 4 + h] = pl;
        erOut[row * 4 + h] = pr;
    }
}

// ---------------- layer-1 GEMM: feat = x @ W1 (fp32 x converted in-flight) ----------
__global__ void __launch_bounds__(256, 4)
gemm1_kernel(const float* __restrict__ xin,
             const float* __restrict__ al, const float* __restrict__ ar) {
    extern __shared__ __align__(16) char sbuf[];
    __half* sA  = reinterpret_cast<__half*>(sbuf);
    float*  sal = reinterpret_cast<float*>(sbuf + OFF_AL);
    float*  sar = sal + 128;
    int t = threadIdx.x;
    int rb = blockIdx.x * 64;

    if (t < 128) sal[t] = __ldg(&al[t]);
    else         sar[t - 128] = __ldg(&ar[t - 128]);

    for (int i = t; i < 1024; i += 256) {    // 64 rows x 16 chunks
        int r = i >> 4, s = i & 15;
        float4 a = make_float4(0.f, 0.f, 0.f, 0.f), b = a;
        if (rb + r < N_NODES) {
            const float4* xr =
                reinterpret_cast<const float4*>(xin + (size_t)(rb + r) * 128 + s * 8);
            a = __ldg(xr); b = __ldg(xr + 1);
        }
        __half2 h0 = __float22half2_rn(make_float2(a.x, a.y));
        __half2 h1 = __float22half2_rn(make_float2(a.z, a.w));
        __half2 h2 = __float22half2_rn(make_float2(b.x, b.y));
        __half2 h3 = __float22half2_rn(make_float2(b.z, b.w));
        uint4 u;
        u.x = *reinterpret_cast<unsigned*>(&h0);
        u.y = *reinterpret_cast<unsigned*>(&h1);
        u.z = *reinterpret_cast<unsigned*>(&h2);
        u.w = *reinterpret_cast<unsigned*>(&h3);
        *reinterpret_cast<uint4*>(&sA[r * 136 + s * 8]) = u;
    }
    __syncthreads();
    gemm_core(sbuf, 0, rb, g_featA, g_elA, g_erA);
}

// ---------------- fused: aggregate(prev layer) into smem act -> GEMM next layer ----
__global__ void __launch_bounds__(256, 4)
fused_agg_gemm_kernel(int dir, int whichW,
                      const float* __restrict__ al, const float* __restrict__ ar) {
    extern __shared__ __align__(16) char sbuf[];
    __half* sA   = reinterpret_cast<__half*>(sbuf);
    float*  s_w  = reinterpret_cast<float*>(sbuf + OFF_SW);     // [8][4][33]
    int*    s_src= reinterpret_cast<int*>(sbuf + OFF_SSRC);     // [8][32]
    float*  sal  = reinterpret_cast<float*>(sbuf + OFF_AL);
    float*  sar  = sal + 128;

    const uint4*  featIn = reinterpret_cast<const uint4*>(dir ? g_featB : g_featA);
    const float4* elIn   = reinterpret_cast<const float4*>(dir ? g_elB : g_elA);
    const float4* erIn   = reinterpret_cast<const float4*>(dir ? g_erB : g_erA);
    __half* featOut = dir ? g_featA : g_featB;
    float*  elOut   = dir ? g_elA : g_elB;
    float*  erOut   = dir ? g_erA : g_erB;

    int t = threadIdx.x, w = t >> 5, lane = t & 31;
    int rb = blockIdx.x * 64;
    int sub = lane & 15, hf = lane >> 4;
    int hh  = sub >> 2;

    if (t < 128) sal[t] = __ldg(&al[t]);
    else         sar[t - 128] = __ldg(&ar[t - 128]);

    // ---- aggregate phase: each warp produces 8 act rows into sA ----
    for (int it = 0; it < 8; it++) {
        int node = rb + it * 8 + w;
        float acc8[8];
#pragma unroll
        for (int i = 0; i < 8; i++) acc8[i] = 0.f;
        float q0 = 0.f, q1 = 0.f, q2 = 0.f, q3 = 0.f;
        int s0 = 0, deg = 0;
        if (node < N_NODES) {
            s0 = g_rowptr[node];
            deg = g_rowptr[node + 1] - s0;
        }
        if (deg > 0) {
            float4 erd = erIn[node];
            for (int base = 0; base < deg; base += 32) {
                int idx = base + lane;
                int s = 0;
                float w0 = 0.f, w1 = 0.f, w2 = 0.f, w3 = 0.f;
                if (idx < deg) {
                    s = __ldg(&g_esrc[s0 + idx]);
                    float4 ev = __ldg(&elIn[s]);
                    w0 = __expf(lrelu(ev.x + erd.x));
                    w1 = __expf(lrelu(ev.y + erd.y));
                    w2 = __expf(lrelu(ev.z + erd.z));
                    w3 = __expf(lrelu(ev.w + erd.w));
                    q0 += w0; q1 += w1; q2 += w2; q3 += w3;
                }
                __syncwarp();
                s_src[w * 32 + lane] = s;
                s_w[(w * 4 + 0) * 33 + lane] = w0;
                s_w[(w * 4 + 1) * 33 + lane] = w1;
                s_w[(w * 4 + 2) * 33 + lane] = w2;
                s_w[(w * 4 + 3) * 33 + lane] = w3;
                __syncwarp();
                int cnt = min(32, deg - base);
#pragma unroll 4
                for (int j = 0; j < cnt; j += 2) {
                    int jj = j + hf;
                    int   sj = 0;
                    float aa = 0.f;
                    if (jj < cnt) {
                        sj = s_src[w * 32 + jj];
                        aa = s_w[(w * 4 + hh) * 33 + jj];
                    }
                    uint4 fr = __ldg(&featIn[(size_t)sj * 16 + sub]);
                    float2 f0 = __half22float2(*reinterpret_cast<__half2*>(&fr.x));
                    float2 f1 = __half22float2(*reinterpret_cast<__half2*>(&fr.y));
                    float2 f2 = __half22float2(*reinterpret_cast<__half2*>(&fr.z));
                    float2 f3 = __half22float2(*reinterpret_cast<__half2*>(&fr.w));
                    acc8[0] += f0.x * aa; acc8[1] += f0.y * aa;
                    acc8[2] += f1.x * aa; acc8[3] += f1.y * aa;
                    acc8[4] += f2.x * aa; acc8[5] += f2.y * aa;
                    acc8[6] += f3.x * aa; acc8[7] += f3.y * aa;
                }
            }
#pragma unroll
            for (int i = 0; i < 8; i++)
                acc8[i] += __shfl_down_sync(0xffffffffu, acc8[i], 16);
#pragma unroll
            for (int o = 16; o; o >>= 1) {
                q0 += __shfl_xor_sync(0xffffffffu, q0, o);
                q1 += __shfl_xor_sync(0xffffffffu, q1, o);
                q2 += __shfl_xor_sync(0xffffffffu, q2, o);
                q3 += __shfl_xor_sync(0xffffffffu, q3, o);
            }
            float qh = (hh == 0) ? q0 : ((hh == 1) ? q1 : ((hh == 2) ? q2 : q3));
            float inv = 1.f / qh;
#pragma unroll
            for (int i = 0; i < 8; i++) acc8[i] *= inv;
        }
        if (hf == 0) {     // relu + fp16 pack into sA row
            uint4 u;
            unsigned* pu = reinterpret_cast<unsigned*>(&u);
#pragma unroll
            for (int p = 0; p < 4; p++) {
                float lo = fmaxf(acc8[p * 2], 0.f), hi2 = fmaxf(acc8[p * 2 + 1], 0.f);
                __half2 hp = __float22half2_rn(make_float2(lo, hi2));
                pu[p] = *reinterpret_cast<unsigned*>(&hp);
            }
            *reinterpret_cast<uint4*>(&sA[(it * 8 + w) * 136 + sub * 8]) = u;
        }
    }
    __syncthreads();   // act tile complete; s_w/s_src dead -> sB (W) may load

    gemm_core(sbuf, whichW, rb, featOut, elOut, erOut);
}

// ---------------- final aggregation + fused graph max-pool (reads A buffers) ------
__global__ void aggregate_pool_kernel() {
    __shared__ float s_w[8][4][33];
    __shared__ int   s_src[8][32];
    __shared__ float s_pool[8][128];
    int node = (blockIdx.x * blockDim.x + threadIdx.x) >> 5;
    int lane = threadIdx.x & 31;
    int w    = threadIdx.x >> 5;
    int sub  = lane & 15, hf = lane >> 4;
    int hh   = sub >> 2;

    int s0  = g_rowptr[node];
    int deg = g_rowptr[node + 1] - s0;
    float acc8[8];
#pragma unroll
    for (int i = 0; i < 8; i++) acc8[i] = 0.f;
    float q0 = 0.f, q1 = 0.f, q2 = 0.f, q3 = 0.f;

    if (deg > 0) {
        const float4* el4 = reinterpret_cast<const float4*>(g_elA);
        float4 erd = reinterpret_cast<const float4*>(g_erA)[node];
        const uint4* feat4 = reinterpret_cast<const uint4*>(g_featA);

        for (int base = 0; base < deg; base += 32) {
            int idx = base + lane;
            int s = 0;
            float w0 = 0.f, w1 = 0.f, w2 = 0.f, w3 = 0.f;
            if (idx < deg) {
                s = __ldg(&g_esrc[s0 + idx]);
                float4 ev = __ldg(&el4[s]);
                w0 = __expf(lrelu(ev.x + erd.x));
                w1 = __expf(lrelu(ev.y + erd.y));
                w2 = __expf(lrelu(ev.z + erd.z));
                w3 = __expf(lrelu(ev.w + erd.w));
                q0 += w0; q1 += w1; q2 += w2; q3 += w3;
            }
            __syncwarp();
            s_src[w][lane] = s;
            s_w[w][0][lane] = w0; s_w[w][1][lane] = w1;
            s_w[w][2][lane] = w2; s_w[w][3][lane] = w3;
            __syncwarp();
            int cnt = min(32, deg - base);
#pragma unroll 4
            for (int j = 0; j < cnt; j += 2) {
                int jj = j + hf;
                int   sj = 0;
                float aa = 0.f;
                if (jj < cnt) {
                    sj = s_src[w][jj];
                    aa = s_w[w][hh][jj];
                }
                uint4 fr = __ldg(&feat4[(size_t)sj * 16 + sub]);
                float2 f0 = __half22float2(*reinterpret_cast<__half2*>(&fr.x));
                float2 f1 = __half22float2(*reinterpret_cast<__half2*>(&fr.y));
                float2 f2 = __half22float2(*reinterpret_cast<__half2*>(&fr.z));
                float2 f3 = __half22float2(*reinterpret_cast<__half2*>(&fr.w));
                acc8[0] += f0.x * aa; acc8[1] += f0.y * aa;
                acc8[2] += f1.x * aa; acc8[3] += f1.y * aa;
                acc8[4] += f2.x * aa; acc8[5] += f2.y * aa;
                acc8[6] += f3.x * aa; acc8[7] += f3.y * aa;
            }
        }
#pragma unroll
        for (int i = 0; i < 8; i++)
            acc8[i] += __shfl_down_sync(0xffffffffu, acc8[i], 16);
#pragma unroll
        for (int o = 16; o; o >>= 1) {
            q0 += __shfl_xor_sync(0xffffffffu, q0, o);
            q1 += __shfl_xor_sync(0xffffffffu, q1, o);
            q2 += __shfl_xor_sync(0xffffffffu, q2, o);
            q3 += __shfl_xor_sync(0xffffffffu, q3, o);
        }
        float qh = (hh == 0) ? q0 : ((hh == 1) ? q1 : ((hh == 2) ? q2 : q3));
        float inv = 1.f / qh;
#pragma unroll
        for (int i = 0; i < 8; i++) acc8[i] *= inv;
    }
#pragma unroll
    for (int i = 0; i < 8; i++) acc8[i] = fmaxf(acc8[i], 0.f);

    if (hf == 0) {
#pragma unroll
        for (int i = 0; i < 8; i++) s_pool[w][sub * 8 + i] = acc8[i];
    }
    __syncthreads();
    int t = threadIdx.x;
    if (t < 128) {
        float m = s_pool[0][t];
#pragma unroll
        for (int i = 1; i < 8; i++) m = fmaxf(m, s_pool[i][t]);
        atomicMax(reinterpret_cast<int*>(&g_pooled[t]), __float_as_int(m));
    }
}

// ---------------- FC + softmax head ----------------
__global__ void head_kernel(const float* __restrict__ Wfc, const float* __restrict__ bfc,
                            float* __restrict__ out) {
    __shared__ float lg[8];
    int t = threadIdx.x;
    if (t < 8) {
        float acc = bfc[t];
        for (int k = 0; k < 128; k++) acc += g_pooled[k] * Wfc[k * 8 + t];
        lg[t] = acc;
    }
    __syncthreads();
    if (t == 0) {
        float m = lg[0];
        for (int i = 1; i < 8; i++) m = fmaxf(m, lg[i]);
        float e[8], s = 0.f;
        for (int i = 0; i < 8; i++) { e[i] = expf(lg[i] - m); s += e[i]; }
        for (int i = 0; i < 8; i++) out[i] = e[i] / s;
    }
}

// ---------------- launch ----------------
extern "C" void kernel_launch(void* const* d_in, const int* in_sizes, int n_in,
                              void* d_out, int out_size) {
    (void)in_sizes; (void)n_in; (void)out_size;
    const float* x   = (const float*)d_in[0];
    const int*   src = (const int*)d_in[1];
    const int*   dst = (const int*)d_in[2];
    const float* W1  = (const float*)d_in[3];
    const float* al1 = (const float*)d_in[4];
    const float* ar1 = (const float*)d_in[5];
    const float* W2  = (const float*)d_in[6];
    const float* al2 = (const float*)d_in[7];
    const float* ar2 = (const float*)d_in[8];
    const float* W3  = (const float*)d_in[9];
    const float* al3 = (const float*)d_in[10];
    const float* ar3 = (const float*)d_in[11];
    const float* Wfc = (const float*)d_in[12];
    const float* bfc = (const float*)d_in[13];
    float* out = (float*)d_out;

    cudaFuncSetAttribute(gemm1_kernel,
                         cudaFuncAttributeMaxDynamicSharedMemorySize, SMEM_GEMM);
    cudaFuncSetAttribute(fused_agg_gemm_kernel,
                         cudaFuncAttributeMaxDynamicSharedMemorySize, SMEM_GEMM);
    cudaFuncSetAttribute(gemm1_kernel,
                         cudaFuncAttributePreferredSharedMemoryCarveout, 100);
    cudaFuncSetAttribute(fused_agg_gemm_kernel,
                         cudaFuncAttributePreferredSharedMemoryCarveout, 100);

    const int GEMM_BLOCKS = (N_NODES + 63) / 64;   // 1563

    convW_kernel<<<64, 256>>>(W1, W2, W3);
    init_kernel<<<(N_NODES + 255) / 256, 256>>>();
    count_kernel<<<(N_EDGES / 4 + 255) / 256, 256>>>(dst);
    gemm1_kernel<<<GEMM_BLOCKS, 256, SMEM_GEMM>>>(x, al1, ar1);   // layer 1 (profiled)

    scan1_kernel<<<NBLK_SCAN, 1024>>>();
    scan2_kernel<<<1, 128>>>();
    scan3_kernel<<<(N_NODES + 255) / 256, 256>>>();
    fill_kernel<<<(N_EDGES / 4 + 255) / 256, 256>>>(src, dst);

    // agg(layer1) + gemm(layer2): A -> B
    fused_agg_gemm_kernel<<<GEMM_BLOCKS, 256, SMEM_GEMM>>>(0, 1, al2, ar2);
    // agg(layer2) + gemm(layer3): B -> A
    fused_agg_gemm_kernel<<<GEMM_BLOCKS, 256, SMEM_GEMM>>>(1, 2, al3, ar3);
    // agg(layer3) + max-pool (reads A)
    aggregate_pool_kernel<<<N_NODES / 8, 256>>>();

    head_kernel<<<1, 32>>>(Wfc, bfc, out);
}

// round 16
// speedup vs baseline: 2.9293x; 1.0046x over previous
#include <cuda_runtime.h>
#include <cuda_fp16.h>
#include <mma.h>
using namespace nvcuda;

#define N_NODES 100000
#define N_EDGES 1600000
#define NBLK_SCAN 98   // ceil(100000/1024)

// BM=64 GEMM smem layout
#define OFF_B   17408                     // sA: 64 x 136 halfs
#define OFF_SW  17408                     // s_w aliases sB region (dead until W load)
#define OFF_SSRC (17408 + 4224)
#define OFF_AL  52224                     // after sA+sB
#define SMEM_GEMM (52224 + 1024)

#define FILL_BLOCKS 1563                  // ceil(400000/256)
#define GEMM_BLOCKS 1563                  // ceil(100000/64)

// ---------------- scratch (allocation-free: __device__ globals) ----------------
__device__ __align__(16) __half g_featA[100096 * 128];   // double-buffered fp16 features
__device__ __align__(16) __half g_featB[100096 * 128];
__device__ __align__(16) __half g_Wh[3][128 * 128];      // fp16 weights
__device__ __align__(16) float g_elA[N_NODES * 4];
__device__ __align__(16) float g_erA[N_NODES * 4];
__device__ __align__(16) float g_elB[N_NODES * 4];
__device__ __align__(16) float g_erB[N_NODES * 4];
__device__ int   g_rowptr[N_NODES + 1];
__device__ int   g_cursor[N_NODES];
__device__ int   g_deg[N_NODES];
__device__ int   g_esrc[N_EDGES];
__device__ int   g_bsum[128];
__device__ float g_pooled[128];

__device__ __forceinline__ float lrelu(float x) { return x > 0.f ? x : 0.2f * x; }

// ---------------- prep: convert W + zero degree counts + pooled ----------------
__global__ void prep_kernel(const float* __restrict__ W1, const float* __restrict__ W2,
                            const float* __restrict__ W3) {
    int i = blockIdx.x * blockDim.x + threadIdx.x;
    if (i < 128 * 128) {
        g_Wh[0][i] = __float2half_rn(W1[i]);
        g_Wh[1][i] = __float2half_rn(W2[i]);
        g_Wh[2][i] = __float2half_rn(W3[i]);
    }
    if (i < N_NODES) g_deg[i] = 0;
    if (i < 128)     g_pooled[i] = 0.f;
}

// ---------------- CSR build (int4-vectorized edge reads) ----------------
__global__ void count_kernel(const int* __restrict__ dst) {
    int e4 = blockIdx.x * blockDim.x + threadIdx.x;
    if (e4 < N_EDGES / 4) {
        int4 d = __ldg(&reinterpret_cast<const int4*>(dst)[e4]);
        atomicAdd(&g_deg[d.x], 1);
        atomicAdd(&g_deg[d.y], 1);
        atomicAdd(&g_deg[d.z], 1);
        atomicAdd(&g_deg[d.w], 1);
    }
}

__global__ void scan1_kernel() {          // NBLK_SCAN blocks x 1024
    __shared__ int wsum[32];
    int t = threadIdx.x, lane = t & 31, w = t >> 5;
    int i = blockIdx.x * 1024 + t;
    int v = (i < N_NODES) ? g_deg[i] : 0;
    int x = v;
#pragma unroll
    for (int o = 1; o < 32; o <<= 1) {
        int y = __shfl_up_sync(0xffffffffu, x, o);
        if (lane >= o) x += y;
    }
    if (lane == 31) wsum[w] = x;
    __syncthreads();
    if (w == 0) {
        int sv = wsum[lane];
#pragma unroll
        for (int o = 1; o < 32; o <<= 1) {
            int y = __shfl_up_sync(0xffffffffu, sv, o);
            if (lane >= o) sv += y;
        }
        wsum[lane] = sv;
    }
    __syncthreads();
    int incl = x + (w > 0 ? wsum[w - 1] : 0);
    if (i < N_NODES) g_rowptr[i + 1] = incl;
    if (t == 1023)   g_bsum[blockIdx.x] = incl;
}

// scan3 now re-derives the 98-entry block-prefix in smem (absorbs old scan2)
__global__ void scan3_kernel() {
    __shared__ int s[128];
    int t = threadIdx.x;
    if (t < 128) s[t] = (t < NBLK_SCAN) ? g_bsum[t] : 0;
    __syncthreads();
    for (int o = 1; o < 128; o <<= 1) {
        int y = (t < 128 && t >= o) ? s[t - o] : 0;
        __syncthreads();
        if (t < 128) s[t] += y;
        __syncthreads();
    }
    int i = blockIdx.x * blockDim.x + t;
    if (i < N_NODES) {
        int b = i >> 10;
        int off = (b > 0) ? s[b - 1] : 0;
        int r = g_rowptr[i + 1] + off;
        g_rowptr[i + 1] = r;
        g_cursor[i] = r - g_deg[i];
        if (i == 0) g_rowptr[0] = 0;
    }
}

// ---------------- shared GEMM core (BM=64), called with sA filled ----------------
// 8 warps, warp tile 16x64: wr=w&3 -> rows wr*16..+15, wc=w>>2 -> cols wc*64..+63.
__device__ __forceinline__ void gemm_core(char* sbuf, int which, int rb,
                                          __half* featOut, float* elOut, float* erOut) {
    __half* sA  = reinterpret_cast<__half*>(sbuf);
    __half* sB  = reinterpret_cast<__half*>(sbuf + OFF_B);
    float*  sC  = reinterpret_cast<float*>(sbuf);     // 8 x (16 x 68) f32 = 34816 B
    float*  sal = reinterpret_cast<float*>(sbuf + OFF_AL);
    float*  sar = sal + 128;
    int t = threadIdx.x, w = t >> 5, lane = t & 31;
    int wr = w & 3, wc = w >> 2;

    // load full W: 128 x 128 halfs
    const __half* Wh = g_Wh[which];
    for (int i = t; i < 2048; i += 256) {
        int r = i >> 4, s = i & 15;
        *reinterpret_cast<uint4*>(&sB[r * 136 + s * 8]) =
            *reinterpret_cast<const uint4*>(&Wh[r * 128 + s * 8]);
    }
    __syncthreads();

    wmma::fragment<wmma::matrix_a, 16, 16, 16, __half, wmma::row_major> af;
    wmma::fragment<wmma::matrix_b, 16, 16, 16, __half, wmma::row_major> bf;
    wmma::fragment<wmma::accumulator, 16, 16, 16, float> acc[4];
#pragma unroll
    for (int i = 0; i < 4; i++) wmma::fill_fragment(acc[i], 0.f);

#pragma unroll
    for (int k = 0; k < 8; k++) {
        wmma::load_matrix_sync(af, sA + (wr * 16) * 136 + k * 16, 136);
#pragma unroll
        for (int i = 0; i < 4; i++) {
            wmma::load_matrix_sync(bf, sB + (k * 16) * 136 + (wc * 64 + i * 16), 136);
            wmma::mma_sync(acc[i], af, bf, acc[i]);
        }
    }
    __syncthreads();   // all warps done reading sA/sB; sC aliases them

    float* myC = sC + w * (16 * 68);
#pragma unroll
    for (int i = 0; i < 4; i++)
        wmma::store_matrix_sync(myC + i * 16, acc[i], 68, wmma::mem_row_major);
    __syncwarp();

    // epilogue: lane -> row r=lane&15, head-half hi=lane>>4, head h=2*wc+hi (32 cols)
    int r  = lane & 15, hi = lane >> 4;
    int h  = 2 * wc + hi;
    int row = rb + wr * 16 + r;
    const float* rowC = myC + r * 68 + hi * 32;
    if (row < N_NODES) {
        float pl = 0.f, pr = 0.f;
        uint4 packo[4];                      // 32 halfs = 16 unsigned
        unsigned* pw = reinterpret_cast<unsigned*>(packo);
#pragma unroll
        for (int c4 = 0; c4 < 8; c4++) {
            float4 v = *reinterpret_cast<const float4*>(&rowC[c4 * 4]);
            float4 a = *reinterpret_cast<float4*>(&sal[h * 32 + c4 * 4]);
            float4 b = *reinterpret_cast<float4*>(&sar[h * 32 + c4 * 4]);
            pl += v.x * a.x + v.y * a.y + v.z * a.z + v.w * a.w;
            pr += v.x * b.x + v.y * b.y + v.z * b.z + v.w * b.w;
            __half2 p0 = __float22half2_rn(make_float2(v.x, v.y));
            __half2 p1 = __float22half2_rn(make_float2(v.z, v.w));
            pw[c4 * 2 + 0] = *reinterpret_cast<unsigned*>(&p0);
            pw[c4 * 2 + 1] = *reinterpret_cast<unsigned*>(&p1);
        }
        uint4* dstp = reinterpret_cast<uint4*>(featOut) + (size_t)row * 16 + h * 4;
        dstp[0] = packo[0]; dstp[1] = packo[1];
        dstp[2] = packo[2]; dstp[3] = packo[3];
        elOut[row * 4 + h] = pl;
        erOut[row * 4 + h] = pr;
    }
}

// ---------------- merged: fill (CSR scatter) ∥ layer-1 GEMM ----------------
// blocks [0, FILL_BLOCKS) do the esrc scatter; remaining blocks run gemm1.
__global__ void __launch_bounds__(256, 4)
fill_gemm1_kernel(const int* __restrict__ src, const int* __restrict__ dst,
                  const float* __restrict__ xin,
                  const float* __restrict__ al, const float* __restrict__ ar) {
    if (blockIdx.x < FILL_BLOCKS) {
        int e4 = blockIdx.x * blockDim.x + threadIdx.x;
        if (e4 < N_EDGES / 4) {
            int4 s = __ldg(&reinterpret_cast<const int4*>(src)[e4]);
            int4 d = __ldg(&reinterpret_cast<const int4*>(dst)[e4]);
            g_esrc[atomicAdd(&g_cursor[d.x], 1)] = s.x;
            g_esrc[atomicAdd(&g_cursor[d.y], 1)] = s.y;
            g_esrc[atomicAdd(&g_cursor[d.z], 1)] = s.z;
            g_esrc[atomicAdd(&g_cursor[d.w], 1)] = s.w;
        }
        return;
    }
    extern __shared__ __align__(16) char sbuf[];
    __half* sA  = reinterpret_cast<__half*>(sbuf);
    float*  sal = reinterpret_cast<float*>(sbuf + OFF_AL);
    float*  sar = sal + 128;
    int t = threadIdx.x;
    int rb = (blockIdx.x - FILL_BLOCKS) * 64;

    if (t < 128) sal[t] = __ldg(&al[t]);
    else         sar[t - 128] = __ldg(&ar[t - 128]);

    for (int i = t; i < 1024; i += 256) {    // 64 rows x 16 chunks
        int r = i >> 4, s = i & 15;
        float4 a = make_float4(0.f, 0.f, 0.f, 0.f), b = a;
        if (rb + r < N_NODES) {
            const float4* xr =
                reinterpret_cast<const float4*>(xin + (size_t)(rb + r) * 128 + s * 8);
            a = __ldg(xr); b = __ldg(xr + 1);
        }
        __half2 h0 = __float22half2_rn(make_float2(a.x, a.y));
        __half2 h1 = __float22half2_rn(make_float2(a.z, a.w));
        __half2 h2 = __float22half2_rn(make_float2(b.x, b.y));
        __half2 h3 = __float22half2_rn(make_float2(b.z, b.w));
        uint4 u;
        u.x = *reinterpret_cast<unsigned*>(&h0);
        u.y = *reinterpret_cast<unsigned*>(&h1);
        u.z = *reinterpret_cast<unsigned*>(&h2);
        u.w = *reinterpret_cast<unsigned*>(&h3);
        *reinterpret_cast<uint4*>(&sA[r * 136 + s * 8]) = u;
    }
    __syncthreads();
    gemm_core(sbuf, 0, rb, g_featA, g_elA, g_erA);
}

// ---------------- fused: aggregate(prev layer) into smem act -> GEMM next layer ----
__global__ void __launch_bounds__(256, 4)
fused_agg_gemm_kernel(int dir, int whichW,
                      const float* __restrict__ al, const float* __restrict__ ar) {
    extern __shared__ __align__(16) char sbuf[];
    __half* sA   = reinterpret_cast<__half*>(sbuf);
    float*  s_w  = reinterpret_cast<float*>(sbuf + OFF_SW);     // [8][4][33]
    int*    s_src= reinterpret_cast<int*>(sbuf + OFF_SSRC);     // [8][32]
    float*  sal  = reinterpret_cast<float*>(sbuf + OFF_AL);
    float*  sar  = sal + 128;

    const uint4*  featIn = reinterpret_cast<const uint4*>(dir ? g_featB : g_featA);
    const float4* elIn   = reinterpret_cast<const float4*>(dir ? g_elB : g_elA);
    const float4* erIn   = reinterpret_cast<const float4*>(dir ? g_erB : g_erA);
    __half* featOut = dir ? g_featA : g_featB;
    float*  elOut   = dir ? g_elA : g_elB;
    float*  erOut   = dir ? g_erA : g_erB;

    int t = threadIdx.x, w = t >> 5, lane = t & 31;
    int rb = blockIdx.x * 64;
    int sub = lane & 15, hf = lane >> 4;
    int hh  = sub >> 2;

    if (t < 128) sal[t] = __ldg(&al[t]);
    else         sar[t - 128] = __ldg(&ar[t - 128]);

    // ---- aggregate phase: each warp produces 8 act rows into sA ----
    for (int it = 0; it < 8; it++) {
        int node = rb + it * 8 + w;
        float acc8[8];
#pragma unroll
        for (int i = 0; i < 8; i++) acc8[i] = 0.f;
        float q0 = 0.f, q1 = 0.f, q2 = 0.f, q3 = 0.f;
        int s0 = 0, deg = 0;
        if (node < N_NODES) {
            s0 = g_rowptr[node];
            deg = g_rowptr[node + 1] - s0;
        }
        if (deg > 0) {
            float4 erd = erIn[node];
            for (int base = 0; base < deg; base += 32) {
                int idx = base + lane;
                int s = 0;
                float w0 = 0.f, w1 = 0.f, w2 = 0.f, w3 = 0.f;
                if (idx < deg) {
                    s = __ldg(&g_esrc[s0 + idx]);
                    float4 ev = __ldg(&elIn[s]);
                    w0 = __expf(lrelu(ev.x + erd.x));
                    w1 = __expf(lrelu(ev.y + erd.y));
                    w2 = __expf(lrelu(ev.z + erd.z));
                    w3 = __expf(lrelu(ev.w + erd.w));
                    q0 += w0; q1 += w1; q2 += w2; q3 += w3;
                }
                __syncwarp();
                s_src[w * 32 + lane] = s;
                s_w[(w * 4 + 0) * 33 + lane] = w0;
                s_w[(w * 4 + 1) * 33 + lane] = w1;
                s_w[(w * 4 + 2) * 33 + lane] = w2;
                s_w[(w * 4 + 3) * 33 + lane] = w3;
                __syncwarp();
                int cnt = min(32, deg - base);
#pragma unroll 4
                for (int j = 0; j < cnt; j += 2) {
                    int jj = j + hf;
                    int   sj = 0;
                    float aa = 0.f;
                    if (jj < cnt) {
                        sj = s_src[w * 32 + jj];
                        aa = s_w[(w * 4 + hh) * 33 + jj];
                    }
                    uint4 fr = __ldg(&featIn[(size_t)sj * 16 + sub]);
                    float2 f0 = __half22float2(*reinterpret_cast<__half2*>(&fr.x));
                    float2 f1 = __half22float2(*reinterpret_cast<__half2*>(&fr.y));
                    float2 f2 = __half22float2(*reinterpret_cast<__half2*>(&fr.z));
                    float2 f3 = __half22float2(*reinterpret_cast<__half2*>(&fr.w));
                    acc8[0] += f0.x * aa; acc8[1] += f0.y * aa;
                    acc8[2] += f1.x * aa; acc8[3] += f1.y * aa;
                    acc8[4] += f2.x * aa; acc8[5] += f2.y * aa;
                    acc8[6] += f3.x * aa; acc8[7] += f3.y * aa;
                }
            }
#pragma unroll
            for (int i = 0; i < 8; i++)
                acc8[i] += __shfl_down_sync(0xffffffffu, acc8[i], 16);
#pragma unroll
            for (int o = 16; o; o >>= 1) {
                q0 += __shfl_xor_sync(0xffffffffu, q0, o);
                q1 += __shfl_xor_sync(0xffffffffu, q1, o);
                q2 += __shfl_xor_sync(0xffffffffu, q2, o);
                q3 += __shfl_xor_sync(0xffffffffu, q3, o);
            }
            float qh = (hh == 0) ? q0 : ((hh == 1) ? q1 : ((hh == 2) ? q2 : q3));
            float inv = 1.f / qh;
#pragma unroll
            for (int i = 0; i < 8; i++) acc8[i] *= inv;
        }
        if (hf == 0) {     // relu + fp16 pack into sA row
            uint4 u;
            unsigned* pu = reinterpret_cast<unsigned*>(&u);
#pragma unroll
            for (int p = 0; p < 4; p++) {
                float lo = fmaxf(acc8[p * 2], 0.f), hi2 = fmaxf(acc8[p * 2 + 1], 0.f);
                __half2 hp = __float22half2_rn(make_float2(lo, hi2));
                pu[p] = *reinterpret_cast<unsigned*>(&hp);
            }
            *reinterpret_cast<uint4*>(&sA[(it * 8 + w) * 136 + sub * 8]) = u;
        }
    }
    __syncthreads();   // act tile complete; s_w/s_src dead -> sB (W) may load

    gemm_core(sbuf, whichW, rb, featOut, elOut, erOut);
}

// ---------------- final aggregation + fused graph max-pool (reads A buffers) ------
__global__ void aggregate_pool_kernel() {
    __shared__ float s_w[8][4][33];
    __shared__ int   s_src[8][32];
    __shared__ float s_pool[8][128];
    int node = (blockIdx.x * blockDim.x + threadIdx.x) >> 5;
    int lane = threadIdx.x & 31;
    int w    = threadIdx.x >> 5;
    int sub  = lane & 15, hf = lane >> 4;
    int hh   = sub >> 2;

    int s0  = g_rowptr[node];
    int deg = g_rowptr[node + 1] - s0;
    float acc8[8];
#pragma unroll
    for (int i = 0; i < 8; i++) acc8[i] = 0.f;
    float q0 = 0.f, q1 = 0.f, q2 = 0.f, q3 = 0.f;

    if (deg > 0) {
        const float4* el4 = reinterpret_cast<const float4*>(g_elA);
        float4 erd = reinterpret_cast<const float4*>(g_erA)[node];
        const uint4* feat4 = reinterpret_cast<const uint4*>(g_featA);

        for (int base = 0; base < deg; base += 32) {
            int idx = base + lane;
            int s = 0;
            float w0 = 0.f, w1 = 0.f, w2 = 0.f, w3 = 0.f;
            if (idx < deg) {
                s = __ldg(&g_esrc[s0 + idx]);
                float4 ev = __ldg(&el4[s]);
                w0 = __expf(lrelu(ev.x + erd.x));
                w1 = __expf(lrelu(ev.y + erd.y));
                w2 = __expf(lrelu(ev.z + erd.z));
                w3 = __expf(lrelu(ev.w + erd.w));
                q0 += w0; q1 += w1; q2 += w2; q3 += w3;
            }
            __syncwarp();
            s_src[w][lane] = s;
            s_w[w][0][lane] = w0; s_w[w][1][lane] = w1;
            s_w[w][2][lane] = w2; s_w[w][3][lane] = w3;
            __syncwarp();
            int cnt = min(32, deg - base);
#pragma unroll 4
            for (int j = 0; j < cnt; j += 2) {
                int jj = j + hf;
                int   sj = 0;
                float aa = 0.f;
                if (jj < cnt) {
                    sj = s_src[w][jj];
                    aa = s_w[w][hh][jj];
                }
                uint4 fr = __ldg(&feat4[(size_t)sj * 16 + sub]);
                float2 f0 = __half22float2(*reinterpret_cast<__half2*>(&fr.x));
                float2 f1 = __half22float2(*reinterpret_cast<__half2*>(&fr.y));
                float2 f2 = __half22float2(*reinterpret_cast<__half2*>(&fr.z));
                float2 f3 = __half22float2(*reinterpret_cast<__half2*>(&fr.w));
                acc8[0] += f0.x * aa; acc8[1] += f0.y * aa;
                acc8[2] += f1.x * aa; acc8[3] += f1.y * aa;
                acc8[4] += f2.x * aa; acc8[5] += f2.y * aa;
                acc8[6] += f3.x * aa; acc8[7] += f3.y * aa;
            }
        }
#pragma unroll
        for (int i = 0; i < 8; i++)
            acc8[i] += __shfl_down_sync(0xffffffffu, acc8[i], 16);
#pragma unroll
        for (int o = 16; o; o >>= 1) {
            q0 += __shfl_xor_sync(0xffffffffu, q0, o);
            q1 += __shfl_xor_sync(0xffffffffu, q1, o);
            q2 += __shfl_xor_sync(0xffffffffu, q2, o);
            q3 += __shfl_xor_sync(0xffffffffu, q3, o);
        }
        float qh = (hh == 0) ? q0 : ((hh == 1) ? q1 : ((hh == 2) ? q2 : q3));
        float inv = 1.f / qh;
#pragma unroll
        for (int i = 0; i < 8; i++) acc8[i] *= inv;
    }
#pragma unroll
    for (int i = 0; i < 8; i++) acc8[i] = fmaxf(acc8[i], 0.f);

    if (hf == 0) {
#pragma unroll
        for (int i = 0; i < 8; i++) s_pool[w][sub * 8 + i] = acc8[i];
    }
    __syncthreads();
    int t = threadIdx.x;
    if (t < 128) {
        float m = s_pool[0][t];
#pragma unroll
        for (int i = 1; i < 8; i++) m = fmaxf(m, s_pool[i][t]);
        atomicMax(reinterpret_cast<int*>(&g_pooled[t]), __float_as_int(m));
    }
}

// ---------------- FC + softmax head ----------------
__global__ void head_kernel(const float* __restrict__ Wfc, const float* __restrict__ bfc,
                            float* __restrict__ out) {
    __shared__ float lg[8];
    int t = threadIdx.x;
    if (t < 8) {
        float acc = bfc[t];
        for (int k = 0; k < 128; k++) acc += g_pooled[k] * Wfc[k * 8 + t];
        lg[t] = acc;
    }
    __syncthreads();
    if (t == 0) {
        float m = lg[0];
        for (int i = 1; i < 8; i++) m = fmaxf(m, lg[i]);
        float e[8], s = 0.f;
        for (int i = 0; i < 8; i++) { e[i] = expf(lg[i] - m); s += e[i]; }
        for (int i = 0; i < 8; i++) out[i] = e[i] / s;
    }
}

// ---------------- launch ----------------
extern "C" void kernel_launch(void* const* d_in, const int* in_sizes, int n_in,
                              void* d_out, int out_size) {
    (void)in_sizes; (void)n_in; (void)out_size;
    const float* x   = (const float*)d_in[0];
    const int*   src = (const int*)d_in[1];
    const int*   dst = (const int*)d_in[2];
    const float* W1  = (const float*)d_in[3];
    const float* al1 = (const float*)d_in[4];
    const float* ar1 = (const float*)d_in[5];
    const float* W2  = (const float*)d_in[6];
    const float* al2 = (const float*)d_in[7];
    const float* ar2 = (const float*)d_in[8];
    const float* W3  = (const float*)d_in[9];
    const float* al3 = (const float*)d_in[10];
    const float* ar3 = (const float*)d_in[11];
    const float* Wfc = (const float*)d_in[12];
    const float* bfc = (const float*)d_in[13];
    float* out = (float*)d_out;

    cudaFuncSetAttribute(fill_gemm1_kernel,
                         cudaFuncAttributeMaxDynamicSharedMemorySize, SMEM_GEMM);
    cudaFuncSetAttribute(fused_agg_gemm_kernel,
                         cudaFuncAttributeMaxDynamicSharedMemorySize, SMEM_GEMM);
    cudaFuncSetAttribute(fill_gemm1_kernel,
                         cudaFuncAttributePreferredSharedMemoryCarveout, 100);
    cudaFuncSetAttribute(fused_agg_gemm_kernel,
                         cudaFuncAttributePreferredSharedMemoryCarveout, 100);

    prep_kernel<<<(N_NODES + 255) / 256, 256>>>(W1, W2, W3);
    count_kernel<<<(N_EDGES / 4 + 255) / 256, 256>>>(dst);
    scan1_kernel<<<NBLK_SCAN, 1024>>>();
    scan3_kernel<<<(N_NODES + 255) / 256, 256>>>();

    // fill (CSR scatter) overlapped with layer-1 GEMM
    fill_gemm1_kernel<<<FILL_BLOCKS + GEMM_BLOCKS, 256, SMEM_GEMM>>>(src, dst, x, al1, ar1);

    // agg(layer1) + gemm(layer2): A -> B
    fused_agg_gemm_kernel<<<GEMM_BLOCKS, 256, SMEM_GEMM>>>(0, 1, al2, ar2);
    // agg(layer2) + gemm(layer3): B -> A
    fused_agg_gemm_kernel<<<GEMM_BLOCKS, 256, SMEM_GEMM>>>(1, 2, al3, ar3);
    // agg(layer3) + max-pool (reads A)
    aggregate_pool_kernel<<<N_NODES / 8, 256>>>();

    head_kernel<<<1, 32>>>(Wfc, bfc, out);
}